// round 2
// baseline (speedup 1.0000x reference)
#include <cuda_runtime.h>
#include <math.h>

#define S_LEN 2048
#define DMODEL 2048
#define NH 16
#define HD 128

// Scratch (allocation-free rule: __device__ globals)
__device__ float g_Q[S_LEN * DMODEL];
__device__ float g_K[S_LEN * DMODEL];
__device__ float g_V[S_LEN * DMODEL];
__device__ float g_O[S_LEN * DMODEL];

// ---------------------------------------------------------------------------
// SGEMM: C[M,N] = A[M,K] @ B[K,N], M=N=K=2048, row-major fp32.
// 128x128 tile, BK=8, 256 threads, 8x8 microtile per thread.
// ---------------------------------------------------------------------------
__global__ __launch_bounds__(256) void sgemm128(const float* __restrict__ A,
                                                const float* __restrict__ B,
                                                float* __restrict__ C) {
    const int K = DMODEL, N = DMODEL;
    __shared__ float As[8][128];
    __shared__ float Bs[8][128];

    int tid  = threadIdx.x;
    int brow = blockIdx.y * 128;
    int bcol = blockIdx.x * 128;

    int aRow = tid >> 1;          // 0..127
    int aCol = (tid & 1) << 2;    // 0 or 4
    int bRow = tid >> 5;          // 0..7
    int bCol = (tid & 31) << 2;   // 0..124

    int ty = tid >> 4;            // 0..15
    int tx = tid & 15;            // 0..15

    const float* Aptr = A + (size_t)(brow + aRow) * K + aCol;
    const float* Bptr = B + (size_t)bRow * N + bcol + bCol;

    float acc[8][8];
#pragma unroll
    for (int i = 0; i < 8; i++)
#pragma unroll
        for (int j = 0; j < 8; j++) acc[i][j] = 0.f;

    for (int k0 = 0; k0 < K; k0 += 8) {
        float4 av = *(const float4*)(Aptr + k0);
        float4 bv = *(const float4*)(Bptr + (size_t)k0 * N);
        As[aCol + 0][aRow] = av.x;
        As[aCol + 1][aRow] = av.y;
        As[aCol + 2][aRow] = av.z;
        As[aCol + 3][aRow] = av.w;
        *(float4*)&Bs[bRow][bCol] = bv;
        __syncthreads();

#pragma unroll
        for (int kk = 0; kk < 8; kk++) {
            float4 a0 = *(const float4*)&As[kk][ty * 8];
            float4 a1 = *(const float4*)&As[kk][ty * 8 + 4];
            float4 b0 = *(const float4*)&Bs[kk][tx * 8];
            float4 b1 = *(const float4*)&Bs[kk][tx * 8 + 4];
            float ar[8] = {a0.x, a0.y, a0.z, a0.w, a1.x, a1.y, a1.z, a1.w};
            float br[8] = {b0.x, b0.y, b0.z, b0.w, b1.x, b1.y, b1.z, b1.w};
#pragma unroll
            for (int i = 0; i < 8; i++)
#pragma unroll
                for (int j = 0; j < 8; j++)
                    acc[i][j] = fmaf(ar[i], br[j], acc[i][j]);
        }
        __syncthreads();
    }

#pragma unroll
    for (int i = 0; i < 8; i++) {
        float* Crow = C + (size_t)(brow + ty * 8 + i) * N + bcol + tx * 8;
        float4 c0 = {acc[i][0], acc[i][1], acc[i][2], acc[i][3]};
        float4 c1 = {acc[i][4], acc[i][5], acc[i][6], acc[i][7]};
        *(float4*)Crow       = c0;
        *(float4*)(Crow + 4) = c1;
    }
}

// ---------------------------------------------------------------------------
// RoPE (interleaved pairs) applied in-place to g_Q and g_K.
// One thread per (s, h, i) pair; pairs = S*NH*HD/2.
// ---------------------------------------------------------------------------
__global__ void rope_kernel(const float* __restrict__ fcos,
                            const float* __restrict__ fsin) {
    int p = blockIdx.x * blockDim.x + threadIdx.x;
    int total = S_LEN * NH * (HD / 2);
    if (p >= total) return;
    int i = p & 63;            // HD/2 = 64
    int h = (p >> 6) & 15;     // NH = 16
    int s = p >> 10;           // / (16*64)

    float c  = fcos[s * 64 + i];
    float sn = fsin[s * 64 + i];
    size_t base = (size_t)s * DMODEL + h * HD + 2 * i;

    float q0 = g_Q[base], q1 = g_Q[base + 1];
    g_Q[base]     = q0 * c - q1 * sn;
    g_Q[base + 1] = q0 * sn + q1 * c;

    float k0 = g_K[base], k1 = g_K[base + 1];
    g_K[base]     = k0 * c - k1 * sn;
    g_K[base + 1] = k0 * sn + k1 * c;
}

// ---------------------------------------------------------------------------
// Flash attention, causal, softcap 50*tanh(s/50), scale 1/sqrt(128).
// Block = (q-tile of 32 rows, one head). 256 threads.
// Smem: Q 16KB + KV 16KB + S 4.2KB + reductions  (< 48KB static)
// ---------------------------------------------------------------------------
#define BQ 32
#define BKV 32
__global__ __launch_bounds__(256) void attn_kernel() {
    __shared__ float Qs[BQ][HD];
    __shared__ float KVs[BKV][HD];
    __shared__ float Ss[BQ][BKV + 1];
    __shared__ float red[8][BQ];
    __shared__ float mrow[BQ], lrow[BQ], cf[BQ];

    int tid = threadIdx.x;
    int qb  = blockIdx.x;   // 0..63
    int h   = blockIdx.y;   // 0..15
    int ty  = tid >> 4, tx = tid & 15;
    int r0  = ty * 2, r1 = ty * 2 + 1;
    int srow = tid & 31;    // softmax row
    int seg  = tid >> 5;    // 0..7

    // Load Q tile [32 x 128]
#pragma unroll
    for (int it = 0; it < 4; ++it) {
        int slot = tid + it * 256;      // 1024 float4 slots
        int row = slot >> 5;
        int c4  = slot & 31;
        *(float4*)&Qs[row][c4 * 4] =
            *(const float4*)(g_Q + (size_t)(qb * BQ + row) * DMODEL + h * HD + c4 * 4);
    }
    if (tid < BQ) { mrow[tid] = -INFINITY; lrow[tid] = 0.f; }

    float acc[2][8];
#pragma unroll
    for (int i = 0; i < 2; i++)
#pragma unroll
        for (int j = 0; j < 8; j++) acc[i][j] = 0.f;

    const float inv_sqrt_hd = 0.08838834764831845f;  // 1/sqrt(128)

    for (int kb = 0; kb <= qb; ++kb) {
        __syncthreads();  // protect KVs/Ss from previous iteration
        // Load K tile
#pragma unroll
        for (int it = 0; it < 4; ++it) {
            int slot = tid + it * 256;
            int row = slot >> 5;
            int c4  = slot & 31;
            *(float4*)&KVs[row][c4 * 4] =
                *(const float4*)(g_K + (size_t)(kb * BKV + row) * DMODEL + h * HD + c4 * 4);
        }
        __syncthreads();

        // Scores: 2x2 microtile per thread over [32 x 32]
        int c0 = tx * 2, c1 = tx * 2 + 1;
        float s00 = 0.f, s01 = 0.f, s10 = 0.f, s11 = 0.f;
#pragma unroll 4
        for (int d = 0; d < HD; d += 4) {
            float4 qa = *(const float4*)&Qs[r0][d];
            float4 qc = *(const float4*)&Qs[r1][d];
            float4 ka = *(const float4*)&KVs[c0][d];
            float4 kc = *(const float4*)&KVs[c1][d];
            s00 = fmaf(qa.x, ka.x, s00); s00 = fmaf(qa.y, ka.y, s00);
            s00 = fmaf(qa.z, ka.z, s00); s00 = fmaf(qa.w, ka.w, s00);
            s01 = fmaf(qa.x, kc.x, s01); s01 = fmaf(qa.y, kc.y, s01);
            s01 = fmaf(qa.z, kc.z, s01); s01 = fmaf(qa.w, kc.w, s01);
            s10 = fmaf(qc.x, ka.x, s10); s10 = fmaf(qc.y, ka.y, s10);
            s10 = fmaf(qc.z, ka.z, s10); s10 = fmaf(qc.w, ka.w, s10);
            s11 = fmaf(qc.x, kc.x, s11); s11 = fmaf(qc.y, kc.y, s11);
            s11 = fmaf(qc.z, kc.z, s11); s11 = fmaf(qc.w, kc.w, s11);
        }
        Ss[r0][c0] = s00; Ss[r0][c1] = s01;
        Ss[r1][c0] = s10; Ss[r1][c1] = s11;
        __syncthreads();   // all KVs reads done; Ss visible

        // Load V tile into KVs (K no longer needed)
#pragma unroll
        for (int it = 0; it < 4; ++it) {
            int slot = tid + it * 256;
            int row = slot >> 5;
            int c4  = slot & 31;
            *(float4*)&KVs[row][c4 * 4] =
                *(const float4*)(g_V + (size_t)(kb * BKV + row) * DMODEL + h * HD + c4 * 4);
        }

        // Softcap + causal mask + per-segment max (8 threads per row, 4 cols each)
        float lmax = -INFINITY;
        int gq = qb * BQ + srow;
#pragma unroll
        for (int jj = 0; jj < 4; ++jj) {
            int c  = seg * 4 + jj;
            int gk = kb * BKV + c;
            float sv = Ss[srow][c] * inv_sqrt_hd;
            sv = 50.f * tanhf(sv * 0.02f);
            if (gk > gq) sv = -INFINITY;
            Ss[srow][c] = sv;
            lmax = fmaxf(lmax, sv);
        }
        red[seg][srow] = lmax;
        __syncthreads();

        if (tid < BQ) {
            float nm = mrow[tid];
#pragma unroll
            for (int s2 = 0; s2 < 8; s2++) nm = fmaxf(nm, red[s2][tid]);
            cf[tid]   = __expf(mrow[tid] - nm);   // 0 when mrow was -inf
            mrow[tid] = nm;
        }
        __syncthreads();

        // exp + local sums; rescale accumulators
        float nm = mrow[srow];
        float lsum = 0.f;
#pragma unroll
        for (int jj = 0; jj < 4; ++jj) {
            int c = seg * 4 + jj;
            float pv = __expf(Ss[srow][c] - nm);
            Ss[srow][c] = pv;
            lsum += pv;
        }
        red[seg][srow] = lsum;

        float cf0 = cf[r0], cf1 = cf[r1];
#pragma unroll
        for (int j = 0; j < 8; j++) { acc[0][j] *= cf0; acc[1][j] *= cf1; }
        __syncthreads();

        if (tid < BQ) {
            float t = 0.f;
#pragma unroll
            for (int s2 = 0; s2 < 8; s2++) t += red[s2][tid];
            lrow[tid] = lrow[tid] * cf[tid] + t;
        }

        // O += P @ V  (rows r0/r1, cols tx*8..tx*8+7)
#pragma unroll 4
        for (int k = 0; k < BKV; k++) {
            float p0 = Ss[r0][k];
            float p1 = Ss[r1][k];
            float4 v0 = *(const float4*)&KVs[k][tx * 8];
            float4 v1 = *(const float4*)&KVs[k][tx * 8 + 4];
            acc[0][0] = fmaf(p0, v0.x, acc[0][0]);
            acc[0][1] = fmaf(p0, v0.y, acc[0][1]);
            acc[0][2] = fmaf(p0, v0.z, acc[0][2]);
            acc[0][3] = fmaf(p0, v0.w, acc[0][3]);
            acc[0][4] = fmaf(p0, v1.x, acc[0][4]);
            acc[0][5] = fmaf(p0, v1.y, acc[0][5]);
            acc[0][6] = fmaf(p0, v1.z, acc[0][6]);
            acc[0][7] = fmaf(p0, v1.w, acc[0][7]);
            acc[1][0] = fmaf(p1, v0.x, acc[1][0]);
            acc[1][1] = fmaf(p1, v0.y, acc[1][1]);
            acc[1][2] = fmaf(p1, v0.z, acc[1][2]);
            acc[1][3] = fmaf(p1, v0.w, acc[1][3]);
            acc[1][4] = fmaf(p1, v1.x, acc[1][4]);
            acc[1][5] = fmaf(p1, v1.y, acc[1][5]);
            acc[1][6] = fmaf(p1, v1.z, acc[1][6]);
            acc[1][7] = fmaf(p1, v1.w, acc[1][7]);
        }
    }

    __syncthreads();  // lrow final
    float il0 = 1.f / lrow[r0];
    float il1 = 1.f / lrow[r1];
    {
        float* o0 = g_O + (size_t)(qb * BQ + r0) * DMODEL + h * HD + tx * 8;
        float* o1 = g_O + (size_t)(qb * BQ + r1) * DMODEL + h * HD + tx * 8;
        float4 a = {acc[0][0] * il0, acc[0][1] * il0, acc[0][2] * il0, acc[0][3] * il0};
        float4 b = {acc[0][4] * il0, acc[0][5] * il0, acc[0][6] * il0, acc[0][7] * il0};
        float4 c = {acc[1][0] * il1, acc[1][1] * il1, acc[1][2] * il1, acc[1][3] * il1};
        float4 d = {acc[1][4] * il1, acc[1][5] * il1, acc[1][6] * il1, acc[1][7] * il1};
        *(float4*)o0 = a; *(float4*)(o0 + 4) = b;
        *(float4*)o1 = c; *(float4*)(o1 + 4) = d;
    }
}

// ---------------------------------------------------------------------------
// Launch
// ---------------------------------------------------------------------------
extern "C" void kernel_launch(void* const* d_in, const int* in_sizes, int n_in,
                              void* d_out, int out_size) {
    const float* x    = (const float*)d_in[0];
    const float* wq   = (const float*)d_in[1];
    const float* wk   = (const float*)d_in[2];
    const float* wv   = (const float*)d_in[3];
    const float* wo   = (const float*)d_in[4];
    const float* fcos = (const float*)d_in[5];
    const float* fsin = (const float*)d_in[6];
    float* out = (float*)d_out;

    float *Qp, *Kp, *Vp, *Op;
    cudaGetSymbolAddress((void**)&Qp, g_Q);
    cudaGetSymbolAddress((void**)&Kp, g_K);
    cudaGetSymbolAddress((void**)&Vp, g_V);
    cudaGetSymbolAddress((void**)&Op, g_O);

    dim3 gg(DMODEL / 128, DMODEL / 128);  // 16x16
    sgemm128<<<gg, 256>>>(x, wq, Qp);
    sgemm128<<<gg, 256>>>(x, wk, Kp);
    sgemm128<<<gg, 256>>>(x, wv, Vp);

    int pairs = S_LEN * NH * (HD / 2);
    rope_kernel<<<pairs / 256, 256>>>(fcos, fsin);

    attn_kernel<<<dim3(S_LEN / BQ, NH), 256>>>();

    sgemm128<<<gg, 256>>>(Op, wo, out);
}

// round 6
// speedup vs baseline: 1.2270x; 1.2270x over previous
#include <cuda_runtime.h>
#include <cuda_bf16.h>
#include <math.h>
#include <stdint.h>

#define S_LEN 2048
#define DMODEL 2048
#define NH 16
#define HD 128

// ---------------------------------------------------------------------------
// Scratch (__device__ globals; allocation-free rule)
// ---------------------------------------------------------------------------
__device__ float g_Q[S_LEN * DMODEL];
__device__ float g_K[S_LEN * DMODEL];
__device__ float g_V[S_LEN * DMODEL];
__device__ float g_O[S_LEN * DMODEL];

__device__ __nv_bfloat16 g_xhi[S_LEN * DMODEL];
__device__ __nv_bfloat16 g_xlo[S_LEN * DMODEL];
__device__ __nv_bfloat16 g_ohi[S_LEN * DMODEL];
__device__ __nv_bfloat16 g_olo[S_LEN * DMODEL];
__device__ __nv_bfloat16 g_wth[4][DMODEL * DMODEL];  // transposed [N][K] hi
__device__ __nv_bfloat16 g_wtl[4][DMODEL * DMODEL];  // transposed [N][K] lo

// ---------------------------------------------------------------------------
// Helpers
// ---------------------------------------------------------------------------
__device__ __forceinline__ void cp16(uint32_t s, const void* g) {
    asm volatile("cp.async.cg.shared.global [%0], [%1], 16;" :: "r"(s), "l"(g) : "memory");
}
__device__ __forceinline__ uint32_t smem_u32(const void* p) {
    uint32_t a;
    asm("{ .reg .u64 t; cvta.to.shared.u64 t, %1; cvt.u32.u64 %0, t; }"
        : "=r"(a) : "l"(p));
    return a;
}
__device__ __forceinline__ void mma16816(float* c, uint32_t a0, uint32_t a1,
                                         uint32_t a2, uint32_t a3,
                                         uint32_t b0, uint32_t b1) {
    asm volatile(
        "mma.sync.aligned.m16n8k16.row.col.f32.bf16.bf16.f32 "
        "{%0,%1,%2,%3}, {%4,%5,%6,%7}, {%8,%9}, {%0,%1,%2,%3};"
        : "+f"(c[0]), "+f"(c[1]), "+f"(c[2]), "+f"(c[3])
        : "r"(a0), "r"(a1), "r"(a2), "r"(a3), "r"(b0), "r"(b1));
}

// ---------------------------------------------------------------------------
// Split fp32 -> bf16 hi/lo (elementwise)
// ---------------------------------------------------------------------------
__global__ void split_kernel(const float* __restrict__ src,
                             __nv_bfloat16* __restrict__ hi,
                             __nv_bfloat16* __restrict__ lo) {
    int i = (blockIdx.x * blockDim.x + threadIdx.x) * 4;
    float4 v = *(const float4*)(src + i);
    float vv[4] = {v.x, v.y, v.z, v.w};
#pragma unroll
    for (int j = 0; j < 4; j++) {
        __nv_bfloat16 h = __float2bfloat16(vv[j]);
        hi[i + j] = h;
        lo[i + j] = __float2bfloat16(vv[j] - __bfloat162float(h));
    }
}

// Transpose + split: W [K=2048][N=2048] row-major -> T [N][K] hi/lo
__global__ void wt_split_kernel(const float* __restrict__ W,
                                __nv_bfloat16* __restrict__ Thi,
                                __nv_bfloat16* __restrict__ Tlo) {
    __shared__ float tile[32][33];
    int n0 = blockIdx.x * 32, k0 = blockIdx.y * 32;
    int tx = threadIdx.x, ty = threadIdx.y;
#pragma unroll
    for (int r = 0; r < 32; r += 8)
        tile[ty + r][tx] = W[(size_t)(k0 + ty + r) * DMODEL + n0 + tx];
    __syncthreads();
#pragma unroll
    for (int r = 0; r < 32; r += 8) {
        float v = tile[tx][ty + r];
        size_t o = (size_t)(n0 + ty + r) * DMODEL + k0 + tx;
        __nv_bfloat16 h = __float2bfloat16(v);
        Thi[o] = h;
        Tlo[o] = __float2bfloat16(v - __bfloat162float(h));
    }
}

// ---------------------------------------------------------------------------
// HMMA split-bf16 GEMM: C[2048,2048] = A @ W, W given transposed [N][K].
// Block tile 128x128, BK=32, 256 threads (8 warps, 2Mx4N), warp tile 64x32.
// 3 terms: AhiBhi + AhiBlo + AloBhi, fp32 accum. Double-buffered cp.async.
// Smem tile: [128 rows][32 bf16 + 8 pad] -> row stride 80 B (20 words).
// ---------------------------------------------------------------------------
#define BK2 32
#define NCHUNK2 (DMODEL / BK2)          // 64
#define ROWSTRIDE_W 20                  // words per smem row (80 B)
#define TILE_BYTES (128 * 80)           // 10240
#define TILE_WORDS (TILE_BYTES / 4)     // 2560
#define BUF_STRIDE_B (4 * TILE_BYTES)   // Ahi, Alo, Bhi, Blo = 40960
#define GEMM_SMEM (2 * BUF_STRIDE_B)    // 81920

__device__ __forceinline__ void load_tile32(uint32_t sbase, const __nv_bfloat16* g,
                                            int row0, int k0, int tid) {
#pragma unroll
    for (int i = 0; i < 2; i++) {
        int slot = tid + i * 256;        // 512 chunks of 16 B
        int row = slot >> 2;
        int j = slot & 3;
        cp16(sbase + row * 80 + j * 16,
             g + (size_t)(row0 + row) * DMODEL + k0 + j * 8);
    }
}

__global__ __launch_bounds__(256) void gemm_hmma(
        const __nv_bfloat16* __restrict__ Ahi,
        const __nv_bfloat16* __restrict__ Alo,
        const __nv_bfloat16* __restrict__ Bhi,
        const __nv_bfloat16* __restrict__ Blo,
        float* __restrict__ C) {
    extern __shared__ char smem[];
    uint32_t sb = smem_u32(smem);
    const uint32_t* sw = (const uint32_t*)smem;

    int tid = threadIdx.x;
    int wid = tid >> 5, lane = tid & 31;
    int wm = wid & 1, wn = wid >> 1;        // 2 x 4 warp grid
    int g = lane >> 2, tq = lane & 3;
    int n0 = blockIdx.x * 128, m0 = blockIdx.y * 128;

    float acc[4][4][4];
#pragma unroll
    for (int i = 0; i < 4; i++)
#pragma unroll
        for (int j = 0; j < 4; j++)
#pragma unroll
            for (int k = 0; k < 4; k++) acc[i][j][k] = 0.f;

    // prologue: chunk 0 -> buffer 0
    {
        uint32_t b = sb;
        load_tile32(b, Ahi, m0, 0, tid);
        load_tile32(b + TILE_BYTES, Alo, m0, 0, tid);
        load_tile32(b + 2 * TILE_BYTES, Bhi, n0, 0, tid);
        load_tile32(b + 3 * TILE_BYTES, Blo, n0, 0, tid);
        asm volatile("cp.async.commit_group;" ::: "memory");
    }

    for (int c = 0; c < NCHUNK2; ++c) {
        if (c + 1 < NCHUNK2) {
            uint32_t nb = sb + ((c + 1) & 1) * BUF_STRIDE_B;
            int k0 = (c + 1) * BK2;
            load_tile32(nb, Ahi, m0, k0, tid);
            load_tile32(nb + TILE_BYTES, Alo, m0, k0, tid);
            load_tile32(nb + 2 * TILE_BYTES, Bhi, n0, k0, tid);
            load_tile32(nb + 3 * TILE_BYTES, Blo, n0, k0, tid);
            asm volatile("cp.async.commit_group;" ::: "memory");
            asm volatile("cp.async.wait_group 1;" ::: "memory");
        } else {
            asm volatile("cp.async.wait_group 0;" ::: "memory");
        }
        __syncthreads();

        uint32_t wbase = ((c & 1) * BUF_STRIDE_B) >> 2;   // word offset of buffer
        const uint32_t wAh = wbase;
        const uint32_t wAl = wbase + TILE_WORDS;
        const uint32_t wBh = wbase + 2 * TILE_WORDS;
        const uint32_t wBl = wbase + 3 * TILE_WORDS;

#pragma unroll
        for (int ks = 0; ks < 2; ks++) {
            int kw = ks * 8 + tq;            // word offset in row for first pair
            // row word-offsets
            uint32_t arow[4], brow[4];
#pragma unroll
            for (int mf = 0; mf < 4; mf++)
                arow[mf] = (uint32_t)(wm * 64 + mf * 16 + g) * ROWSTRIDE_W;
#pragma unroll
            for (int nf = 0; nf < 4; nf++)
                brow[nf] = (uint32_t)(wn * 32 + nf * 8 + g) * ROWSTRIDE_W;

            uint32_t ah[4][4], bh[4][2];
#pragma unroll
            for (int mf = 0; mf < 4; mf++) {
                ah[mf][0] = sw[wAh + arow[mf] + kw];
                ah[mf][1] = sw[wAh + arow[mf] + 8 * ROWSTRIDE_W + kw];
                ah[mf][2] = sw[wAh + arow[mf] + kw + 4];
                ah[mf][3] = sw[wAh + arow[mf] + 8 * ROWSTRIDE_W + kw + 4];
            }
#pragma unroll
            for (int nf = 0; nf < 4; nf++) {
                bh[nf][0] = sw[wBh + brow[nf] + kw];
                bh[nf][1] = sw[wBh + brow[nf] + kw + 4];
            }
#pragma unroll
            for (int mf = 0; mf < 4; mf++)
#pragma unroll
                for (int nf = 0; nf < 4; nf++)
                    mma16816(acc[mf][nf], ah[mf][0], ah[mf][1], ah[mf][2], ah[mf][3],
                             bh[nf][0], bh[nf][1]);

            // Ahi * Blo
            uint32_t bl[4][2];
#pragma unroll
            for (int nf = 0; nf < 4; nf++) {
                bl[nf][0] = sw[wBl + brow[nf] + kw];
                bl[nf][1] = sw[wBl + brow[nf] + kw + 4];
            }
#pragma unroll
            for (int mf = 0; mf < 4; mf++)
#pragma unroll
                for (int nf = 0; nf < 4; nf++)
                    mma16816(acc[mf][nf], ah[mf][0], ah[mf][1], ah[mf][2], ah[mf][3],
                             bl[nf][0], bl[nf][1]);

            // Alo * Bhi
            uint32_t al[4][4];
#pragma unroll
            for (int mf = 0; mf < 4; mf++) {
                al[mf][0] = sw[wAl + arow[mf] + kw];
                al[mf][1] = sw[wAl + arow[mf] + 8 * ROWSTRIDE_W + kw];
                al[mf][2] = sw[wAl + arow[mf] + kw + 4];
                al[mf][3] = sw[wAl + arow[mf] + 8 * ROWSTRIDE_W + kw + 4];
            }
#pragma unroll
            for (int mf = 0; mf < 4; mf++)
#pragma unroll
                for (int nf = 0; nf < 4; nf++)
                    mma16816(acc[mf][nf], al[mf][0], al[mf][1], al[mf][2], al[mf][3],
                             bh[nf][0], bh[nf][1]);
        }
        __syncthreads();
    }

    // Epilogue: direct register -> global (float2 per fragment row)
#pragma unroll
    for (int mf = 0; mf < 4; mf++) {
#pragma unroll
        for (int nf = 0; nf < 4; nf++) {
            int row = m0 + wm * 64 + mf * 16 + g;
            int col = n0 + wn * 32 + nf * 8 + 2 * tq;
            float2 v0 = {acc[mf][nf][0], acc[mf][nf][1]};
            float2 v1 = {acc[mf][nf][2], acc[mf][nf][3]};
            *(float2*)&C[(size_t)row * DMODEL + col] = v0;
            *(float2*)&C[(size_t)(row + 8) * DMODEL + col] = v1;
        }
    }
}

// ---------------------------------------------------------------------------
// RoPE (unchanged)
// ---------------------------------------------------------------------------
__global__ void rope_kernel(const float* __restrict__ fcos,
                            const float* __restrict__ fsin) {
    int p = blockIdx.x * blockDim.x + threadIdx.x;
    int total = S_LEN * NH * (HD / 2);
    if (p >= total) return;
    int i = p & 63;
    int h = (p >> 6) & 15;
    int s = p >> 10;

    float c  = fcos[s * 64 + i];
    float sn = fsin[s * 64 + i];
    size_t base = (size_t)s * DMODEL + h * HD + 2 * i;

    float q0 = g_Q[base], q1 = g_Q[base + 1];
    g_Q[base]     = q0 * c - q1 * sn;
    g_Q[base + 1] = q0 * sn + q1 * c;

    float k0 = g_K[base], k1 = g_K[base + 1];
    g_K[base]     = k0 * c - k1 * sn;
    g_K[base + 1] = k0 * sn + k1 * c;
}

// ---------------------------------------------------------------------------
// Flash attention (unchanged from R2)
// ---------------------------------------------------------------------------
#define BQ 32
#define BKV 32
__global__ __launch_bounds__(256) void attn_kernel() {
    __shared__ float Qs[BQ][HD];
    __shared__ float KVs[BKV][HD];
    __shared__ float Ss[BQ][BKV + 1];
    __shared__ float red[8][BQ];
    __shared__ float mrow[BQ], lrow[BQ], cf[BQ];

    int tid = threadIdx.x;
    int qb  = blockIdx.x;
    int h   = blockIdx.y;
    int ty  = tid >> 4, tx = tid & 15;
    int r0  = ty * 2, r1 = ty * 2 + 1;
    int srow = tid & 31;
    int seg  = tid >> 5;

#pragma unroll
    for (int it = 0; it < 4; ++it) {
        int slot = tid + it * 256;
        int row = slot >> 5;
        int c4  = slot & 31;
        *(float4*)&Qs[row][c4 * 4] =
            *(const float4*)(g_Q + (size_t)(qb * BQ + row) * DMODEL + h * HD + c4 * 4);
    }
    if (tid < BQ) { mrow[tid] = -INFINITY; lrow[tid] = 0.f; }

    float acc[2][8];
#pragma unroll
    for (int i = 0; i < 2; i++)
#pragma unroll
        for (int j = 0; j < 8; j++) acc[i][j] = 0.f;

    const float inv_sqrt_hd = 0.08838834764831845f;

    for (int kb = 0; kb <= qb; ++kb) {
        __syncthreads();
#pragma unroll
        for (int it = 0; it < 4; ++it) {
            int slot = tid + it * 256;
            int row = slot >> 5;
            int c4  = slot & 31;
            *(float4*)&KVs[row][c4 * 4] =
                *(const float4*)(g_K + (size_t)(kb * BKV + row) * DMODEL + h * HD + c4 * 4);
        }
        __syncthreads();

        int c0 = tx * 2, c1 = tx * 2 + 1;
        float s00 = 0.f, s01 = 0.f, s10 = 0.f, s11 = 0.f;
#pragma unroll 4
        for (int d = 0; d < HD; d += 4) {
            float4 qa = *(const float4*)&Qs[r0][d];
            float4 qc = *(const float4*)&Qs[r1][d];
            float4 ka = *(const float4*)&KVs[c0][d];
            float4 kc = *(const float4*)&KVs[c1][d];
            s00 = fmaf(qa.x, ka.x, s00); s00 = fmaf(qa.y, ka.y, s00);
            s00 = fmaf(qa.z, ka.z, s00); s00 = fmaf(qa.w, ka.w, s00);
            s01 = fmaf(qa.x, kc.x, s01); s01 = fmaf(qa.y, kc.y, s01);
            s01 = fmaf(qa.z, kc.z, s01); s01 = fmaf(qa.w, kc.w, s01);
            s10 = fmaf(qc.x, ka.x, s10); s10 = fmaf(qc.y, ka.y, s10);
            s10 = fmaf(qc.z, ka.z, s10); s10 = fmaf(qc.w, ka.w, s10);
            s11 = fmaf(qc.x, kc.x, s11); s11 = fmaf(qc.y, kc.y, s11);
            s11 = fmaf(qc.z, kc.z, s11); s11 = fmaf(qc.w, kc.w, s11);
        }
        Ss[r0][c0] = s00; Ss[r0][c1] = s01;
        Ss[r1][c0] = s10; Ss[r1][c1] = s11;
        __syncthreads();

#pragma unroll
        for (int it = 0; it < 4; ++it) {
            int slot = tid + it * 256;
            int row = slot >> 5;
            int c4  = slot & 31;
            *(float4*)&KVs[row][c4 * 4] =
                *(const float4*)(g_V + (size_t)(kb * BKV + row) * DMODEL + h * HD + c4 * 4);
        }

        float lmax = -INFINITY;
        int gq = qb * BQ + srow;
#pragma unroll
        for (int jj = 0; jj < 4; ++jj) {
            int c  = seg * 4 + jj;
            int gk = kb * BKV + c;
            float sv = Ss[srow][c] * inv_sqrt_hd;
            sv = 50.f * tanhf(sv * 0.02f);
            if (gk > gq) sv = -INFINITY;
            Ss[srow][c] = sv;
            lmax = fmaxf(lmax, sv);
        }
        red[seg][srow] = lmax;
        __syncthreads();

        if (tid < BQ) {
            float nm = mrow[tid];
#pragma unroll
            for (int s2 = 0; s2 < 8; s2++) nm = fmaxf(nm, red[s2][tid]);
            cf[tid]   = __expf(mrow[tid] - nm);
            mrow[tid] = nm;
        }
        __syncthreads();

        float nm = mrow[srow];
        float lsum = 0.f;
#pragma unroll
        for (int jj = 0; jj < 4; ++jj) {
            int c = seg * 4 + jj;
            float pv = __expf(Ss[srow][c] - nm);
            Ss[srow][c] = pv;
            lsum += pv;
        }
        red[seg][srow] = lsum;

        float cf0 = cf[r0], cf1 = cf[r1];
#pragma unroll
        for (int j = 0; j < 8; j++) { acc[0][j] *= cf0; acc[1][j] *= cf1; }
        __syncthreads();

        if (tid < BQ) {
            float t = 0.f;
#pragma unroll
            for (int s2 = 0; s2 < 8; s2++) t += red[s2][tid];
            lrow[tid] = lrow[tid] * cf[tid] + t;
        }

#pragma unroll 4
        for (int k = 0; k < BKV; k++) {
            float p0 = Ss[r0][k];
            float p1 = Ss[r1][k];
            float4 v0 = *(const float4*)&KVs[k][tx * 8];
            float4 v1 = *(const float4*)&KVs[k][tx * 8 + 4];
            acc[0][0] = fmaf(p0, v0.x, acc[0][0]);
            acc[0][1] = fmaf(p0, v0.y, acc[0][1]);
            acc[0][2] = fmaf(p0, v0.z, acc[0][2]);
            acc[0][3] = fmaf(p0, v0.w, acc[0][3]);
            acc[0][4] = fmaf(p0, v1.x, acc[0][4]);
            acc[0][5] = fmaf(p0, v1.y, acc[0][5]);
            acc[0][6] = fmaf(p0, v1.z, acc[0][6]);
            acc[0][7] = fmaf(p0, v1.w, acc[0][7]);
            acc[1][0] = fmaf(p1, v0.x, acc[1][0]);
            acc[1][1] = fmaf(p1, v0.y, acc[1][1]);
            acc[1][2] = fmaf(p1, v0.z, acc[1][2]);
            acc[1][3] = fmaf(p1, v0.w, acc[1][3]);
            acc[1][4] = fmaf(p1, v1.x, acc[1][4]);
            acc[1][5] = fmaf(p1, v1.y, acc[1][5]);
            acc[1][6] = fmaf(p1, v1.z, acc[1][6]);
            acc[1][7] = fmaf(p1, v1.w, acc[1][7]);
        }
    }

    __syncthreads();
    float il0 = 1.f / lrow[r0];
    float il1 = 1.f / lrow[r1];
    {
        float* o0 = g_O + (size_t)(qb * BQ + r0) * DMODEL + h * HD + tx * 8;
        float* o1 = g_O + (size_t)(qb * BQ + r1) * DMODEL + h * HD + tx * 8;
        float4 a = {acc[0][0] * il0, acc[0][1] * il0, acc[0][2] * il0, acc[0][3] * il0};
        float4 b = {acc[0][4] * il0, acc[0][5] * il0, acc[0][6] * il0, acc[0][7] * il0};
        float4 c = {acc[1][0] * il1, acc[1][1] * il1, acc[1][2] * il1, acc[1][3] * il1};
        float4 d = {acc[1][4] * il1, acc[1][5] * il1, acc[1][6] * il1, acc[1][7] * il1};
        *(float4*)o0 = a; *(float4*)(o0 + 4) = b;
        *(float4*)o1 = c; *(float4*)(o1 + 4) = d;
    }
}

// ---------------------------------------------------------------------------
// Launch
// ---------------------------------------------------------------------------
extern "C" void kernel_launch(void* const* d_in, const int* in_sizes, int n_in,
                              void* d_out, int out_size) {
    const float* x    = (const float*)d_in[0];
    const float* wq   = (const float*)d_in[1];
    const float* wk   = (const float*)d_in[2];
    const float* wv   = (const float*)d_in[3];
    const float* wo   = (const float*)d_in[4];
    const float* fcos = (const float*)d_in[5];
    const float* fsin = (const float*)d_in[6];
    float* out = (float*)d_out;

    float *Qp, *Kp, *Vp, *Op;
    __nv_bfloat16 *xhi, *xlo, *ohi, *olo, *wth, *wtl;
    cudaGetSymbolAddress((void**)&Qp, g_Q);
    cudaGetSymbolAddress((void**)&Kp, g_K);
    cudaGetSymbolAddress((void**)&Vp, g_V);
    cudaGetSymbolAddress((void**)&Op, g_O);
    cudaGetSymbolAddress((void**)&xhi, g_xhi);
    cudaGetSymbolAddress((void**)&xlo, g_xlo);
    cudaGetSymbolAddress((void**)&ohi, g_ohi);
    cudaGetSymbolAddress((void**)&olo, g_olo);
    cudaGetSymbolAddress((void**)&wth, g_wth);
    cudaGetSymbolAddress((void**)&wtl, g_wtl);

    cudaFuncSetAttribute(gemm_hmma, cudaFuncAttributeMaxDynamicSharedMemorySize, GEMM_SMEM);

    const size_t WSZ = (size_t)DMODEL * DMODEL;
    int nElem = S_LEN * DMODEL;

    // Split x; transpose+split weights
    split_kernel<<<nElem / (256 * 4), 256>>>(x, xhi, xlo);
    dim3 tgrid(DMODEL / 32, DMODEL / 32);
    dim3 tblk(32, 8);
    wt_split_kernel<<<tgrid, tblk>>>(wq, wth + 0 * WSZ, wtl + 0 * WSZ);
    wt_split_kernel<<<tgrid, tblk>>>(wk, wth + 1 * WSZ, wtl + 1 * WSZ);
    wt_split_kernel<<<tgrid, tblk>>>(wv, wth + 2 * WSZ, wtl + 2 * WSZ);
    wt_split_kernel<<<tgrid, tblk>>>(wo, wth + 3 * WSZ, wtl + 3 * WSZ);

    // QKV GEMMs on tensor cores (legacy HMMA path)
    dim3 gg(DMODEL / 128, DMODEL / 128);
    gemm_hmma<<<gg, 256, GEMM_SMEM>>>(xhi, xlo, wth + 0 * WSZ, wtl + 0 * WSZ, Qp);
    gemm_hmma<<<gg, 256, GEMM_SMEM>>>(xhi, xlo, wth + 1 * WSZ, wtl + 1 * WSZ, Kp);
    gemm_hmma<<<gg, 256, GEMM_SMEM>>>(xhi, xlo, wth + 2 * WSZ, wtl + 2 * WSZ, Vp);

    int pairs = S_LEN * NH * (HD / 2);
    rope_kernel<<<pairs / 256, 256>>>(fcos, fsin);

    attn_kernel<<<dim3(S_LEN / BQ, NH), 256>>>();

    // Output projection
    split_kernel<<<nElem / (256 * 4), 256>>>(Op, ohi, olo);
    gemm_hmma<<<gg, 256, GEMM_SMEM>>>(ohi, olo, wth + 3 * WSZ, wtl + 3 * WSZ, out);
}

// round 7
// speedup vs baseline: 4.8119x; 3.9217x over previous
#include <cuda_runtime.h>
#include <cuda_bf16.h>
#include <math.h>
#include <stdint.h>

#define S_LEN 2048
#define DMODEL 2048
#define NH 16
#define HD 128

// ---------------------------------------------------------------------------
// Scratch (__device__ globals; allocation-free rule)
// ---------------------------------------------------------------------------
__device__ float g_Q[S_LEN * DMODEL];
__device__ float g_K[S_LEN * DMODEL];
__device__ float g_V[S_LEN * DMODEL];
__device__ float g_O[S_LEN * DMODEL];

__device__ __nv_bfloat16 g_xhi[S_LEN * DMODEL];
__device__ __nv_bfloat16 g_xlo[S_LEN * DMODEL];
__device__ __nv_bfloat16 g_ohi[S_LEN * DMODEL];
__device__ __nv_bfloat16 g_olo[S_LEN * DMODEL];
__device__ __nv_bfloat16 g_wth[4][DMODEL * DMODEL];  // transposed [N][K] hi
__device__ __nv_bfloat16 g_wtl[4][DMODEL * DMODEL];  // transposed [N][K] lo

// Attention operands, head-major
__device__ __nv_bfloat16 g_Qh[NH * S_LEN * HD];   // [h][s][d]
__device__ __nv_bfloat16 g_Ql[NH * S_LEN * HD];
__device__ __nv_bfloat16 g_Kh[NH * S_LEN * HD];
__device__ __nv_bfloat16 g_Kl[NH * S_LEN * HD];
__device__ __nv_bfloat16 g_Vth[NH * HD * S_LEN];  // [h][d][s]
__device__ __nv_bfloat16 g_Vtl[NH * HD * S_LEN];

// ---------------------------------------------------------------------------
// Helpers
// ---------------------------------------------------------------------------
__device__ __forceinline__ void cp16(uint32_t s, const void* g) {
    asm volatile("cp.async.cg.shared.global [%0], [%1], 16;" :: "r"(s), "l"(g) : "memory");
}
__device__ __forceinline__ uint32_t smem_u32(const void* p) {
    uint32_t a;
    asm("{ .reg .u64 t; cvta.to.shared.u64 t, %1; cvt.u32.u64 %0, t; }"
        : "=r"(a) : "l"(p));
    return a;
}
__device__ __forceinline__ void mma16816(float* c, uint32_t a0, uint32_t a1,
                                         uint32_t a2, uint32_t a3,
                                         uint32_t b0, uint32_t b1) {
    asm volatile(
        "mma.sync.aligned.m16n8k16.row.col.f32.bf16.bf16.f32 "
        "{%0,%1,%2,%3}, {%4,%5,%6,%7}, {%8,%9}, {%0,%1,%2,%3};"
        : "+f"(c[0]), "+f"(c[1]), "+f"(c[2]), "+f"(c[3])
        : "r"(a0), "r"(a1), "r"(a2), "r"(a3), "r"(b0), "r"(b1));
}
// packed = {lo16 = lo, hi16 = hi}
__device__ __forceinline__ uint32_t pack_bf16(float lo, float hi) {
    uint32_t r;
    asm("cvt.rn.bf16x2.f32 %0, %1, %2;" : "=r"(r) : "f"(hi), "f"(lo));
    return r;
}
__device__ __forceinline__ float bf16lo_f(uint32_t p) { return __uint_as_float(p << 16); }
__device__ __forceinline__ float bf16hi_f(uint32_t p) { return __uint_as_float(p & 0xFFFF0000u); }

// ---------------------------------------------------------------------------
// Split fp32 -> bf16 hi/lo (elementwise)
// ---------------------------------------------------------------------------
__global__ void split_kernel(const float* __restrict__ src,
                             __nv_bfloat16* __restrict__ hi,
                             __nv_bfloat16* __restrict__ lo) {
    int i = (blockIdx.x * blockDim.x + threadIdx.x) * 4;
    float4 v = *(const float4*)(src + i);
    float vv[4] = {v.x, v.y, v.z, v.w};
#pragma unroll
    for (int j = 0; j < 4; j++) {
        __nv_bfloat16 h = __float2bfloat16(vv[j]);
        hi[i + j] = h;
        lo[i + j] = __float2bfloat16(vv[j] - __bfloat162float(h));
    }
}

// Transpose + split: W [K][N] row-major -> T [N][K] hi/lo
__global__ void wt_split_kernel(const float* __restrict__ W,
                                __nv_bfloat16* __restrict__ Thi,
                                __nv_bfloat16* __restrict__ Tlo) {
    __shared__ float tile[32][33];
    int n0 = blockIdx.x * 32, k0 = blockIdx.y * 32;
    int tx = threadIdx.x, ty = threadIdx.y;
#pragma unroll
    for (int r = 0; r < 32; r += 8)
        tile[ty + r][tx] = W[(size_t)(k0 + ty + r) * DMODEL + n0 + tx];
    __syncthreads();
#pragma unroll
    for (int r = 0; r < 32; r += 8) {
        float v = tile[tx][ty + r];
        size_t o = (size_t)(n0 + ty + r) * DMODEL + k0 + tx;
        __nv_bfloat16 h = __float2bfloat16(v);
        Thi[o] = h;
        Tlo[o] = __float2bfloat16(v - __bfloat162float(h));
    }
}

// ---------------------------------------------------------------------------
// HMMA split-bf16 GEMM (unchanged from R6)
// ---------------------------------------------------------------------------
#define BK2 32
#define NCHUNK2 (DMODEL / BK2)
#define ROWSTRIDE_W 20
#define TILE_BYTES (128 * 80)
#define TILE_WORDS (TILE_BYTES / 4)
#define BUF_STRIDE_B (4 * TILE_BYTES)
#define GEMM_SMEM (2 * BUF_STRIDE_B)

__device__ __forceinline__ void load_tile32(uint32_t sbase, const __nv_bfloat16* g,
                                            int row0, int k0, int tid) {
#pragma unroll
    for (int i = 0; i < 2; i++) {
        int slot = tid + i * 256;
        int row = slot >> 2;
        int j = slot & 3;
        cp16(sbase + row * 80 + j * 16,
             g + (size_t)(row0 + row) * DMODEL + k0 + j * 8);
    }
}

__global__ __launch_bounds__(256) void gemm_hmma(
        const __nv_bfloat16* __restrict__ Ahi,
        const __nv_bfloat16* __restrict__ Alo,
        const __nv_bfloat16* __restrict__ Bhi,
        const __nv_bfloat16* __restrict__ Blo,
        float* __restrict__ C) {
    extern __shared__ char smem[];
    uint32_t sb = smem_u32(smem);
    const uint32_t* sw = (const uint32_t*)smem;

    int tid = threadIdx.x;
    int wid = tid >> 5, lane = tid & 31;
    int wm = wid & 1, wn = wid >> 1;
    int g = lane >> 2, tq = lane & 3;
    int n0 = blockIdx.x * 128, m0 = blockIdx.y * 128;

    float acc[4][4][4];
#pragma unroll
    for (int i = 0; i < 4; i++)
#pragma unroll
        for (int j = 0; j < 4; j++)
#pragma unroll
            for (int k = 0; k < 4; k++) acc[i][j][k] = 0.f;

    {
        uint32_t b = sb;
        load_tile32(b, Ahi, m0, 0, tid);
        load_tile32(b + TILE_BYTES, Alo, m0, 0, tid);
        load_tile32(b + 2 * TILE_BYTES, Bhi, n0, 0, tid);
        load_tile32(b + 3 * TILE_BYTES, Blo, n0, 0, tid);
        asm volatile("cp.async.commit_group;" ::: "memory");
    }

    for (int c = 0; c < NCHUNK2; ++c) {
        if (c + 1 < NCHUNK2) {
            uint32_t nb = sb + ((c + 1) & 1) * BUF_STRIDE_B;
            int k0 = (c + 1) * BK2;
            load_tile32(nb, Ahi, m0, k0, tid);
            load_tile32(nb + TILE_BYTES, Alo, m0, k0, tid);
            load_tile32(nb + 2 * TILE_BYTES, Bhi, n0, k0, tid);
            load_tile32(nb + 3 * TILE_BYTES, Blo, n0, k0, tid);
            asm volatile("cp.async.commit_group;" ::: "memory");
            asm volatile("cp.async.wait_group 1;" ::: "memory");
        } else {
            asm volatile("cp.async.wait_group 0;" ::: "memory");
        }
        __syncthreads();

        uint32_t wbase = ((c & 1) * BUF_STRIDE_B) >> 2;
        const uint32_t wAh = wbase;
        const uint32_t wAl = wbase + TILE_WORDS;
        const uint32_t wBh = wbase + 2 * TILE_WORDS;
        const uint32_t wBl = wbase + 3 * TILE_WORDS;

#pragma unroll
        for (int ks = 0; ks < 2; ks++) {
            int kw = ks * 8 + tq;
            uint32_t arow[4], brow[4];
#pragma unroll
            for (int mf = 0; mf < 4; mf++)
                arow[mf] = (uint32_t)(wm * 64 + mf * 16 + g) * ROWSTRIDE_W;
#pragma unroll
            for (int nf = 0; nf < 4; nf++)
                brow[nf] = (uint32_t)(wn * 32 + nf * 8 + g) * ROWSTRIDE_W;

            uint32_t ah[4][4], bh[4][2];
#pragma unroll
            for (int mf = 0; mf < 4; mf++) {
                ah[mf][0] = sw[wAh + arow[mf] + kw];
                ah[mf][1] = sw[wAh + arow[mf] + 8 * ROWSTRIDE_W + kw];
                ah[mf][2] = sw[wAh + arow[mf] + kw + 4];
                ah[mf][3] = sw[wAh + arow[mf] + 8 * ROWSTRIDE_W + kw + 4];
            }
#pragma unroll
            for (int nf = 0; nf < 4; nf++) {
                bh[nf][0] = sw[wBh + brow[nf] + kw];
                bh[nf][1] = sw[wBh + brow[nf] + kw + 4];
            }
#pragma unroll
            for (int mf = 0; mf < 4; mf++)
#pragma unroll
                for (int nf = 0; nf < 4; nf++)
                    mma16816(acc[mf][nf], ah[mf][0], ah[mf][1], ah[mf][2], ah[mf][3],
                             bh[nf][0], bh[nf][1]);

            uint32_t bl[4][2];
#pragma unroll
            for (int nf = 0; nf < 4; nf++) {
                bl[nf][0] = sw[wBl + brow[nf] + kw];
                bl[nf][1] = sw[wBl + brow[nf] + kw + 4];
            }
#pragma unroll
            for (int mf = 0; mf < 4; mf++)
#pragma unroll
                for (int nf = 0; nf < 4; nf++)
                    mma16816(acc[mf][nf], ah[mf][0], ah[mf][1], ah[mf][2], ah[mf][3],
                             bl[nf][0], bl[nf][1]);

            uint32_t al[4][4];
#pragma unroll
            for (int mf = 0; mf < 4; mf++) {
                al[mf][0] = sw[wAl + arow[mf] + kw];
                al[mf][1] = sw[wAl + arow[mf] + 8 * ROWSTRIDE_W + kw];
                al[mf][2] = sw[wAl + arow[mf] + kw + 4];
                al[mf][3] = sw[wAl + arow[mf] + 8 * ROWSTRIDE_W + kw + 4];
            }
#pragma unroll
            for (int mf = 0; mf < 4; mf++)
#pragma unroll
                for (int nf = 0; nf < 4; nf++)
                    mma16816(acc[mf][nf], al[mf][0], al[mf][1], al[mf][2], al[mf][3],
                             bh[nf][0], bh[nf][1]);
        }
        __syncthreads();
    }

#pragma unroll
    for (int mf = 0; mf < 4; mf++) {
#pragma unroll
        for (int nf = 0; nf < 4; nf++) {
            int row = m0 + wm * 64 + mf * 16 + g;
            int col = n0 + wn * 32 + nf * 8 + 2 * tq;
            float2 v0 = {acc[mf][nf][0], acc[mf][nf][1]};
            float2 v1 = {acc[mf][nf][2], acc[mf][nf][3]};
            *(float2*)&C[(size_t)row * DMODEL + col] = v0;
            *(float2*)&C[(size_t)(row + 8) * DMODEL + col] = v1;
        }
    }
}

// ---------------------------------------------------------------------------
// RoPE + split to head-major bf16 hi/lo for Q and K
// ---------------------------------------------------------------------------
__global__ void rope_split_kernel(const float* __restrict__ fcos,
                                  const float* __restrict__ fsin) {
    int p = blockIdx.x * blockDim.x + threadIdx.x;
    int i = p & 63;            // pair index (d = 2i, 2i+1)
    int h = (p >> 6) & 15;
    int s = p >> 10;

    float c  = fcos[s * 64 + i];
    float sn = fsin[s * 64 + i];
    size_t src = (size_t)s * DMODEL + h * HD + 2 * i;
    size_t dst = (size_t)h * (S_LEN * HD) + (size_t)s * HD + 2 * i;

    float q0 = g_Q[src], q1 = g_Q[src + 1];
    float r0 = q0 * c - q1 * sn;
    float r1 = q0 * sn + q1 * c;
    __nv_bfloat16 h0 = __float2bfloat16(r0), h1 = __float2bfloat16(r1);
    *(__nv_bfloat162*)&g_Qh[dst] = {h0, h1};
    *(__nv_bfloat162*)&g_Ql[dst] = {__float2bfloat16(r0 - __bfloat162float(h0)),
                                    __float2bfloat16(r1 - __bfloat162float(h1))};

    float k0 = g_K[src], k1 = g_K[src + 1];
    float t0 = k0 * c - k1 * sn;
    float t1 = k0 * sn + k1 * c;
    __nv_bfloat16 u0 = __float2bfloat16(t0), u1 = __float2bfloat16(t1);
    *(__nv_bfloat162*)&g_Kh[dst] = {u0, u1};
    *(__nv_bfloat162*)&g_Kl[dst] = {__float2bfloat16(t0 - __bfloat162float(u0)),
                                    __float2bfloat16(t1 - __bfloat162float(u1))};
}

// V: [s][h*128+d] fp32 -> Vt [h][d][s] bf16 hi/lo
__global__ void v_split_t_kernel() {
    __shared__ float tile[32][33];
    int s0 = blockIdx.x * 32, d0 = blockIdx.y * 32, h = blockIdx.z;
    int tx = threadIdx.x, ty = threadIdx.y;
#pragma unroll
    for (int r = 0; r < 32; r += 8)
        tile[ty + r][tx] = g_V[(size_t)(s0 + ty + r) * DMODEL + h * HD + d0 + tx];
    __syncthreads();
#pragma unroll
    for (int r = 0; r < 32; r += 8) {
        float v = tile[tx][ty + r];
        size_t o = (size_t)(h * HD + d0 + ty + r) * S_LEN + s0 + tx;
        __nv_bfloat16 hh = __float2bfloat16(v);
        g_Vth[o] = hh;
        g_Vtl[o] = __float2bfloat16(v - __bfloat162float(hh));
    }
}

// ---------------------------------------------------------------------------
// FA2-style HMMA flash attention. BQ=BKV=64, 4 warps, 1 head per CTA.
// Split-bf16 3-term for QK^T and PV. Register softmax with poly softcap.
// Smem (words): Qh[64*68] Ql KH KL at stride 68 (row = 128 bf16 + 8 pad)
//               Vth[128*36] Vtl (row = 64 bf16 + 8 pad)
// ---------------------------------------------------------------------------
#define QH_W 0
#define QL_W (64 * 68)
#define KH_W (2 * 64 * 68)
#define KL_W (3 * 64 * 68)
#define VH_W (4 * 64 * 68)
#define VL_W (4 * 64 * 68 + 128 * 36)
#define ATTN_SMEM ((4 * 64 * 68 + 2 * 128 * 36) * 4)   // 106496 B

__global__ __launch_bounds__(128) void attn_hmma() {
    extern __shared__ char smem[];
    uint32_t sb = smem_u32(smem);
    const uint32_t* s32 = (const uint32_t*)smem;

    int tid = threadIdx.x;
    int w = tid >> 5, lane = tid & 31;
    int g = lane >> 2, tq = lane & 3;
    int h = blockIdx.y;
    int qb = gridDim.x - 1 - blockIdx.x;     // big tiles first

    const __nv_bfloat16* Qhp = g_Qh + (size_t)h * (S_LEN * HD);
    const __nv_bfloat16* Qlp = g_Ql + (size_t)h * (S_LEN * HD);
    const __nv_bfloat16* Khp = g_Kh + (size_t)h * (S_LEN * HD);
    const __nv_bfloat16* Klp = g_Kl + (size_t)h * (S_LEN * HD);
    const __nv_bfloat16* Vhp = g_Vth + (size_t)h * (HD * S_LEN);
    const __nv_bfloat16* Vlp = g_Vtl + (size_t)h * (HD * S_LEN);

    // Load Q tile hi/lo: 64 rows x 256B = 16 cp16/row
#pragma unroll
    for (int i = 0; i < 8; i++) {
        int slot = tid + i * 128;             // 1024
        int row = slot >> 4, j = slot & 15;
        cp16(sb + (QH_W + row * 68) * 4 + j * 16,
             Qhp + (size_t)(qb * 64 + row) * HD + j * 8);
    }
#pragma unroll
    for (int i = 0; i < 8; i++) {
        int slot = tid + i * 128;
        int row = slot >> 4, j = slot & 15;
        cp16(sb + (QL_W + row * 68) * 4 + j * 16,
             Qlp + (size_t)(qb * 64 + row) * HD + j * 8);
    }
    asm volatile("cp.async.commit_group;" ::: "memory");

    float of[16][4];
#pragma unroll
    for (int i = 0; i < 16; i++)
#pragma unroll
        for (int j = 0; j < 4; j++) of[i][j] = 0.f;
    float m0 = -INFINITY, m1 = -INFINITY, l0 = 0.f, l1 = 0.f;

    const float inv_sqrt_hd = 0.08838834764831845f;
    const int qrow0 = qb * 64 + w * 16 + g;
    const int qrow1 = qrow0 + 8;
    const uint32_t arow = (uint32_t)(w * 16 + g) * 68;

    for (int kb = 0; kb <= qb; ++kb) {
        __syncthreads();   // previous tile's MMAs done everywhere
        // Load K hi/lo [64][128] and Vt hi/lo [128][64]
#pragma unroll
        for (int i = 0; i < 8; i++) {
            int slot = tid + i * 128;
            int row = slot >> 4, j = slot & 15;
            cp16(sb + (KH_W + row * 68) * 4 + j * 16,
                 Khp + (size_t)(kb * 64 + row) * HD + j * 8);
        }
#pragma unroll
        for (int i = 0; i < 8; i++) {
            int slot = tid + i * 128;
            int row = slot >> 4, j = slot & 15;
            cp16(sb + (KL_W + row * 68) * 4 + j * 16,
                 Klp + (size_t)(kb * 64 + row) * HD + j * 8);
        }
#pragma unroll
        for (int i = 0; i < 8; i++) {
            int slot = tid + i * 128;
            int row = slot >> 3, j = slot & 7;
            cp16(sb + (VH_W + row * 36) * 4 + j * 16,
                 Vhp + (size_t)row * S_LEN + kb * 64 + j * 8);
        }
#pragma unroll
        for (int i = 0; i < 8; i++) {
            int slot = tid + i * 128;
            int row = slot >> 3, j = slot & 7;
            cp16(sb + (VL_W + row * 36) * 4 + j * 16,
                 Vlp + (size_t)row * S_LEN + kb * 64 + j * 8);
        }
        asm volatile("cp.async.commit_group;" ::: "memory");
        asm volatile("cp.async.wait_group 0;" ::: "memory");
        __syncthreads();

        // --- S = Q K^T (3-term split) ---
        float sf[8][4];
#pragma unroll
        for (int i = 0; i < 8; i++)
#pragma unroll
            for (int j = 0; j < 4; j++) sf[i][j] = 0.f;

#pragma unroll
        for (int ks = 0; ks < 8; ks++) {
            int kw = ks * 8 + tq;
            uint32_t ah0 = s32[QH_W + arow + kw];
            uint32_t ah1 = s32[QH_W + arow + 8 * 68 + kw];
            uint32_t ah2 = s32[QH_W + arow + kw + 4];
            uint32_t ah3 = s32[QH_W + arow + 8 * 68 + kw + 4];
            uint32_t al0 = s32[QL_W + arow + kw];
            uint32_t al1 = s32[QL_W + arow + 8 * 68 + kw];
            uint32_t al2 = s32[QL_W + arow + kw + 4];
            uint32_t al3 = s32[QL_W + arow + 8 * 68 + kw + 4];
#pragma unroll
            for (int nf = 0; nf < 8; nf++) {
                uint32_t brow = (uint32_t)(nf * 8 + g) * 68;
                uint32_t bh0 = s32[KH_W + brow + kw];
                uint32_t bh1 = s32[KH_W + brow + kw + 4];
                uint32_t bl0 = s32[KL_W + brow + kw];
                uint32_t bl1 = s32[KL_W + brow + kw + 4];
                mma16816(sf[nf], ah0, ah1, ah2, ah3, bh0, bh1);
                mma16816(sf[nf], ah0, ah1, ah2, ah3, bl0, bl1);
                mma16816(sf[nf], al0, al1, al2, al3, bh0, bh1);
            }
        }

        // --- softcap + mask + online softmax (registers) ---
        float mloc0 = -INFINITY, mloc1 = -INFINITY;
        bool diag = (kb == qb);
#pragma unroll
        for (int nf = 0; nf < 8; nf++) {
#pragma unroll
            for (int cc = 0; cc < 2; cc++) {
                int kcol = kb * 64 + nf * 8 + 2 * tq + cc;
                // rows g
                float s = sf[nf][cc] * inv_sqrt_hd;
                float t = s * s * 0.0004f;
                s = s * (1.f - t * (0.3333333333f - 0.1333333333f * t));
                if (diag && kcol > qrow0) s = -INFINITY;
                sf[nf][cc] = s;
                mloc0 = fmaxf(mloc0, s);
                // rows g+8
                float s2 = sf[nf][cc + 2] * inv_sqrt_hd;
                float t2 = s2 * s2 * 0.0004f;
                s2 = s2 * (1.f - t2 * (0.3333333333f - 0.1333333333f * t2));
                if (diag && kcol > qrow1) s2 = -INFINITY;
                sf[nf][cc + 2] = s2;
                mloc1 = fmaxf(mloc1, s2);
            }
        }
        mloc0 = fmaxf(mloc0, __shfl_xor_sync(0xFFFFFFFF, mloc0, 1));
        mloc0 = fmaxf(mloc0, __shfl_xor_sync(0xFFFFFFFF, mloc0, 2));
        mloc1 = fmaxf(mloc1, __shfl_xor_sync(0xFFFFFFFF, mloc1, 1));
        mloc1 = fmaxf(mloc1, __shfl_xor_sync(0xFFFFFFFF, mloc1, 2));

        float mn0 = fmaxf(m0, mloc0), mn1 = fmaxf(m1, mloc1);
        float cf0 = __expf(m0 - mn0), cf1 = __expf(m1 - mn1);
        m0 = mn0; m1 = mn1;

        float ls0 = 0.f, ls1 = 0.f;
#pragma unroll
        for (int nf = 0; nf < 8; nf++) {
#pragma unroll
            for (int cc = 0; cc < 2; cc++) {
                float p = __expf(sf[nf][cc] - mn0);
                sf[nf][cc] = p; ls0 += p;
                float p2 = __expf(sf[nf][cc + 2] - mn1);
                sf[nf][cc + 2] = p2; ls1 += p2;
            }
        }
        ls0 += __shfl_xor_sync(0xFFFFFFFF, ls0, 1);
        ls0 += __shfl_xor_sync(0xFFFFFFFF, ls0, 2);
        ls1 += __shfl_xor_sync(0xFFFFFFFF, ls1, 1);
        ls1 += __shfl_xor_sync(0xFFFFFFFF, ls1, 2);
        l0 = l0 * cf0 + ls0;
        l1 = l1 * cf1 + ls1;

#pragma unroll
        for (int i = 0; i < 16; i++) {
            of[i][0] *= cf0; of[i][1] *= cf0;
            of[i][2] *= cf1; of[i][3] *= cf1;
        }

        // --- O += P V (3-term split), P from registers ---
#pragma unroll
        for (int ksv = 0; ksv < 4; ksv++) {
            float c00 = sf[2 * ksv][0],     c01 = sf[2 * ksv][1];
            float c02 = sf[2 * ksv][2],     c03 = sf[2 * ksv][3];
            float c10 = sf[2 * ksv + 1][0], c11 = sf[2 * ksv + 1][1];
            float c12 = sf[2 * ksv + 1][2], c13 = sf[2 * ksv + 1][3];
            uint32_t pa0 = pack_bf16(c00, c01);
            uint32_t pa1 = pack_bf16(c02, c03);
            uint32_t pa2 = pack_bf16(c10, c11);
            uint32_t pa3 = pack_bf16(c12, c13);
            uint32_t pl0 = pack_bf16(c00 - bf16lo_f(pa0), c01 - bf16hi_f(pa0));
            uint32_t pl1 = pack_bf16(c02 - bf16lo_f(pa1), c03 - bf16hi_f(pa1));
            uint32_t pl2 = pack_bf16(c10 - bf16lo_f(pa2), c11 - bf16hi_f(pa2));
            uint32_t pl3 = pack_bf16(c12 - bf16lo_f(pa3), c13 - bf16hi_f(pa3));
            int kvw = ksv * 8 + tq;
#pragma unroll
            for (int nf2 = 0; nf2 < 16; nf2++) {
                uint32_t brow = (uint32_t)(nf2 * 8 + g) * 36;
                uint32_t vh0 = s32[VH_W + brow + kvw];
                uint32_t vh1 = s32[VH_W + brow + kvw + 4];
                uint32_t vl0 = s32[VL_W + brow + kvw];
                uint32_t vl1 = s32[VL_W + brow + kvw + 4];
                mma16816(of[nf2], pa0, pa1, pa2, pa3, vh0, vh1);
                mma16816(of[nf2], pa0, pa1, pa2, pa3, vl0, vl1);
                mma16816(of[nf2], pl0, pl1, pl2, pl3, vh0, vh1);
            }
        }
    }

    // normalize + write to g_O [s][h*128+d]
    float il0 = 1.f / l0, il1 = 1.f / l1;
#pragma unroll
    for (int nf2 = 0; nf2 < 16; nf2++) {
        int col = h * HD + nf2 * 8 + 2 * tq;
        float2 v0 = {of[nf2][0] * il0, of[nf2][1] * il0};
        float2 v1 = {of[nf2][2] * il1, of[nf2][3] * il1};
        *(float2*)&g_O[(size_t)qrow0 * DMODEL + col] = v0;
        *(float2*)&g_O[(size_t)qrow1 * DMODEL + col] = v1;
    }
}

// ---------------------------------------------------------------------------
// Launch
// ---------------------------------------------------------------------------
extern "C" void kernel_launch(void* const* d_in, const int* in_sizes, int n_in,
                              void* d_out, int out_size) {
    const float* x    = (const float*)d_in[0];
    const float* wq   = (const float*)d_in[1];
    const float* wk   = (const float*)d_in[2];
    const float* wv   = (const float*)d_in[3];
    const float* wo   = (const float*)d_in[4];
    const float* fcos = (const float*)d_in[5];
    const float* fsin = (const float*)d_in[6];
    float* out = (float*)d_out;

    float *Qp, *Kp, *Vp, *Op;
    __nv_bfloat16 *xhi, *xlo, *ohi, *olo, *wth, *wtl;
    cudaGetSymbolAddress((void**)&Qp, g_Q);
    cudaGetSymbolAddress((void**)&Kp, g_K);
    cudaGetSymbolAddress((void**)&Vp, g_V);
    cudaGetSymbolAddress((void**)&Op, g_O);
    cudaGetSymbolAddress((void**)&xhi, g_xhi);
    cudaGetSymbolAddress((void**)&xlo, g_xlo);
    cudaGetSymbolAddress((void**)&ohi, g_ohi);
    cudaGetSymbolAddress((void**)&olo, g_olo);
    cudaGetSymbolAddress((void**)&wth, g_wth);
    cudaGetSymbolAddress((void**)&wtl, g_wtl);

    cudaFuncSetAttribute(gemm_hmma, cudaFuncAttributeMaxDynamicSharedMemorySize, GEMM_SMEM);
    cudaFuncSetAttribute(attn_hmma, cudaFuncAttributeMaxDynamicSharedMemorySize, ATTN_SMEM);

    const size_t WSZ = (size_t)DMODEL * DMODEL;
    int nElem = S_LEN * DMODEL;

    split_kernel<<<nElem / (256 * 4), 256>>>(x, xhi, xlo);
    dim3 tgrid(DMODEL / 32, DMODEL / 32);
    dim3 tblk(32, 8);
    wt_split_kernel<<<tgrid, tblk>>>(wq, wth + 0 * WSZ, wtl + 0 * WSZ);
    wt_split_kernel<<<tgrid, tblk>>>(wk, wth + 1 * WSZ, wtl + 1 * WSZ);
    wt_split_kernel<<<tgrid, tblk>>>(wv, wth + 2 * WSZ, wtl + 2 * WSZ);
    wt_split_kernel<<<tgrid, tblk>>>(wo, wth + 3 * WSZ, wtl + 3 * WSZ);

    dim3 gg(DMODEL / 128, DMODEL / 128);
    gemm_hmma<<<gg, 256, GEMM_SMEM>>>(xhi, xlo, wth + 0 * WSZ, wtl + 0 * WSZ, Qp);
    gemm_hmma<<<gg, 256, GEMM_SMEM>>>(xhi, xlo, wth + 1 * WSZ, wtl + 1 * WSZ, Kp);
    gemm_hmma<<<gg, 256, GEMM_SMEM>>>(xhi, xlo, wth + 2 * WSZ, wtl + 2 * WSZ, Vp);

    int pairs = S_LEN * NH * (HD / 2);
    rope_split_kernel<<<pairs / 256, 256>>>(fcos, fsin);
    v_split_t_kernel<<<dim3(S_LEN / 32, HD / 32, NH), dim3(32, 8)>>>();

    attn_hmma<<<dim3(S_LEN / 64, NH), 128, ATTN_SMEM>>>();

    split_kernel<<<nElem / (256 * 4), 256>>>(Op, ohi, olo);
    gemm_hmma<<<gg, 256, GEMM_SMEM>>>(ohi, olo, wth + 3 * WSZ, wtl + 3 * WSZ, out);
}

// round 8
// speedup vs baseline: 5.2397x; 1.0889x over previous
#include <cuda_runtime.h>
#include <cuda_bf16.h>
#include <math.h>
#include <stdint.h>

#define S_LEN 2048
#define DMODEL 2048
#define NH 16
#define HD 128

// ---------------------------------------------------------------------------
// Scratch (__device__ globals; allocation-free rule)
// ---------------------------------------------------------------------------
__device__ float g_Q[S_LEN * DMODEL];
__device__ float g_K[S_LEN * DMODEL];
__device__ float g_V[S_LEN * DMODEL];

__device__ __nv_bfloat16 g_xhi[S_LEN * DMODEL];
__device__ __nv_bfloat16 g_xlo[S_LEN * DMODEL];
__device__ __nv_bfloat16 g_ohi[S_LEN * DMODEL];
__device__ __nv_bfloat16 g_olo[S_LEN * DMODEL];
__device__ __nv_bfloat16 g_wth[4][DMODEL * DMODEL];  // transposed [N][K] hi
__device__ __nv_bfloat16 g_wtl[4][DMODEL * DMODEL];  // transposed [N][K] lo

// Attention operands, head-major
__device__ __nv_bfloat16 g_Qh[NH * S_LEN * HD];   // [h][s][d]
__device__ __nv_bfloat16 g_Ql[NH * S_LEN * HD];
__device__ __nv_bfloat16 g_Kh[NH * S_LEN * HD];
__device__ __nv_bfloat16 g_Kl[NH * S_LEN * HD];
__device__ __nv_bfloat16 g_Vth[NH * HD * S_LEN];  // [h][d][s]
__device__ __nv_bfloat16 g_Vtl[NH * HD * S_LEN];

// ---------------------------------------------------------------------------
// Helpers
// ---------------------------------------------------------------------------
__device__ __forceinline__ void cp16(uint32_t s, const void* g) {
    asm volatile("cp.async.cg.shared.global [%0], [%1], 16;" :: "r"(s), "l"(g) : "memory");
}
__device__ __forceinline__ uint32_t smem_u32(const void* p) {
    uint32_t a;
    asm("{ .reg .u64 t; cvta.to.shared.u64 t, %1; cvt.u32.u64 %0, t; }"
        : "=r"(a) : "l"(p));
    return a;
}
__device__ __forceinline__ void mma16816(float* c, uint32_t a0, uint32_t a1,
                                         uint32_t a2, uint32_t a3,
                                         uint32_t b0, uint32_t b1) {
    asm volatile(
        "mma.sync.aligned.m16n8k16.row.col.f32.bf16.bf16.f32 "
        "{%0,%1,%2,%3}, {%4,%5,%6,%7}, {%8,%9}, {%0,%1,%2,%3};"
        : "+f"(c[0]), "+f"(c[1]), "+f"(c[2]), "+f"(c[3])
        : "r"(a0), "r"(a1), "r"(a2), "r"(a3), "r"(b0), "r"(b1));
}
// packed = {lo16 = lo, hi16 = hi}
__device__ __forceinline__ uint32_t pack_bf16(float lo, float hi) {
    uint32_t r;
    asm("cvt.rn.bf16x2.f32 %0, %1, %2;" : "=r"(r) : "f"(hi), "f"(lo));
    return r;
}
__device__ __forceinline__ float bf16lo_f(uint32_t p) { return __uint_as_float(p << 16); }
__device__ __forceinline__ float bf16hi_f(uint32_t p) { return __uint_as_float(p & 0xFFFF0000u); }

// ---------------------------------------------------------------------------
// Split fp32 -> bf16 hi/lo (elementwise)
// ---------------------------------------------------------------------------
__global__ void split_kernel(const float* __restrict__ src,
                             __nv_bfloat16* __restrict__ hi,
                             __nv_bfloat16* __restrict__ lo) {
    int i = (blockIdx.x * blockDim.x + threadIdx.x) * 4;
    float4 v = *(const float4*)(src + i);
    float vv[4] = {v.x, v.y, v.z, v.w};
#pragma unroll
    for (int j = 0; j < 4; j++) {
        __nv_bfloat16 h = __float2bfloat16(vv[j]);
        hi[i + j] = h;
        lo[i + j] = __float2bfloat16(vv[j] - __bfloat162float(h));
    }
}

// Transpose + split all 4 weights: W [K][N] -> T [N][K] hi/lo. blockIdx.z = which W.
__global__ void wt_split4_kernel(const float* __restrict__ w0,
                                 const float* __restrict__ w1,
                                 const float* __restrict__ w2,
                                 const float* __restrict__ w3,
                                 __nv_bfloat16* __restrict__ Thi,
                                 __nv_bfloat16* __restrict__ Tlo) {
    __shared__ float tile[32][33];
    int z = blockIdx.z;
    const float* W = (z == 0) ? w0 : (z == 1) ? w1 : (z == 2) ? w2 : w3;
    Thi += (size_t)z * DMODEL * DMODEL;
    Tlo += (size_t)z * DMODEL * DMODEL;
    int n0 = blockIdx.x * 32, k0 = blockIdx.y * 32;
    int tx = threadIdx.x, ty = threadIdx.y;
#pragma unroll
    for (int r = 0; r < 32; r += 8)
        tile[ty + r][tx] = W[(size_t)(k0 + ty + r) * DMODEL + n0 + tx];
    __syncthreads();
#pragma unroll
    for (int r = 0; r < 32; r += 8) {
        float v = tile[tx][ty + r];
        size_t o = (size_t)(n0 + ty + r) * DMODEL + k0 + tx;
        __nv_bfloat16 h = __float2bfloat16(v);
        Thi[o] = h;
        Tlo[o] = __float2bfloat16(v - __bfloat162float(h));
    }
}

// ---------------------------------------------------------------------------
// HMMA split-bf16 GEMM (R6 core + 2 CTAs/SM)
// ---------------------------------------------------------------------------
#define BK2 32
#define NCHUNK2 (DMODEL / BK2)
#define ROWSTRIDE_W 20
#define TILE_BYTES (128 * 80)
#define TILE_WORDS (TILE_BYTES / 4)
#define BUF_STRIDE_B (4 * TILE_BYTES)
#define GEMM_SMEM (2 * BUF_STRIDE_B)

__device__ __forceinline__ void load_tile32(uint32_t sbase, const __nv_bfloat16* g,
                                            int row0, int k0, int tid) {
#pragma unroll
    for (int i = 0; i < 2; i++) {
        int slot = tid + i * 256;
        int row = slot >> 2;
        int j = slot & 3;
        cp16(sbase + row * 80 + j * 16,
             g + (size_t)(row0 + row) * DMODEL + k0 + j * 8);
    }
}

__global__ __launch_bounds__(256, 2) void gemm_hmma(
        const __nv_bfloat16* __restrict__ Ahi,
        const __nv_bfloat16* __restrict__ Alo,
        const __nv_bfloat16* __restrict__ Bhi,
        const __nv_bfloat16* __restrict__ Blo,
        float* __restrict__ C) {
    extern __shared__ char smem[];
    uint32_t sb = smem_u32(smem);
    const uint32_t* sw = (const uint32_t*)smem;

    int tid = threadIdx.x;
    int wid = tid >> 5, lane = tid & 31;
    int wm = wid & 1, wn = wid >> 1;
    int g = lane >> 2, tq = lane & 3;
    int n0 = blockIdx.x * 128, m0 = blockIdx.y * 128;

    float acc[4][4][4];
#pragma unroll
    for (int i = 0; i < 4; i++)
#pragma unroll
        for (int j = 0; j < 4; j++)
#pragma unroll
            for (int k = 0; k < 4; k++) acc[i][j][k] = 0.f;

    {
        uint32_t b = sb;
        load_tile32(b, Ahi, m0, 0, tid);
        load_tile32(b + TILE_BYTES, Alo, m0, 0, tid);
        load_tile32(b + 2 * TILE_BYTES, Bhi, n0, 0, tid);
        load_tile32(b + 3 * TILE_BYTES, Blo, n0, 0, tid);
        asm volatile("cp.async.commit_group;" ::: "memory");
    }

    for (int c = 0; c < NCHUNK2; ++c) {
        if (c + 1 < NCHUNK2) {
            uint32_t nb = sb + ((c + 1) & 1) * BUF_STRIDE_B;
            int k0 = (c + 1) * BK2;
            load_tile32(nb, Ahi, m0, k0, tid);
            load_tile32(nb + TILE_BYTES, Alo, m0, k0, tid);
            load_tile32(nb + 2 * TILE_BYTES, Bhi, n0, k0, tid);
            load_tile32(nb + 3 * TILE_BYTES, Blo, n0, k0, tid);
            asm volatile("cp.async.commit_group;" ::: "memory");
            asm volatile("cp.async.wait_group 1;" ::: "memory");
        } else {
            asm volatile("cp.async.wait_group 0;" ::: "memory");
        }
        __syncthreads();

        uint32_t wbase = ((c & 1) * BUF_STRIDE_B) >> 2;
        const uint32_t wAh = wbase;
        const uint32_t wAl = wbase + TILE_WORDS;
        const uint32_t wBh = wbase + 2 * TILE_WORDS;
        const uint32_t wBl = wbase + 3 * TILE_WORDS;

#pragma unroll
        for (int ks = 0; ks < 2; ks++) {
            int kw = ks * 8 + tq;
            uint32_t arow[4], brow[4];
#pragma unroll
            for (int mf = 0; mf < 4; mf++)
                arow[mf] = (uint32_t)(wm * 64 + mf * 16 + g) * ROWSTRIDE_W;
#pragma unroll
            for (int nf = 0; nf < 4; nf++)
                brow[nf] = (uint32_t)(wn * 32 + nf * 8 + g) * ROWSTRIDE_W;

            uint32_t ah[4][4], bh[4][2];
#pragma unroll
            for (int mf = 0; mf < 4; mf++) {
                ah[mf][0] = sw[wAh + arow[mf] + kw];
                ah[mf][1] = sw[wAh + arow[mf] + 8 * ROWSTRIDE_W + kw];
                ah[mf][2] = sw[wAh + arow[mf] + kw + 4];
                ah[mf][3] = sw[wAh + arow[mf] + 8 * ROWSTRIDE_W + kw + 4];
            }
#pragma unroll
            for (int nf = 0; nf < 4; nf++) {
                bh[nf][0] = sw[wBh + brow[nf] + kw];
                bh[nf][1] = sw[wBh + brow[nf] + kw + 4];
            }
#pragma unroll
            for (int mf = 0; mf < 4; mf++)
#pragma unroll
                for (int nf = 0; nf < 4; nf++)
                    mma16816(acc[mf][nf], ah[mf][0], ah[mf][1], ah[mf][2], ah[mf][3],
                             bh[nf][0], bh[nf][1]);

            uint32_t bl[4][2];
#pragma unroll
            for (int nf = 0; nf < 4; nf++) {
                bl[nf][0] = sw[wBl + brow[nf] + kw];
                bl[nf][1] = sw[wBl + brow[nf] + kw + 4];
            }
#pragma unroll
            for (int mf = 0; mf < 4; mf++)
#pragma unroll
                for (int nf = 0; nf < 4; nf++)
                    mma16816(acc[mf][nf], ah[mf][0], ah[mf][1], ah[mf][2], ah[mf][3],
                             bl[nf][0], bl[nf][1]);

            uint32_t al[4][4];
#pragma unroll
            for (int mf = 0; mf < 4; mf++) {
                al[mf][0] = sw[wAl + arow[mf] + kw];
                al[mf][1] = sw[wAl + arow[mf] + 8 * ROWSTRIDE_W + kw];
                al[mf][2] = sw[wAl + arow[mf] + kw + 4];
                al[mf][3] = sw[wAl + arow[mf] + 8 * ROWSTRIDE_W + kw + 4];
            }
#pragma unroll
            for (int mf = 0; mf < 4; mf++)
#pragma unroll
                for (int nf = 0; nf < 4; nf++)
                    mma16816(acc[mf][nf], al[mf][0], al[mf][1], al[mf][2], al[mf][3],
                             bh[nf][0], bh[nf][1]);
        }
        __syncthreads();
    }

#pragma unroll
    for (int mf = 0; mf < 4; mf++) {
#pragma unroll
        for (int nf = 0; nf < 4; nf++) {
            int row = m0 + wm * 64 + mf * 16 + g;
            int col = n0 + wn * 32 + nf * 8 + 2 * tq;
            float2 v0 = {acc[mf][nf][0], acc[mf][nf][1]};
            float2 v1 = {acc[mf][nf][2], acc[mf][nf][3]};
            *(float2*)&C[(size_t)row * DMODEL + col] = v0;
            *(float2*)&C[(size_t)(row + 8) * DMODEL + col] = v1;
        }
    }
}

// ---------------------------------------------------------------------------
// RoPE + split to head-major bf16 hi/lo for Q and K
// ---------------------------------------------------------------------------
__global__ void rope_split_kernel(const float* __restrict__ fcos,
                                  const float* __restrict__ fsin) {
    int p = blockIdx.x * blockDim.x + threadIdx.x;
    int i = p & 63;
    int h = (p >> 6) & 15;
    int s = p >> 10;

    float c  = fcos[s * 64 + i];
    float sn = fsin[s * 64 + i];
    size_t src = (size_t)s * DMODEL + h * HD + 2 * i;
    size_t dst = (size_t)h * (S_LEN * HD) + (size_t)s * HD + 2 * i;

    float q0 = g_Q[src], q1 = g_Q[src + 1];
    float r0 = q0 * c - q1 * sn;
    float r1 = q0 * sn + q1 * c;
    __nv_bfloat16 h0 = __float2bfloat16(r0), h1 = __float2bfloat16(r1);
    *(__nv_bfloat162*)&g_Qh[dst] = {h0, h1};
    *(__nv_bfloat162*)&g_Ql[dst] = {__float2bfloat16(r0 - __bfloat162float(h0)),
                                    __float2bfloat16(r1 - __bfloat162float(h1))};

    float k0 = g_K[src], k1 = g_K[src + 1];
    float t0 = k0 * c - k1 * sn;
    float t1 = k0 * sn + k1 * c;
    __nv_bfloat16 u0 = __float2bfloat16(t0), u1 = __float2bfloat16(t1);
    *(__nv_bfloat162*)&g_Kh[dst] = {u0, u1};
    *(__nv_bfloat162*)&g_Kl[dst] = {__float2bfloat16(t0 - __bfloat162float(u0)),
                                    __float2bfloat16(t1 - __bfloat162float(u1))};
}

// V: [s][h*128+d] fp32 -> Vt [h][d][s] bf16 hi/lo
__global__ void v_split_t_kernel() {
    __shared__ float tile[32][33];
    int s0 = blockIdx.x * 32, d0 = blockIdx.y * 32, h = blockIdx.z;
    int tx = threadIdx.x, ty = threadIdx.y;
#pragma unroll
    for (int r = 0; r < 32; r += 8)
        tile[ty + r][tx] = g_V[(size_t)(s0 + ty + r) * DMODEL + h * HD + d0 + tx];
    __syncthreads();
#pragma unroll
    for (int r = 0; r < 32; r += 8) {
        float v = tile[tx][ty + r];
        size_t o = (size_t)(h * HD + d0 + ty + r) * S_LEN + s0 + tx;
        __nv_bfloat16 hh = __float2bfloat16(v);
        g_Vth[o] = hh;
        g_Vtl[o] = __float2bfloat16(v - __bfloat162float(hh));
    }
}

// ---------------------------------------------------------------------------
// FA2-style HMMA flash attention with split-group K/V pipelining.
// BQ=BKV=64, 4 warps, 1 head per CTA. Writes g_ohi/g_olo directly.
// ---------------------------------------------------------------------------
#define QH_W 0
#define QL_W (64 * 68)
#define KH_W (2 * 64 * 68)
#define KL_W (3 * 64 * 68)
#define VH_W (4 * 64 * 68)
#define VL_W (4 * 64 * 68 + 128 * 36)
#define ATTN_SMEM ((4 * 64 * 68 + 2 * 128 * 36) * 4)   // 106496 B

__global__ __launch_bounds__(128) void attn_hmma() {
    extern __shared__ char smem[];
    uint32_t sb = smem_u32(smem);
    const uint32_t* s32 = (const uint32_t*)smem;

    int tid = threadIdx.x;
    int w = tid >> 5, lane = tid & 31;
    int g = lane >> 2, tq = lane & 3;
    int h = blockIdx.y;
    int qb = gridDim.x - 1 - blockIdx.x;     // big tiles first

    const __nv_bfloat16* Qhp = g_Qh + (size_t)h * (S_LEN * HD);
    const __nv_bfloat16* Qlp = g_Ql + (size_t)h * (S_LEN * HD);
    const __nv_bfloat16* Khp = g_Kh + (size_t)h * (S_LEN * HD);
    const __nv_bfloat16* Klp = g_Kl + (size_t)h * (S_LEN * HD);
    const __nv_bfloat16* Vhp = g_Vth + (size_t)h * (HD * S_LEN);
    const __nv_bfloat16* Vlp = g_Vtl + (size_t)h * (HD * S_LEN);

    // ---- group 1: Q tile hi/lo ----
#pragma unroll
    for (int i = 0; i < 8; i++) {
        int slot = tid + i * 128;
        int row = slot >> 4, j = slot & 15;
        cp16(sb + (QH_W + row * 68) * 4 + j * 16,
             Qhp + (size_t)(qb * 64 + row) * HD + j * 8);
    }
#pragma unroll
    for (int i = 0; i < 8; i++) {
        int slot = tid + i * 128;
        int row = slot >> 4, j = slot & 15;
        cp16(sb + (QL_W + row * 68) * 4 + j * 16,
             Qlp + (size_t)(qb * 64 + row) * HD + j * 8);
    }
    asm volatile("cp.async.commit_group;" ::: "memory");

    // ---- group 2: K_0 ; group 3: V_0 ----
#pragma unroll
    for (int i = 0; i < 8; i++) {
        int slot = tid + i * 128;
        int row = slot >> 4, j = slot & 15;
        cp16(sb + (KH_W + row * 68) * 4 + j * 16, Khp + (size_t)row * HD + j * 8);
    }
#pragma unroll
    for (int i = 0; i < 8; i++) {
        int slot = tid + i * 128;
        int row = slot >> 4, j = slot & 15;
        cp16(sb + (KL_W + row * 68) * 4 + j * 16, Klp + (size_t)row * HD + j * 8);
    }
    asm volatile("cp.async.commit_group;" ::: "memory");
#pragma unroll
    for (int i = 0; i < 8; i++) {
        int slot = tid + i * 128;
        int row = slot >> 3, j = slot & 7;
        cp16(sb + (VH_W + row * 36) * 4 + j * 16, Vhp + (size_t)row * S_LEN + j * 8);
    }
#pragma unroll
    for (int i = 0; i < 8; i++) {
        int slot = tid + i * 128;
        int row = slot >> 3, j = slot & 7;
        cp16(sb + (VL_W + row * 36) * 4 + j * 16, Vlp + (size_t)row * S_LEN + j * 8);
    }
    asm volatile("cp.async.commit_group;" ::: "memory");

    float of[16][4];
#pragma unroll
    for (int i = 0; i < 16; i++)
#pragma unroll
        for (int j = 0; j < 4; j++) of[i][j] = 0.f;
    float m0 = -INFINITY, m1 = -INFINITY, l0 = 0.f, l1 = 0.f;

    const float inv_sqrt_hd = 0.08838834764831845f;
    const int qrow0 = qb * 64 + w * 16 + g;
    const int qrow1 = qrow0 + 8;
    const uint32_t arow = (uint32_t)(w * 16 + g) * 68;

    for (int kb = 0; kb <= qb; ++kb) {
        // K_kb (and Q on first iter) ready; V_kb may still be in flight
        asm volatile("cp.async.wait_group 1;" ::: "memory");
        __syncthreads();

        // --- S = Q K^T (3-term split) ---
        float sf[8][4];
#pragma unroll
        for (int i = 0; i < 8; i++)
#pragma unroll
            for (int j = 0; j < 4; j++) sf[i][j] = 0.f;

#pragma unroll
        for (int ks = 0; ks < 8; ks++) {
            int kw = ks * 8 + tq;
            uint32_t ah0 = s32[QH_W + arow + kw];
            uint32_t ah1 = s32[QH_W + arow + 8 * 68 + kw];
            uint32_t ah2 = s32[QH_W + arow + kw + 4];
            uint32_t ah3 = s32[QH_W + arow + 8 * 68 + kw + 4];
            uint32_t al0 = s32[QL_W + arow + kw];
            uint32_t al1 = s32[QL_W + arow + 8 * 68 + kw];
            uint32_t al2 = s32[QL_W + arow + kw + 4];
            uint32_t al3 = s32[QL_W + arow + 8 * 68 + kw + 4];
#pragma unroll
            for (int nf = 0; nf < 8; nf++) {
                uint32_t brow = (uint32_t)(nf * 8 + g) * 68;
                uint32_t bh0 = s32[KH_W + brow + kw];
                uint32_t bh1 = s32[KH_W + brow + kw + 4];
                uint32_t bl0 = s32[KL_W + brow + kw];
                uint32_t bl1 = s32[KL_W + brow + kw + 4];
                mma16816(sf[nf], ah0, ah1, ah2, ah3, bh0, bh1);
                mma16816(sf[nf], ah0, ah1, ah2, ah3, bl0, bl1);
                mma16816(sf[nf], al0, al1, al2, al3, bh0, bh1);
            }
        }
        __syncthreads();   // all warps finished reading K smem

        // prefetch K_{kb+1} (overlaps softmax + PV)
        if (kb + 1 <= qb) {
#pragma unroll
            for (int i = 0; i < 8; i++) {
                int slot = tid + i * 128;
                int row = slot >> 4, j = slot & 15;
                cp16(sb + (KH_W + row * 68) * 4 + j * 16,
                     Khp + (size_t)((kb + 1) * 64 + row) * HD + j * 8);
            }
#pragma unroll
            for (int i = 0; i < 8; i++) {
                int slot = tid + i * 128;
                int row = slot >> 4, j = slot & 15;
                cp16(sb + (KL_W + row * 68) * 4 + j * 16,
                     Klp + (size_t)((kb + 1) * 64 + row) * HD + j * 8);
            }
        }
        asm volatile("cp.async.commit_group;" ::: "memory");

        // --- softcap + mask + online softmax (registers) ---
        float mloc0 = -INFINITY, mloc1 = -INFINITY;
        bool diag = (kb == qb);
#pragma unroll
        for (int nf = 0; nf < 8; nf++) {
#pragma unroll
            for (int cc = 0; cc < 2; cc++) {
                int kcol = kb * 64 + nf * 8 + 2 * tq + cc;
                float s = sf[nf][cc] * inv_sqrt_hd;
                float t = s * s * 0.0004f;
                s = s * (1.f - t * (0.3333333333f - 0.1333333333f * t));
                if (diag && kcol > qrow0) s = -INFINITY;
                sf[nf][cc] = s;
                mloc0 = fmaxf(mloc0, s);
                float s2 = sf[nf][cc + 2] * inv_sqrt_hd;
                float t2 = s2 * s2 * 0.0004f;
                s2 = s2 * (1.f - t2 * (0.3333333333f - 0.1333333333f * t2));
                if (diag && kcol > qrow1) s2 = -INFINITY;
                sf[nf][cc + 2] = s2;
                mloc1 = fmaxf(mloc1, s2);
            }
        }
        mloc0 = fmaxf(mloc0, __shfl_xor_sync(0xFFFFFFFF, mloc0, 1));
        mloc0 = fmaxf(mloc0, __shfl_xor_sync(0xFFFFFFFF, mloc0, 2));
        mloc1 = fmaxf(mloc1, __shfl_xor_sync(0xFFFFFFFF, mloc1, 1));
        mloc1 = fmaxf(mloc1, __shfl_xor_sync(0xFFFFFFFF, mloc1, 2));

        float mn0 = fmaxf(m0, mloc0), mn1 = fmaxf(m1, mloc1);
        float cf0 = __expf(m0 - mn0), cf1 = __expf(m1 - mn1);
        m0 = mn0; m1 = mn1;

        float ls0 = 0.f, ls1 = 0.f;
#pragma unroll
        for (int nf = 0; nf < 8; nf++) {
#pragma unroll
            for (int cc = 0; cc < 2; cc++) {
                float p = __expf(sf[nf][cc] - mn0);
                sf[nf][cc] = p; ls0 += p;
                float p2 = __expf(sf[nf][cc + 2] - mn1);
                sf[nf][cc + 2] = p2; ls1 += p2;
            }
        }
        ls0 += __shfl_xor_sync(0xFFFFFFFF, ls0, 1);
        ls0 += __shfl_xor_sync(0xFFFFFFFF, ls0, 2);
        ls1 += __shfl_xor_sync(0xFFFFFFFF, ls1, 1);
        ls1 += __shfl_xor_sync(0xFFFFFFFF, ls1, 2);
        l0 = l0 * cf0 + ls0;
        l1 = l1 * cf1 + ls1;

#pragma unroll
        for (int i = 0; i < 16; i++) {
            of[i][0] *= cf0; of[i][1] *= cf0;
            of[i][2] *= cf1; of[i][3] *= cf1;
        }

        // V_kb ready (K_{kb+1} may still be in flight)
        asm volatile("cp.async.wait_group 1;" ::: "memory");
        __syncthreads();

        // --- O += P V (3-term split), P from registers ---
#pragma unroll
        for (int ksv = 0; ksv < 4; ksv++) {
            float c00 = sf[2 * ksv][0],     c01 = sf[2 * ksv][1];
            float c02 = sf[2 * ksv][2],     c03 = sf[2 * ksv][3];
            float c10 = sf[2 * ksv + 1][0], c11 = sf[2 * ksv + 1][1];
            float c12 = sf[2 * ksv + 1][2], c13 = sf[2 * ksv + 1][3];
            uint32_t pa0 = pack_bf16(c00, c01);
            uint32_t pa1 = pack_bf16(c02, c03);
            uint32_t pa2 = pack_bf16(c10, c11);
            uint32_t pa3 = pack_bf16(c12, c13);
            uint32_t pl0 = pack_bf16(c00 - bf16lo_f(pa0), c01 - bf16hi_f(pa0));
            uint32_t pl1 = pack_bf16(c02 - bf16lo_f(pa1), c03 - bf16hi_f(pa1));
            uint32_t pl2 = pack_bf16(c10 - bf16lo_f(pa2), c11 - bf16hi_f(pa2));
            uint32_t pl3 = pack_bf16(c12 - bf16lo_f(pa3), c13 - bf16hi_f(pa3));
            int kvw = ksv * 8 + tq;
#pragma unroll
            for (int nf2 = 0; nf2 < 16; nf2++) {
                uint32_t brow = (uint32_t)(nf2 * 8 + g) * 36;
                uint32_t vh0 = s32[VH_W + brow + kvw];
                uint32_t vh1 = s32[VH_W + brow + kvw + 4];
                uint32_t vl0 = s32[VL_W + brow + kvw];
                uint32_t vl1 = s32[VL_W + brow + kvw + 4];
                mma16816(of[nf2], pa0, pa1, pa2, pa3, vh0, vh1);
                mma16816(of[nf2], pa0, pa1, pa2, pa3, vl0, vl1);
                mma16816(of[nf2], pl0, pl1, pl2, pl3, vh0, vh1);
            }
        }
        __syncthreads();   // all warps finished reading V smem

        // prefetch V_{kb+1} (overlaps next tile's S compute)
        if (kb + 1 <= qb) {
#pragma unroll
            for (int i = 0; i < 8; i++) {
                int slot = tid + i * 128;
                int row = slot >> 3, j = slot & 7;
                cp16(sb + (VH_W + row * 36) * 4 + j * 16,
                     Vhp + (size_t)row * S_LEN + (kb + 1) * 64 + j * 8);
            }
#pragma unroll
            for (int i = 0; i < 8; i++) {
                int slot = tid + i * 128;
                int row = slot >> 3, j = slot & 7;
                cp16(sb + (VL_W + row * 36) * 4 + j * 16,
                     Vlp + (size_t)row * S_LEN + (kb + 1) * 64 + j * 8);
            }
        }
        asm volatile("cp.async.commit_group;" ::: "memory");
    }

    // normalize + write bf16 hi/lo directly (feeds O-projection GEMM)
    float il0 = 1.f / l0, il1 = 1.f / l1;
#pragma unroll
    for (int nf2 = 0; nf2 < 16; nf2++) {
        int col = h * HD + nf2 * 8 + 2 * tq;
        float o00 = of[nf2][0] * il0, o01 = of[nf2][1] * il0;
        float o10 = of[nf2][2] * il1, o11 = of[nf2][3] * il1;
        __nv_bfloat16 h00 = __float2bfloat16(o00), h01 = __float2bfloat16(o01);
        __nv_bfloat16 h10 = __float2bfloat16(o10), h11 = __float2bfloat16(o11);
        *(__nv_bfloat162*)&g_ohi[(size_t)qrow0 * DMODEL + col] = {h00, h01};
        *(__nv_bfloat162*)&g_ohi[(size_t)qrow1 * DMODEL + col] = {h10, h11};
        *(__nv_bfloat162*)&g_olo[(size_t)qrow0 * DMODEL + col] =
            {__float2bfloat16(o00 - __bfloat162float(h00)),
             __float2bfloat16(o01 - __bfloat162float(h01))};
        *(__nv_bfloat162*)&g_olo[(size_t)qrow1 * DMODEL + col] =
            {__float2bfloat16(o10 - __bfloat162float(h10)),
             __float2bfloat16(o11 - __bfloat162float(h11))};
    }
}

// ---------------------------------------------------------------------------
// Launch
// ---------------------------------------------------------------------------
extern "C" void kernel_launch(void* const* d_in, const int* in_sizes, int n_in,
                              void* d_out, int out_size) {
    const float* x    = (const float*)d_in[0];
    const float* wq   = (const float*)d_in[1];
    const float* wk   = (const float*)d_in[2];
    const float* wv   = (const float*)d_in[3];
    const float* wo   = (const float*)d_in[4];
    const float* fcos = (const float*)d_in[5];
    const float* fsin = (const float*)d_in[6];
    float* out = (float*)d_out;

    float *Qp, *Kp, *Vp;
    __nv_bfloat16 *xhi, *xlo, *ohi, *olo, *wth, *wtl;
    cudaGetSymbolAddress((void**)&Qp, g_Q);
    cudaGetSymbolAddress((void**)&Kp, g_K);
    cudaGetSymbolAddress((void**)&Vp, g_V);
    cudaGetSymbolAddress((void**)&xhi, g_xhi);
    cudaGetSymbolAddress((void**)&xlo, g_xlo);
    cudaGetSymbolAddress((void**)&ohi, g_ohi);
    cudaGetSymbolAddress((void**)&olo, g_olo);
    cudaGetSymbolAddress((void**)&wth, g_wth);
    cudaGetSymbolAddress((void**)&wtl, g_wtl);

    cudaFuncSetAttribute(gemm_hmma, cudaFuncAttributeMaxDynamicSharedMemorySize, GEMM_SMEM);
    cudaFuncSetAttribute(attn_hmma, cudaFuncAttributeMaxDynamicSharedMemorySize, ATTN_SMEM);

    const size_t WSZ = (size_t)DMODEL * DMODEL;
    int nElem = S_LEN * DMODEL;

    split_kernel<<<nElem / (256 * 4), 256>>>(x, xhi, xlo);
    wt_split4_kernel<<<dim3(DMODEL / 32, DMODEL / 32, 4), dim3(32, 8)>>>(
        wq, wk, wv, wo, wth, wtl);

    dim3 gg(DMODEL / 128, DMODEL / 128);
    gemm_hmma<<<gg, 256, GEMM_SMEM>>>(xhi, xlo, wth + 0 * WSZ, wtl + 0 * WSZ, Qp);
    gemm_hmma<<<gg, 256, GEMM_SMEM>>>(xhi, xlo, wth + 1 * WSZ, wtl + 1 * WSZ, Kp);
    gemm_hmma<<<gg, 256, GEMM_SMEM>>>(xhi, xlo, wth + 2 * WSZ, wtl + 2 * WSZ, Vp);

    int pairs = S_LEN * NH * (HD / 2);
    rope_split_kernel<<<pairs / 256, 256>>>(fcos, fsin);
    v_split_t_kernel<<<dim3(S_LEN / 32, HD / 32, NH), dim3(32, 8)>>>();

    attn_hmma<<<dim3(S_LEN / 64, NH), 128, ATTN_SMEM>>>();

    gemm_hmma<<<gg, 256, GEMM_SMEM>>>(ohi, olo, wth + 3 * WSZ, wtl + 3 * WSZ, out);
}

// round 9
// speedup vs baseline: 5.5265x; 1.0547x over previous
#include <cuda_runtime.h>
#include <cuda_bf16.h>
#include <math.h>
#include <stdint.h>

#define S_LEN 2048
#define DMODEL 2048
#define NH 16
#define HD 128

// ---------------------------------------------------------------------------
// Scratch (__device__ globals; allocation-free rule)
// ---------------------------------------------------------------------------
__device__ float g_Q[S_LEN * DMODEL];
__device__ float g_K[S_LEN * DMODEL];
__device__ float g_V[S_LEN * DMODEL];

__device__ __nv_bfloat16 g_xhi[S_LEN * DMODEL];
__device__ __nv_bfloat16 g_xlo[S_LEN * DMODEL];
__device__ __nv_bfloat16 g_ohi[S_LEN * DMODEL];
__device__ __nv_bfloat16 g_olo[S_LEN * DMODEL];
__device__ __nv_bfloat16 g_wth[4][DMODEL * DMODEL];  // transposed [N][K] hi
__device__ __nv_bfloat16 g_wtl[4][DMODEL * DMODEL];  // transposed [N][K] lo

// Attention operands, head-major
__device__ __nv_bfloat16 g_Qh[NH * S_LEN * HD];   // [h][s][d]
__device__ __nv_bfloat16 g_Ql[NH * S_LEN * HD];
__device__ __nv_bfloat16 g_Kh[NH * S_LEN * HD];
__device__ __nv_bfloat16 g_Kl[NH * S_LEN * HD];
__device__ __nv_bfloat16 g_Vth[NH * HD * S_LEN];  // [h][d][s]
__device__ __nv_bfloat16 g_Vtl[NH * HD * S_LEN];

// ---------------------------------------------------------------------------
// Helpers
// ---------------------------------------------------------------------------
__device__ __forceinline__ void cp16(uint32_t s, const void* g) {
    asm volatile("cp.async.cg.shared.global [%0], [%1], 16;" :: "r"(s), "l"(g) : "memory");
}
__device__ __forceinline__ uint32_t smem_u32(const void* p) {
    uint32_t a;
    asm("{ .reg .u64 t; cvta.to.shared.u64 t, %1; cvt.u32.u64 %0, t; }"
        : "=r"(a) : "l"(p));
    return a;
}
__device__ __forceinline__ void mma16816(float* c, uint32_t a0, uint32_t a1,
                                         uint32_t a2, uint32_t a3,
                                         uint32_t b0, uint32_t b1) {
    asm volatile(
        "mma.sync.aligned.m16n8k16.row.col.f32.bf16.bf16.f32 "
        "{%0,%1,%2,%3}, {%4,%5,%6,%7}, {%8,%9}, {%0,%1,%2,%3};"
        : "+f"(c[0]), "+f"(c[1]), "+f"(c[2]), "+f"(c[3])
        : "r"(a0), "r"(a1), "r"(a2), "r"(a3), "r"(b0), "r"(b1));
}
__device__ __forceinline__ void ldsm_x4(uint32_t& r0, uint32_t& r1,
                                        uint32_t& r2, uint32_t& r3, uint32_t addr) {
    asm volatile("ldmatrix.sync.aligned.m8n8.x4.shared.b16 {%0,%1,%2,%3}, [%4];"
                 : "=r"(r0), "=r"(r1), "=r"(r2), "=r"(r3) : "r"(addr));
}
// packed = {lo16 = lo, hi16 = hi}
__device__ __forceinline__ uint32_t pack_bf16(float lo, float hi) {
    uint32_t r;
    asm("cvt.rn.bf16x2.f32 %0, %1, %2;" : "=r"(r) : "f"(hi), "f"(lo));
    return r;
}
__device__ __forceinline__ float bf16lo_f(uint32_t p) { return __uint_as_float(p << 16); }
__device__ __forceinline__ float bf16hi_f(uint32_t p) { return __uint_as_float(p & 0xFFFF0000u); }

// ---------------------------------------------------------------------------
// Split fp32 -> bf16 hi/lo (elementwise)
// ---------------------------------------------------------------------------
__global__ void split_kernel(const float* __restrict__ src,
                             __nv_bfloat16* __restrict__ hi,
                             __nv_bfloat16* __restrict__ lo) {
    int i = (blockIdx.x * blockDim.x + threadIdx.x) * 4;
    float4 v = *(const float4*)(src + i);
    float vv[4] = {v.x, v.y, v.z, v.w};
#pragma unroll
    for (int j = 0; j < 4; j++) {
        __nv_bfloat16 h = __float2bfloat16(vv[j]);
        hi[i + j] = h;
        lo[i + j] = __float2bfloat16(vv[j] - __bfloat162float(h));
    }
}

// Transpose + split all 4 weights: W [K][N] -> T [N][K] hi/lo. blockIdx.z = which W.
__global__ void wt_split4_kernel(const float* __restrict__ w0,
                                 const float* __restrict__ w1,
                                 const float* __restrict__ w2,
                                 const float* __restrict__ w3,
                                 __nv_bfloat16* __restrict__ Thi,
                                 __nv_bfloat16* __restrict__ Tlo) {
    __shared__ float tile[32][33];
    int z = blockIdx.z;
    const float* W = (z == 0) ? w0 : (z == 1) ? w1 : (z == 2) ? w2 : w3;
    Thi += (size_t)z * DMODEL * DMODEL;
    Tlo += (size_t)z * DMODEL * DMODEL;
    int n0 = blockIdx.x * 32, k0 = blockIdx.y * 32;
    int tx = threadIdx.x, ty = threadIdx.y;
#pragma unroll
    for (int r = 0; r < 32; r += 8)
        tile[ty + r][tx] = W[(size_t)(k0 + ty + r) * DMODEL + n0 + tx];
    __syncthreads();
#pragma unroll
    for (int r = 0; r < 32; r += 8) {
        float v = tile[tx][ty + r];
        size_t o = (size_t)(n0 + ty + r) * DMODEL + k0 + tx;
        __nv_bfloat16 h = __float2bfloat16(v);
        Thi[o] = h;
        Tlo[o] = __float2bfloat16(v - __bfloat162float(h));
    }
}

// ---------------------------------------------------------------------------
// HMMA split-bf16 GEMM, ldmatrix fragment loads, 2 CTAs/SM.
// Smem row stride 80 B -> ldmatrix 8-row segments tile all 32 banks.
// ---------------------------------------------------------------------------
#define BK2 32
#define NCHUNK2 (DMODEL / BK2)
#define TILE_BYTES (128 * 80)
#define BUF_STRIDE_B (4 * TILE_BYTES)
#define GEMM_SMEM (2 * BUF_STRIDE_B)

__device__ __forceinline__ void load_tile32(uint32_t sbase, const __nv_bfloat16* g,
                                            int row0, int k0, int tid) {
#pragma unroll
    for (int i = 0; i < 2; i++) {
        int slot = tid + i * 256;
        int row = slot >> 2;
        int j = slot & 3;
        cp16(sbase + row * 80 + j * 16,
             g + (size_t)(row0 + row) * DMODEL + k0 + j * 8);
    }
}

__global__ __launch_bounds__(256, 2) void gemm_hmma(
        const __nv_bfloat16* __restrict__ Ahi,
        const __nv_bfloat16* __restrict__ Alo,
        const __nv_bfloat16* __restrict__ Bhi,
        const __nv_bfloat16* __restrict__ Blo,
        float* __restrict__ C) {
    extern __shared__ char smem[];
    uint32_t sb = smem_u32(smem);

    int tid = threadIdx.x;
    int wid = tid >> 5, lane = tid & 31;
    int wm = wid & 1, wn = wid >> 1;
    int g = lane >> 2, tq = lane & 3;
    int n0 = blockIdx.x * 128, m0 = blockIdx.y * 128;

    // ldmatrix lane-dependent base byte-offsets within a tile
    // A (x4: lanes 0-15 -> rows 0-15 @k, lanes 16-31 -> rows 0-15 @k+8)
    uint32_t a_base = (uint32_t)(wm * 64 + (lane & 15)) * 80 + (lane >> 4) * 16;
    // B (x4: matrix m = lane>>3; m>>1 selects nf sub-block, m&1 selects k half)
    uint32_t b_base = (uint32_t)(wn * 32 + ((lane >> 4) << 3) + (lane & 7)) * 80
                      + ((lane >> 3) & 1) * 16;

    float acc[4][4][4];
#pragma unroll
    for (int i = 0; i < 4; i++)
#pragma unroll
        for (int j = 0; j < 4; j++)
#pragma unroll
            for (int k = 0; k < 4; k++) acc[i][j][k] = 0.f;

    {
        uint32_t b = sb;
        load_tile32(b, Ahi, m0, 0, tid);
        load_tile32(b + TILE_BYTES, Alo, m0, 0, tid);
        load_tile32(b + 2 * TILE_BYTES, Bhi, n0, 0, tid);
        load_tile32(b + 3 * TILE_BYTES, Blo, n0, 0, tid);
        asm volatile("cp.async.commit_group;" ::: "memory");
    }

    for (int c = 0; c < NCHUNK2; ++c) {
        if (c + 1 < NCHUNK2) {
            uint32_t nb = sb + ((c + 1) & 1) * BUF_STRIDE_B;
            int k0 = (c + 1) * BK2;
            load_tile32(nb, Ahi, m0, k0, tid);
            load_tile32(nb + TILE_BYTES, Alo, m0, k0, tid);
            load_tile32(nb + 2 * TILE_BYTES, Bhi, n0, k0, tid);
            load_tile32(nb + 3 * TILE_BYTES, Blo, n0, k0, tid);
            asm volatile("cp.async.commit_group;" ::: "memory");
            asm volatile("cp.async.wait_group 1;" ::: "memory");
        } else {
            asm volatile("cp.async.wait_group 0;" ::: "memory");
        }
        __syncthreads();

        uint32_t bufb = sb + (c & 1) * BUF_STRIDE_B;
        uint32_t aAh = bufb + a_base;
        uint32_t aAl = bufb + TILE_BYTES + a_base;
        uint32_t aBh = bufb + 2 * TILE_BYTES + b_base;
        uint32_t aBl = bufb + 3 * TILE_BYTES + b_base;

#pragma unroll
        for (int ks = 0; ks < 2; ks++) {
            uint32_t koff = ks * 32;

            uint32_t ah[4][4], bh[4][2];
#pragma unroll
            for (int mf = 0; mf < 4; mf++)
                ldsm_x4(ah[mf][0], ah[mf][1], ah[mf][2], ah[mf][3],
                        aAh + mf * (16 * 80) + koff);
#pragma unroll
            for (int nfp = 0; nfp < 2; nfp++)
                ldsm_x4(bh[2 * nfp][0], bh[2 * nfp][1],
                        bh[2 * nfp + 1][0], bh[2 * nfp + 1][1],
                        aBh + nfp * (16 * 80) + koff);
#pragma unroll
            for (int mf = 0; mf < 4; mf++)
#pragma unroll
                for (int nf = 0; nf < 4; nf++)
                    mma16816(acc[mf][nf], ah[mf][0], ah[mf][1], ah[mf][2], ah[mf][3],
                             bh[nf][0], bh[nf][1]);

            uint32_t bl[4][2];
#pragma unroll
            for (int nfp = 0; nfp < 2; nfp++)
                ldsm_x4(bl[2 * nfp][0], bl[2 * nfp][1],
                        bl[2 * nfp + 1][0], bl[2 * nfp + 1][1],
                        aBl + nfp * (16 * 80) + koff);
#pragma unroll
            for (int mf = 0; mf < 4; mf++)
#pragma unroll
                for (int nf = 0; nf < 4; nf++)
                    mma16816(acc[mf][nf], ah[mf][0], ah[mf][1], ah[mf][2], ah[mf][3],
                             bl[nf][0], bl[nf][1]);

            uint32_t al[4][4];
#pragma unroll
            for (int mf = 0; mf < 4; mf++)
                ldsm_x4(al[mf][0], al[mf][1], al[mf][2], al[mf][3],
                        aAl + mf * (16 * 80) + koff);
#pragma unroll
            for (int mf = 0; mf < 4; mf++)
#pragma unroll
                for (int nf = 0; nf < 4; nf++)
                    mma16816(acc[mf][nf], al[mf][0], al[mf][1], al[mf][2], al[mf][3],
                             bh[nf][0], bh[nf][1]);
        }
        __syncthreads();
    }

#pragma unroll
    for (int mf = 0; mf < 4; mf++) {
#pragma unroll
        for (int nf = 0; nf < 4; nf++) {
            int row = m0 + wm * 64 + mf * 16 + g;
            int col = n0 + wn * 32 + nf * 8 + 2 * tq;
            float2 v0 = {acc[mf][nf][0], acc[mf][nf][1]};
            float2 v1 = {acc[mf][nf][2], acc[mf][nf][3]};
            *(float2*)&C[(size_t)row * DMODEL + col] = v0;
            *(float2*)&C[(size_t)(row + 8) * DMODEL + col] = v1;
        }
    }
}

// ---------------------------------------------------------------------------
// RoPE + split to head-major bf16 hi/lo for Q and K
// ---------------------------------------------------------------------------
__global__ void rope_split_kernel(const float* __restrict__ fcos,
                                  const float* __restrict__ fsin) {
    int p = blockIdx.x * blockDim.x + threadIdx.x;
    int i = p & 63;
    int h = (p >> 6) & 15;
    int s = p >> 10;

    float c  = fcos[s * 64 + i];
    float sn = fsin[s * 64 + i];
    size_t src = (size_t)s * DMODEL + h * HD + 2 * i;
    size_t dst = (size_t)h * (S_LEN * HD) + (size_t)s * HD + 2 * i;

    float q0 = g_Q[src], q1 = g_Q[src + 1];
    float r0 = q0 * c - q1 * sn;
    float r1 = q0 * sn + q1 * c;
    __nv_bfloat16 h0 = __float2bfloat16(r0), h1 = __float2bfloat16(r1);
    *(__nv_bfloat162*)&g_Qh[dst] = {h0, h1};
    *(__nv_bfloat162*)&g_Ql[dst] = {__float2bfloat16(r0 - __bfloat162float(h0)),
                                    __float2bfloat16(r1 - __bfloat162float(h1))};

    float k0 = g_K[src], k1 = g_K[src + 1];
    float t0 = k0 * c - k1 * sn;
    float t1 = k0 * sn + k1 * c;
    __nv_bfloat16 u0 = __float2bfloat16(t0), u1 = __float2bfloat16(t1);
    *(__nv_bfloat162*)&g_Kh[dst] = {u0, u1};
    *(__nv_bfloat162*)&g_Kl[dst] = {__float2bfloat16(t0 - __bfloat162float(u0)),
                                    __float2bfloat16(t1 - __bfloat162float(u1))};
}

// V: [s][h*128+d] fp32 -> Vt [h][d][s] bf16 hi/lo
__global__ void v_split_t_kernel() {
    __shared__ float tile[32][33];
    int s0 = blockIdx.x * 32, d0 = blockIdx.y * 32, h = blockIdx.z;
    int tx = threadIdx.x, ty = threadIdx.y;
#pragma unroll
    for (int r = 0; r < 32; r += 8)
        tile[ty + r][tx] = g_V[(size_t)(s0 + ty + r) * DMODEL + h * HD + d0 + tx];
    __syncthreads();
#pragma unroll
    for (int r = 0; r < 32; r += 8) {
        float v = tile[tx][ty + r];
        size_t o = (size_t)(h * HD + d0 + ty + r) * S_LEN + s0 + tx;
        __nv_bfloat16 hh = __float2bfloat16(v);
        g_Vth[o] = hh;
        g_Vtl[o] = __float2bfloat16(v - __bfloat162float(hh));
    }
}

// ---------------------------------------------------------------------------
// FA2-style HMMA flash attention with split-group K/V pipelining (unchanged R8)
// ---------------------------------------------------------------------------
#define QH_W 0
#define QL_W (64 * 68)
#define KH_W (2 * 64 * 68)
#define KL_W (3 * 64 * 68)
#define VH_W (4 * 64 * 68)
#define VL_W (4 * 64 * 68 + 128 * 36)
#define ATTN_SMEM ((4 * 64 * 68 + 2 * 128 * 36) * 4)   // 106496 B

__global__ __launch_bounds__(128) void attn_hmma() {
    extern __shared__ char smem[];
    uint32_t sb = smem_u32(smem);
    const uint32_t* s32 = (const uint32_t*)smem;

    int tid = threadIdx.x;
    int w = tid >> 5, lane = tid & 31;
    int g = lane >> 2, tq = lane & 3;
    int h = blockIdx.y;
    int qb = gridDim.x - 1 - blockIdx.x;

    const __nv_bfloat16* Qhp = g_Qh + (size_t)h * (S_LEN * HD);
    const __nv_bfloat16* Qlp = g_Ql + (size_t)h * (S_LEN * HD);
    const __nv_bfloat16* Khp = g_Kh + (size_t)h * (S_LEN * HD);
    const __nv_bfloat16* Klp = g_Kl + (size_t)h * (S_LEN * HD);
    const __nv_bfloat16* Vhp = g_Vth + (size_t)h * (HD * S_LEN);
    const __nv_bfloat16* Vlp = g_Vtl + (size_t)h * (HD * S_LEN);

#pragma unroll
    for (int i = 0; i < 8; i++) {
        int slot = tid + i * 128;
        int row = slot >> 4, j = slot & 15;
        cp16(sb + (QH_W + row * 68) * 4 + j * 16,
             Qhp + (size_t)(qb * 64 + row) * HD + j * 8);
    }
#pragma unroll
    for (int i = 0; i < 8; i++) {
        int slot = tid + i * 128;
        int row = slot >> 4, j = slot & 15;
        cp16(sb + (QL_W + row * 68) * 4 + j * 16,
             Qlp + (size_t)(qb * 64 + row) * HD + j * 8);
    }
    asm volatile("cp.async.commit_group;" ::: "memory");

#pragma unroll
    for (int i = 0; i < 8; i++) {
        int slot = tid + i * 128;
        int row = slot >> 4, j = slot & 15;
        cp16(sb + (KH_W + row * 68) * 4 + j * 16, Khp + (size_t)row * HD + j * 8);
    }
#pragma unroll
    for (int i = 0; i < 8; i++) {
        int slot = tid + i * 128;
        int row = slot >> 4, j = slot & 15;
        cp16(sb + (KL_W + row * 68) * 4 + j * 16, Klp + (size_t)row * HD + j * 8);
    }
    asm volatile("cp.async.commit_group;" ::: "memory");
#pragma unroll
    for (int i = 0; i < 8; i++) {
        int slot = tid + i * 128;
        int row = slot >> 3, j = slot & 7;
        cp16(sb + (VH_W + row * 36) * 4 + j * 16, Vhp + (size_t)row * S_LEN + j * 8);
    }
#pragma unroll
    for (int i = 0; i < 8; i++) {
        int slot = tid + i * 128;
        int row = slot >> 3, j = slot & 7;
        cp16(sb + (VL_W + row * 36) * 4 + j * 16, Vlp + (size_t)row * S_LEN + j * 8);
    }
    asm volatile("cp.async.commit_group;" ::: "memory");

    float of[16][4];
#pragma unroll
    for (int i = 0; i < 16; i++)
#pragma unroll
        for (int j = 0; j < 4; j++) of[i][j] = 0.f;
    float m0 = -INFINITY, m1 = -INFINITY, l0 = 0.f, l1 = 0.f;

    const float inv_sqrt_hd = 0.08838834764831845f;
    const int qrow0 = qb * 64 + w * 16 + g;
    const int qrow1 = qrow0 + 8;
    const uint32_t arow = (uint32_t)(w * 16 + g) * 68;

    for (int kb = 0; kb <= qb; ++kb) {
        asm volatile("cp.async.wait_group 1;" ::: "memory");
        __syncthreads();

        float sf[8][4];
#pragma unroll
        for (int i = 0; i < 8; i++)
#pragma unroll
            for (int j = 0; j < 4; j++) sf[i][j] = 0.f;

#pragma unroll
        for (int ks = 0; ks < 8; ks++) {
            int kw = ks * 8 + tq;
            uint32_t ah0 = s32[QH_W + arow + kw];
            uint32_t ah1 = s32[QH_W + arow + 8 * 68 + kw];
            uint32_t ah2 = s32[QH_W + arow + kw + 4];
            uint32_t ah3 = s32[QH_W + arow + 8 * 68 + kw + 4];
            uint32_t al0 = s32[QL_W + arow + kw];
            uint32_t al1 = s32[QL_W + arow + 8 * 68 + kw];
            uint32_t al2 = s32[QL_W + arow + kw + 4];
            uint32_t al3 = s32[QL_W + arow + 8 * 68 + kw + 4];
#pragma unroll
            for (int nf = 0; nf < 8; nf++) {
                uint32_t brow = (uint32_t)(nf * 8 + g) * 68;
                uint32_t bh0 = s32[KH_W + brow + kw];
                uint32_t bh1 = s32[KH_W + brow + kw + 4];
                uint32_t bl0 = s32[KL_W + brow + kw];
                uint32_t bl1 = s32[KL_W + brow + kw + 4];
                mma16816(sf[nf], ah0, ah1, ah2, ah3, bh0, bh1);
                mma16816(sf[nf], ah0, ah1, ah2, ah3, bl0, bl1);
                mma16816(sf[nf], al0, al1, al2, al3, bh0, bh1);
            }
        }
        __syncthreads();

        if (kb + 1 <= qb) {
#pragma unroll
            for (int i = 0; i < 8; i++) {
                int slot = tid + i * 128;
                int row = slot >> 4, j = slot & 15;
                cp16(sb + (KH_W + row * 68) * 4 + j * 16,
                     Khp + (size_t)((kb + 1) * 64 + row) * HD + j * 8);
            }
#pragma unroll
            for (int i = 0; i < 8; i++) {
                int slot = tid + i * 128;
                int row = slot >> 4, j = slot & 15;
                cp16(sb + (KL_W + row * 68) * 4 + j * 16,
                     Klp + (size_t)((kb + 1) * 64 + row) * HD + j * 8);
            }
        }
        asm volatile("cp.async.commit_group;" ::: "memory");

        float mloc0 = -INFINITY, mloc1 = -INFINITY;
        bool diag = (kb == qb);
#pragma unroll
        for (int nf = 0; nf < 8; nf++) {
#pragma unroll
            for (int cc = 0; cc < 2; cc++) {
                int kcol = kb * 64 + nf * 8 + 2 * tq + cc;
                float s = sf[nf][cc] * inv_sqrt_hd;
                float t = s * s * 0.0004f;
                s = s * (1.f - t * (0.3333333333f - 0.1333333333f * t));
                if (diag && kcol > qrow0) s = -INFINITY;
                sf[nf][cc] = s;
                mloc0 = fmaxf(mloc0, s);
                float s2 = sf[nf][cc + 2] * inv_sqrt_hd;
                float t2 = s2 * s2 * 0.0004f;
                s2 = s2 * (1.f - t2 * (0.3333333333f - 0.1333333333f * t2));
                if (diag && kcol > qrow1) s2 = -INFINITY;
                sf[nf][cc + 2] = s2;
                mloc1 = fmaxf(mloc1, s2);
            }
        }
        mloc0 = fmaxf(mloc0, __shfl_xor_sync(0xFFFFFFFF, mloc0, 1));
        mloc0 = fmaxf(mloc0, __shfl_xor_sync(0xFFFFFFFF, mloc0, 2));
        mloc1 = fmaxf(mloc1, __shfl_xor_sync(0xFFFFFFFF, mloc1, 1));
        mloc1 = fmaxf(mloc1, __shfl_xor_sync(0xFFFFFFFF, mloc1, 2));

        float mn0 = fmaxf(m0, mloc0), mn1 = fmaxf(m1, mloc1);
        float cf0 = __expf(m0 - mn0), cf1 = __expf(m1 - mn1);
        m0 = mn0; m1 = mn1;

        float ls0 = 0.f, ls1 = 0.f;
#pragma unroll
        for (int nf = 0; nf < 8; nf++) {
#pragma unroll
            for (int cc = 0; cc < 2; cc++) {
                float p = __expf(sf[nf][cc] - mn0);
                sf[nf][cc] = p; ls0 += p;
                float p2 = __expf(sf[nf][cc + 2] - mn1);
                sf[nf][cc + 2] = p2; ls1 += p2;
            }
        }
        ls0 += __shfl_xor_sync(0xFFFFFFFF, ls0, 1);
        ls0 += __shfl_xor_sync(0xFFFFFFFF, ls0, 2);
        ls1 += __shfl_xor_sync(0xFFFFFFFF, ls1, 1);
        ls1 += __shfl_xor_sync(0xFFFFFFFF, ls1, 2);
        l0 = l0 * cf0 + ls0;
        l1 = l1 * cf1 + ls1;

#pragma unroll
        for (int i = 0; i < 16; i++) {
            of[i][0] *= cf0; of[i][1] *= cf0;
            of[i][2] *= cf1; of[i][3] *= cf1;
        }

        asm volatile("cp.async.wait_group 1;" ::: "memory");
        __syncthreads();

#pragma unroll
        for (int ksv = 0; ksv < 4; ksv++) {
            float c00 = sf[2 * ksv][0],     c01 = sf[2 * ksv][1];
            float c02 = sf[2 * ksv][2],     c03 = sf[2 * ksv][3];
            float c10 = sf[2 * ksv + 1][0], c11 = sf[2 * ksv + 1][1];
            float c12 = sf[2 * ksv + 1][2], c13 = sf[2 * ksv + 1][3];
            uint32_t pa0 = pack_bf16(c00, c01);
            uint32_t pa1 = pack_bf16(c02, c03);
            uint32_t pa2 = pack_bf16(c10, c11);
            uint32_t pa3 = pack_bf16(c12, c13);
            uint32_t pl0 = pack_bf16(c00 - bf16lo_f(pa0), c01 - bf16hi_f(pa0));
            uint32_t pl1 = pack_bf16(c02 - bf16lo_f(pa1), c03 - bf16hi_f(pa1));
            uint32_t pl2 = pack_bf16(c10 - bf16lo_f(pa2), c11 - bf16hi_f(pa2));
            uint32_t pl3 = pack_bf16(c12 - bf16lo_f(pa3), c13 - bf16hi_f(pa3));
            int kvw = ksv * 8 + tq;
#pragma unroll
            for (int nf2 = 0; nf2 < 16; nf2++) {
                uint32_t brow = (uint32_t)(nf2 * 8 + g) * 36;
                uint32_t vh0 = s32[VH_W + brow + kvw];
                uint32_t vh1 = s32[VH_W + brow + kvw + 4];
                uint32_t vl0 = s32[VL_W + brow + kvw];
                uint32_t vl1 = s32[VL_W + brow + kvw + 4];
                mma16816(of[nf2], pa0, pa1, pa2, pa3, vh0, vh1);
                mma16816(of[nf2], pa0, pa1, pa2, pa3, vl0, vl1);
                mma16816(of[nf2], pl0, pl1, pl2, pl3, vh0, vh1);
            }
        }
        __syncthreads();

        if (kb + 1 <= qb) {
#pragma unroll
            for (int i = 0; i < 8; i++) {
                int slot = tid + i * 128;
                int row = slot >> 3, j = slot & 7;
                cp16(sb + (VH_W + row * 36) * 4 + j * 16,
                     Vhp + (size_t)row * S_LEN + (kb + 1) * 64 + j * 8);
            }
#pragma unroll
            for (int i = 0; i < 8; i++) {
                int slot = tid + i * 128;
                int row = slot >> 3, j = slot & 7;
                cp16(sb + (VL_W + row * 36) * 4 + j * 16,
                     Vlp + (size_t)row * S_LEN + (kb + 1) * 64 + j * 8);
            }
        }
        asm volatile("cp.async.commit_group;" ::: "memory");
    }

    float il0 = 1.f / l0, il1 = 1.f / l1;
#pragma unroll
    for (int nf2 = 0; nf2 < 16; nf2++) {
        int col = h * HD + nf2 * 8 + 2 * tq;
        float o00 = of[nf2][0] * il0, o01 = of[nf2][1] * il0;
        float o10 = of[nf2][2] * il1, o11 = of[nf2][3] * il1;
        __nv_bfloat16 h00 = __float2bfloat16(o00), h01 = __float2bfloat16(o01);
        __nv_bfloat16 h10 = __float2bfloat16(o10), h11 = __float2bfloat16(o11);
        *(__nv_bfloat162*)&g_ohi[(size_t)qrow0 * DMODEL + col] = {h00, h01};
        *(__nv_bfloat162*)&g_ohi[(size_t)qrow1 * DMODEL + col] = {h10, h11};
        *(__nv_bfloat162*)&g_olo[(size_t)qrow0 * DMODEL + col] =
            {__float2bfloat16(o00 - __bfloat162float(h00)),
             __float2bfloat16(o01 - __bfloat162float(h01))};
        *(__nv_bfloat162*)&g_olo[(size_t)qrow1 * DMODEL + col] =
            {__float2bfloat16(o10 - __bfloat162float(h10)),
             __float2bfloat16(o11 - __bfloat162float(h11))};
    }
}

// ---------------------------------------------------------------------------
// Launch
// ---------------------------------------------------------------------------
extern "C" void kernel_launch(void* const* d_in, const int* in_sizes, int n_in,
                              void* d_out, int out_size) {
    const float* x    = (const float*)d_in[0];
    const float* wq   = (const float*)d_in[1];
    const float* wk   = (const float*)d_in[2];
    const float* wv   = (const float*)d_in[3];
    const float* wo   = (const float*)d_in[4];
    const float* fcos = (const float*)d_in[5];
    const float* fsin = (const float*)d_in[6];
    float* out = (float*)d_out;

    float *Qp, *Kp, *Vp;
    __nv_bfloat16 *xhi, *xlo, *ohi, *olo, *wth, *wtl;
    cudaGetSymbolAddress((void**)&Qp, g_Q);
    cudaGetSymbolAddress((void**)&Kp, g_K);
    cudaGetSymbolAddress((void**)&Vp, g_V);
    cudaGetSymbolAddress((void**)&xhi, g_xhi);
    cudaGetSymbolAddress((void**)&xlo, g_xlo);
    cudaGetSymbolAddress((void**)&ohi, g_ohi);
    cudaGetSymbolAddress((void**)&olo, g_olo);
    cudaGetSymbolAddress((void**)&wth, g_wth);
    cudaGetSymbolAddress((void**)&wtl, g_wtl);

    cudaFuncSetAttribute(gemm_hmma, cudaFuncAttributeMaxDynamicSharedMemorySize, GEMM_SMEM);
    cudaFuncSetAttribute(attn_hmma, cudaFuncAttributeMaxDynamicSharedMemorySize, ATTN_SMEM);

    const size_t WSZ = (size_t)DMODEL * DMODEL;
    int nElem = S_LEN * DMODEL;

    split_kernel<<<nElem / (256 * 4), 256>>>(x, xhi, xlo);
    wt_split4_kernel<<<dim3(DMODEL / 32, DMODEL / 32, 4), dim3(32, 8)>>>(
        wq, wk, wv, wo, wth, wtl);

    dim3 gg(DMODEL / 128, DMODEL / 128);
    gemm_hmma<<<gg, 256, GEMM_SMEM>>>(xhi, xlo, wth + 0 * WSZ, wtl + 0 * WSZ, Qp);
    gemm_hmma<<<gg, 256, GEMM_SMEM>>>(xhi, xlo, wth + 1 * WSZ, wtl + 1 * WSZ, Kp);
    gemm_hmma<<<gg, 256, GEMM_SMEM>>>(xhi, xlo, wth + 2 * WSZ, wtl + 2 * WSZ, Vp);

    int pairs = S_LEN * NH * (HD / 2);
    rope_split_kernel<<<pairs / 256, 256>>>(fcos, fsin);
    v_split_t_kernel<<<dim3(S_LEN / 32, HD / 32, NH), dim3(32, 8)>>>();

    attn_hmma<<<dim3(S_LEN / 64, NH), 128, ATTN_SMEM>>>();

    gemm_hmma<<<gg, 256, GEMM_SMEM>>>(ohi, olo, wth + 3 * WSZ, wtl + 3 * WSZ, out);
}

// round 10
// speedup vs baseline: 6.4243x; 1.1625x over previous
#include <cuda_runtime.h>
#include <cuda_bf16.h>
#include <math.h>
#include <stdint.h>

#define S_LEN 2048
#define DMODEL 2048
#define NH 16
#define HD 128

// ---------------------------------------------------------------------------
// Scratch (__device__ globals; allocation-free rule)
// ---------------------------------------------------------------------------
__device__ float g_Q[S_LEN * DMODEL];
__device__ float g_K[S_LEN * DMODEL];
__device__ float g_V[S_LEN * DMODEL];

__device__ __nv_bfloat16 g_xhi[S_LEN * DMODEL];
__device__ __nv_bfloat16 g_xlo[S_LEN * DMODEL];
__device__ __nv_bfloat16 g_ohi[S_LEN * DMODEL];
__device__ __nv_bfloat16 g_olo[S_LEN * DMODEL];
__device__ __nv_bfloat16 g_wth[4][DMODEL * DMODEL];  // transposed [N][K] hi
__device__ __nv_bfloat16 g_wtl[4][DMODEL * DMODEL];  // transposed [N][K] lo

// Attention operands, head-major
__device__ __nv_bfloat16 g_Qh[NH * S_LEN * HD];   // [h][s][d]
__device__ __nv_bfloat16 g_Ql[NH * S_LEN * HD];
__device__ __nv_bfloat16 g_Kh[NH * S_LEN * HD];
__device__ __nv_bfloat16 g_Kl[NH * S_LEN * HD];
__device__ __nv_bfloat16 g_Vth[NH * HD * S_LEN];  // [h][d][s]
__device__ __nv_bfloat16 g_Vtl[NH * HD * S_LEN];

// ---------------------------------------------------------------------------
// Helpers
// ---------------------------------------------------------------------------
__device__ __forceinline__ void cp16(uint32_t s, const void* g) {
    asm volatile("cp.async.cg.shared.global [%0], [%1], 16;" :: "r"(s), "l"(g) : "memory");
}
__device__ __forceinline__ uint32_t smem_u32(const void* p) {
    uint32_t a;
    asm("{ .reg .u64 t; cvta.to.shared.u64 t, %1; cvt.u32.u64 %0, t; }"
        : "=r"(a) : "l"(p));
    return a;
}
__device__ __forceinline__ void mma16816(float* c, uint32_t a0, uint32_t a1,
                                         uint32_t a2, uint32_t a3,
                                         uint32_t b0, uint32_t b1) {
    asm volatile(
        "mma.sync.aligned.m16n8k16.row.col.f32.bf16.bf16.f32 "
        "{%0,%1,%2,%3}, {%4,%5,%6,%7}, {%8,%9}, {%0,%1,%2,%3};"
        : "+f"(c[0]), "+f"(c[1]), "+f"(c[2]), "+f"(c[3])
        : "r"(a0), "r"(a1), "r"(a2), "r"(a3), "r"(b0), "r"(b1));
}
__device__ __forceinline__ void ldsm_x4(uint32_t& r0, uint32_t& r1,
                                        uint32_t& r2, uint32_t& r3, uint32_t addr) {
    asm volatile("ldmatrix.sync.aligned.m8n8.x4.shared.b16 {%0,%1,%2,%3}, [%4];"
                 : "=r"(r0), "=r"(r1), "=r"(r2), "=r"(r3) : "r"(addr));
}
// packed = {lo16 = lo, hi16 = hi}
__device__ __forceinline__ uint32_t pack_bf16(float lo, float hi) {
    uint32_t r;
    asm("cvt.rn.bf16x2.f32 %0, %1, %2;" : "=r"(r) : "f"(hi), "f"(lo));
    return r;
}
__device__ __forceinline__ float bf16lo_f(uint32_t p) { return __uint_as_float(p << 16); }
__device__ __forceinline__ float bf16hi_f(uint32_t p) { return __uint_as_float(p & 0xFFFF0000u); }

// ---------------------------------------------------------------------------
// Split fp32 -> bf16 hi/lo (elementwise)
// ---------------------------------------------------------------------------
__global__ void split_kernel(const float* __restrict__ src,
                             __nv_bfloat16* __restrict__ hi,
                             __nv_bfloat16* __restrict__ lo) {
    int i = (blockIdx.x * blockDim.x + threadIdx.x) * 4;
    float4 v = *(const float4*)(src + i);
    float vv[4] = {v.x, v.y, v.z, v.w};
#pragma unroll
    for (int j = 0; j < 4; j++) {
        __nv_bfloat16 h = __float2bfloat16(vv[j]);
        hi[i + j] = h;
        lo[i + j] = __float2bfloat16(vv[j] - __bfloat162float(h));
    }
}

// Transpose + split all 4 weights: W [K][N] -> T [N][K] hi/lo. blockIdx.z = which W.
__global__ void wt_split4_kernel(const float* __restrict__ w0,
                                 const float* __restrict__ w1,
                                 const float* __restrict__ w2,
                                 const float* __restrict__ w3,
                                 __nv_bfloat16* __restrict__ Thi,
                                 __nv_bfloat16* __restrict__ Tlo) {
    __shared__ float tile[32][33];
    int z = blockIdx.z;
    const float* W = (z == 0) ? w0 : (z == 1) ? w1 : (z == 2) ? w2 : w3;
    Thi += (size_t)z * DMODEL * DMODEL;
    Tlo += (size_t)z * DMODEL * DMODEL;
    int n0 = blockIdx.x * 32, k0 = blockIdx.y * 32;
    int tx = threadIdx.x, ty = threadIdx.y;
#pragma unroll
    for (int r = 0; r < 32; r += 8)
        tile[ty + r][tx] = W[(size_t)(k0 + ty + r) * DMODEL + n0 + tx];
    __syncthreads();
#pragma unroll
    for (int r = 0; r < 32; r += 8) {
        float v = tile[tx][ty + r];
        size_t o = (size_t)(n0 + ty + r) * DMODEL + k0 + tx;
        __nv_bfloat16 h = __float2bfloat16(v);
        Thi[o] = h;
        Tlo[o] = __float2bfloat16(v - __bfloat162float(h));
    }
}

// ---------------------------------------------------------------------------
// HMMA split-bf16 GEMM. Swizzled 64B smem rows, 3-stage cp.async pipeline,
// ldmatrix fragments, 2 CTAs/SM. blockIdx.z selects weight/output (QKV fused).
// Swizzle: 16B-chunk j at row r stored at j ^ ((r>>1)&3).
// ---------------------------------------------------------------------------
#define BK2 32
#define NCHUNK2 (DMODEL / BK2)
#define TILE_BYTES (128 * 64)             // 8192
#define BUF_STRIDE_B (4 * TILE_BYTES)     // 32768
#define GEMM_SMEM (3 * BUF_STRIDE_B)      // 98304

__device__ __forceinline__ void load_tile_sw(uint32_t sbase, const __nv_bfloat16* g,
                                             int row0, int k0, int tid) {
#pragma unroll
    for (int i = 0; i < 2; i++) {
        int slot = tid + i * 256;
        int row = slot >> 2;
        int j = slot & 3;
        uint32_t dst = sbase + row * 64 + ((j ^ ((row >> 1) & 3)) << 4);
        cp16(dst, g + (size_t)(row0 + row) * DMODEL + k0 + j * 8);
    }
}

__device__ __forceinline__ void load_chunk(uint32_t buf, const __nv_bfloat16* Ahi,
                                           const __nv_bfloat16* Alo,
                                           const __nv_bfloat16* Bhi,
                                           const __nv_bfloat16* Blo,
                                           int m0, int n0, int k0, int tid) {
    load_tile_sw(buf, Ahi, m0, k0, tid);
    load_tile_sw(buf + TILE_BYTES, Alo, m0, k0, tid);
    load_tile_sw(buf + 2 * TILE_BYTES, Bhi, n0, k0, tid);
    load_tile_sw(buf + 3 * TILE_BYTES, Blo, n0, k0, tid);
}

__global__ __launch_bounds__(256, 2) void gemm_hmma(
        const __nv_bfloat16* __restrict__ Ahi,
        const __nv_bfloat16* __restrict__ Alo,
        const __nv_bfloat16* __restrict__ Wh,
        const __nv_bfloat16* __restrict__ Wl,
        float* __restrict__ C0, float* __restrict__ C1, float* __restrict__ C2,
        int zoff) {
    extern __shared__ char smem[];
    uint32_t sb = smem_u32(smem);

    const size_t WSZ = (size_t)DMODEL * DMODEL;
    int z = blockIdx.z;
    const __nv_bfloat16* Bhi = Wh + (size_t)(z + zoff) * WSZ;
    const __nv_bfloat16* Blo = Wl + (size_t)(z + zoff) * WSZ;
    float* C = (z == 0) ? C0 : (z == 1) ? C1 : C2;

    int tid = threadIdx.x;
    int wid = tid >> 5, lane = tid & 31;
    int wm = wid & 1, wn = wid >> 1;
    int g = lane >> 2, tq = lane & 3;
    int n0 = blockIdx.x * 128, m0 = blockIdx.y * 128;

    // ldmatrix lane addressing (swizzled)
    int a_rin = lane & 15;
    uint32_t a_j0 = lane >> 4;               // 16B-chunk for k-half
    uint32_t a_t  = (a_rin >> 1) & 3;        // swizzle XOR (row-pair)
    uint32_t a_rowb = (uint32_t)(wm * 64 + a_rin) * 64;

    int b_rin = ((lane >> 4) << 3) + (lane & 7);
    uint32_t b_j0 = (lane >> 3) & 1;
    uint32_t b_t  = (b_rin >> 1) & 3;
    uint32_t b_rowb = (uint32_t)(wn * 32 + b_rin) * 64;

    float acc[4][4][4];
#pragma unroll
    for (int i = 0; i < 4; i++)
#pragma unroll
        for (int j = 0; j < 4; j++)
#pragma unroll
            for (int k = 0; k < 4; k++) acc[i][j][k] = 0.f;

    // prologue: chunks 0,1 -> buffers 0,1
    load_chunk(sb, Ahi, Alo, Bhi, Blo, m0, n0, 0, tid);
    asm volatile("cp.async.commit_group;" ::: "memory");
    load_chunk(sb + BUF_STRIDE_B, Ahi, Alo, Bhi, Blo, m0, n0, BK2, tid);
    asm volatile("cp.async.commit_group;" ::: "memory");

    int bufc = 0;   // buffer index of chunk c
    for (int c = 0; c < NCHUNK2; ++c) {
        if (c + 1 < NCHUNK2) {
            asm volatile("cp.async.wait_group 1;" ::: "memory");
        } else {
            asm volatile("cp.async.wait_group 0;" ::: "memory");
        }
        __syncthreads();   // chunk c ready; all warps done with chunk c-1

        if (c + 2 < NCHUNK2) {
            int nb = bufc + 2; if (nb >= 3) nb -= 3;
            load_chunk(sb + nb * BUF_STRIDE_B, Ahi, Alo, Bhi, Blo,
                       m0, n0, (c + 2) * BK2, tid);
            asm volatile("cp.async.commit_group;" ::: "memory");
        }

        uint32_t bufb = sb + bufc * BUF_STRIDE_B;
        uint32_t tAh = bufb;
        uint32_t tAl = bufb + TILE_BYTES;
        uint32_t tBh = bufb + 2 * TILE_BYTES;
        uint32_t tBl = bufb + 3 * TILE_BYTES;

#pragma unroll
        for (int ks = 0; ks < 2; ks++) {
            uint32_t aoff = a_rowb + (((a_j0 + 2 * ks) ^ a_t) << 4);
            uint32_t boff = b_rowb + (((b_j0 + 2 * ks) ^ b_t) << 4);

            uint32_t ah[4][4], bh[4][2];
#pragma unroll
            for (int mf = 0; mf < 4; mf++)
                ldsm_x4(ah[mf][0], ah[mf][1], ah[mf][2], ah[mf][3],
                        tAh + mf * (16 * 64) + aoff);
#pragma unroll
            for (int nfp = 0; nfp < 2; nfp++)
                ldsm_x4(bh[2 * nfp][0], bh[2 * nfp][1],
                        bh[2 * nfp + 1][0], bh[2 * nfp + 1][1],
                        tBh + nfp * (16 * 64) + boff);
#pragma unroll
            for (int mf = 0; mf < 4; mf++)
#pragma unroll
                for (int nf = 0; nf < 4; nf++)
                    mma16816(acc[mf][nf], ah[mf][0], ah[mf][1], ah[mf][2], ah[mf][3],
                             bh[nf][0], bh[nf][1]);

            uint32_t bl[4][2];
#pragma unroll
            for (int nfp = 0; nfp < 2; nfp++)
                ldsm_x4(bl[2 * nfp][0], bl[2 * nfp][1],
                        bl[2 * nfp + 1][0], bl[2 * nfp + 1][1],
                        tBl + nfp * (16 * 64) + boff);
#pragma unroll
            for (int mf = 0; mf < 4; mf++)
#pragma unroll
                for (int nf = 0; nf < 4; nf++)
                    mma16816(acc[mf][nf], ah[mf][0], ah[mf][1], ah[mf][2], ah[mf][3],
                             bl[nf][0], bl[nf][1]);

            uint32_t al[4][4];
#pragma unroll
            for (int mf = 0; mf < 4; mf++)
                ldsm_x4(al[mf][0], al[mf][1], al[mf][2], al[mf][3],
                        tAl + mf * (16 * 64) + aoff);
#pragma unroll
            for (int mf = 0; mf < 4; mf++)
#pragma unroll
                for (int nf = 0; nf < 4; nf++)
                    mma16816(acc[mf][nf], al[mf][0], al[mf][1], al[mf][2], al[mf][3],
                             bh[nf][0], bh[nf][1]);
        }
        if (++bufc >= 3) bufc -= 3;
    }

#pragma unroll
    for (int mf = 0; mf < 4; mf++) {
#pragma unroll
        for (int nf = 0; nf < 4; nf++) {
            int row = m0 + wm * 64 + mf * 16 + g;
            int col = n0 + wn * 32 + nf * 8 + 2 * tq;
            float2 v0 = {acc[mf][nf][0], acc[mf][nf][1]};
            float2 v1 = {acc[mf][nf][2], acc[mf][nf][3]};
            *(float2*)&C[(size_t)row * DMODEL + col] = v0;
            *(float2*)&C[(size_t)(row + 8) * DMODEL + col] = v1;
        }
    }
}

// ---------------------------------------------------------------------------
// RoPE + split to head-major bf16 hi/lo for Q and K
// ---------------------------------------------------------------------------
__global__ void rope_split_kernel(const float* __restrict__ fcos,
                                  const float* __restrict__ fsin) {
    int p = blockIdx.x * blockDim.x + threadIdx.x;
    int i = p & 63;
    int h = (p >> 6) & 15;
    int s = p >> 10;

    float c  = fcos[s * 64 + i];
    float sn = fsin[s * 64 + i];
    size_t src = (size_t)s * DMODEL + h * HD + 2 * i;
    size_t dst = (size_t)h * (S_LEN * HD) + (size_t)s * HD + 2 * i;

    float q0 = g_Q[src], q1 = g_Q[src + 1];
    float r0 = q0 * c - q1 * sn;
    float r1 = q0 * sn + q1 * c;
    __nv_bfloat16 h0 = __float2bfloat16(r0), h1 = __float2bfloat16(r1);
    *(__nv_bfloat162*)&g_Qh[dst] = {h0, h1};
    *(__nv_bfloat162*)&g_Ql[dst] = {__float2bfloat16(r0 - __bfloat162float(h0)),
                                    __float2bfloat16(r1 - __bfloat162float(h1))};

    float k0 = g_K[src], k1 = g_K[src + 1];
    float t0 = k0 * c - k1 * sn;
    float t1 = k0 * sn + k1 * c;
    __nv_bfloat16 u0 = __float2bfloat16(t0), u1 = __float2bfloat16(t1);
    *(__nv_bfloat162*)&g_Kh[dst] = {u0, u1};
    *(__nv_bfloat162*)&g_Kl[dst] = {__float2bfloat16(t0 - __bfloat162float(u0)),
                                    __float2bfloat16(t1 - __bfloat162float(u1))};
}

// V: [s][h*128+d] fp32 -> Vt [h][d][s] bf16 hi/lo
__global__ void v_split_t_kernel() {
    __shared__ float tile[32][33];
    int s0 = blockIdx.x * 32, d0 = blockIdx.y * 32, h = blockIdx.z;
    int tx = threadIdx.x, ty = threadIdx.y;
#pragma unroll
    for (int r = 0; r < 32; r += 8)
        tile[ty + r][tx] = g_V[(size_t)(s0 + ty + r) * DMODEL + h * HD + d0 + tx];
    __syncthreads();
#pragma unroll
    for (int r = 0; r < 32; r += 8) {
        float v = tile[tx][ty + r];
        size_t o = (size_t)(h * HD + d0 + ty + r) * S_LEN + s0 + tx;
        __nv_bfloat16 hh = __float2bfloat16(v);
        g_Vth[o] = hh;
        g_Vtl[o] = __float2bfloat16(v - __bfloat162float(hh));
    }
}

// ---------------------------------------------------------------------------
// FA2-style HMMA flash attention with split-group K/V pipelining (unchanged R9)
// ---------------------------------------------------------------------------
#define QH_W 0
#define QL_W (64 * 68)
#define KH_W (2 * 64 * 68)
#define KL_W (3 * 64 * 68)
#define VH_W (4 * 64 * 68)
#define VL_W (4 * 64 * 68 + 128 * 36)
#define ATTN_SMEM ((4 * 64 * 68 + 2 * 128 * 36) * 4)   // 106496 B

__global__ __launch_bounds__(128) void attn_hmma() {
    extern __shared__ char smem[];
    uint32_t sb = smem_u32(smem);
    const uint32_t* s32 = (const uint32_t*)smem;

    int tid = threadIdx.x;
    int w = tid >> 5, lane = tid & 31;
    int g = lane >> 2, tq = lane & 3;
    int h = blockIdx.y;
    int qb = gridDim.x - 1 - blockIdx.x;

    const __nv_bfloat16* Qhp = g_Qh + (size_t)h * (S_LEN * HD);
    const __nv_bfloat16* Qlp = g_Ql + (size_t)h * (S_LEN * HD);
    const __nv_bfloat16* Khp = g_Kh + (size_t)h * (S_LEN * HD);
    const __nv_bfloat16* Klp = g_Kl + (size_t)h * (S_LEN * HD);
    const __nv_bfloat16* Vhp = g_Vth + (size_t)h * (HD * S_LEN);
    const __nv_bfloat16* Vlp = g_Vtl + (size_t)h * (HD * S_LEN);

#pragma unroll
    for (int i = 0; i < 8; i++) {
        int slot = tid + i * 128;
        int row = slot >> 4, j = slot & 15;
        cp16(sb + (QH_W + row * 68) * 4 + j * 16,
             Qhp + (size_t)(qb * 64 + row) * HD + j * 8);
    }
#pragma unroll
    for (int i = 0; i < 8; i++) {
        int slot = tid + i * 128;
        int row = slot >> 4, j = slot & 15;
        cp16(sb + (QL_W + row * 68) * 4 + j * 16,
             Qlp + (size_t)(qb * 64 + row) * HD + j * 8);
    }
    asm volatile("cp.async.commit_group;" ::: "memory");

#pragma unroll
    for (int i = 0; i < 8; i++) {
        int slot = tid + i * 128;
        int row = slot >> 4, j = slot & 15;
        cp16(sb + (KH_W + row * 68) * 4 + j * 16, Khp + (size_t)row * HD + j * 8);
    }
#pragma unroll
    for (int i = 0; i < 8; i++) {
        int slot = tid + i * 128;
        int row = slot >> 4, j = slot & 15;
        cp16(sb + (KL_W + row * 68) * 4 + j * 16, Klp + (size_t)row * HD + j * 8);
    }
    asm volatile("cp.async.commit_group;" ::: "memory");
#pragma unroll
    for (int i = 0; i < 8; i++) {
        int slot = tid + i * 128;
        int row = slot >> 3, j = slot & 7;
        cp16(sb + (VH_W + row * 36) * 4 + j * 16, Vhp + (size_t)row * S_LEN + j * 8);
    }
#pragma unroll
    for (int i = 0; i < 8; i++) {
        int slot = tid + i * 128;
        int row = slot >> 3, j = slot & 7;
        cp16(sb + (VL_W + row * 36) * 4 + j * 16, Vlp + (size_t)row * S_LEN + j * 8);
    }
    asm volatile("cp.async.commit_group;" ::: "memory");

    float of[16][4];
#pragma unroll
    for (int i = 0; i < 16; i++)
#pragma unroll
        for (int j = 0; j < 4; j++) of[i][j] = 0.f;
    float m0 = -INFINITY, m1 = -INFINITY, l0 = 0.f, l1 = 0.f;

    const float inv_sqrt_hd = 0.08838834764831845f;
    const int qrow0 = qb * 64 + w * 16 + g;
    const int qrow1 = qrow0 + 8;
    const uint32_t arow = (uint32_t)(w * 16 + g) * 68;

    for (int kb = 0; kb <= qb; ++kb) {
        asm volatile("cp.async.wait_group 1;" ::: "memory");
        __syncthreads();

        float sf[8][4];
#pragma unroll
        for (int i = 0; i < 8; i++)
#pragma unroll
            for (int j = 0; j < 4; j++) sf[i][j] = 0.f;

#pragma unroll
        for (int ks = 0; ks < 8; ks++) {
            int kw = ks * 8 + tq;
            uint32_t ah0 = s32[QH_W + arow + kw];
            uint32_t ah1 = s32[QH_W + arow + 8 * 68 + kw];
            uint32_t ah2 = s32[QH_W + arow + kw + 4];
            uint32_t ah3 = s32[QH_W + arow + 8 * 68 + kw + 4];
            uint32_t al0 = s32[QL_W + arow + kw];
            uint32_t al1 = s32[QL_W + arow + 8 * 68 + kw];
            uint32_t al2 = s32[QL_W + arow + kw + 4];
            uint32_t al3 = s32[QL_W + arow + 8 * 68 + kw + 4];
#pragma unroll
            for (int nf = 0; nf < 8; nf++) {
                uint32_t brow = (uint32_t)(nf * 8 + g) * 68;
                uint32_t bh0 = s32[KH_W + brow + kw];
                uint32_t bh1 = s32[KH_W + brow + kw + 4];
                uint32_t bl0 = s32[KL_W + brow + kw];
                uint32_t bl1 = s32[KL_W + brow + kw + 4];
                mma16816(sf[nf], ah0, ah1, ah2, ah3, bh0, bh1);
                mma16816(sf[nf], ah0, ah1, ah2, ah3, bl0, bl1);
                mma16816(sf[nf], al0, al1, al2, al3, bh0, bh1);
            }
        }
        __syncthreads();

        if (kb + 1 <= qb) {
#pragma unroll
            for (int i = 0; i < 8; i++) {
                int slot = tid + i * 128;
                int row = slot >> 4, j = slot & 15;
                cp16(sb + (KH_W + row * 68) * 4 + j * 16,
                     Khp + (size_t)((kb + 1) * 64 + row) * HD + j * 8);
            }
#pragma unroll
            for (int i = 0; i < 8; i++) {
                int slot = tid + i * 128;
                int row = slot >> 4, j = slot & 15;
                cp16(sb + (KL_W + row * 68) * 4 + j * 16,
                     Klp + (size_t)((kb + 1) * 64 + row) * HD + j * 8);
            }
        }
        asm volatile("cp.async.commit_group;" ::: "memory");

        float mloc0 = -INFINITY, mloc1 = -INFINITY;
        bool diag = (kb == qb);
#pragma unroll
        for (int nf = 0; nf < 8; nf++) {
#pragma unroll
            for (int cc = 0; cc < 2; cc++) {
                int kcol = kb * 64 + nf * 8 + 2 * tq + cc;
                float s = sf[nf][cc] * inv_sqrt_hd;
                float t = s * s * 0.0004f;
                s = s * (1.f - t * (0.3333333333f - 0.1333333333f * t));
                if (diag && kcol > qrow0) s = -INFINITY;
                sf[nf][cc] = s;
                mloc0 = fmaxf(mloc0, s);
                float s2 = sf[nf][cc + 2] * inv_sqrt_hd;
                float t2 = s2 * s2 * 0.0004f;
                s2 = s2 * (1.f - t2 * (0.3333333333f - 0.1333333333f * t2));
                if (diag && kcol > qrow1) s2 = -INFINITY;
                sf[nf][cc + 2] = s2;
                mloc1 = fmaxf(mloc1, s2);
            }
        }
        mloc0 = fmaxf(mloc0, __shfl_xor_sync(0xFFFFFFFF, mloc0, 1));
        mloc0 = fmaxf(mloc0, __shfl_xor_sync(0xFFFFFFFF, mloc0, 2));
        mloc1 = fmaxf(mloc1, __shfl_xor_sync(0xFFFFFFFF, mloc1, 1));
        mloc1 = fmaxf(mloc1, __shfl_xor_sync(0xFFFFFFFF, mloc1, 2));

        float mn0 = fmaxf(m0, mloc0), mn1 = fmaxf(m1, mloc1);
        float cf0 = __expf(m0 - mn0), cf1 = __expf(m1 - mn1);
        m0 = mn0; m1 = mn1;

        float ls0 = 0.f, ls1 = 0.f;
#pragma unroll
        for (int nf = 0; nf < 8; nf++) {
#pragma unroll
            for (int cc = 0; cc < 2; cc++) {
                float p = __expf(sf[nf][cc] - mn0);
                sf[nf][cc] = p; ls0 += p;
                float p2 = __expf(sf[nf][cc + 2] - mn1);
                sf[nf][cc + 2] = p2; ls1 += p2;
            }
        }
        ls0 += __shfl_xor_sync(0xFFFFFFFF, ls0, 1);
        ls0 += __shfl_xor_sync(0xFFFFFFFF, ls0, 2);
        ls1 += __shfl_xor_sync(0xFFFFFFFF, ls1, 1);
        ls1 += __shfl_xor_sync(0xFFFFFFFF, ls1, 2);
        l0 = l0 * cf0 + ls0;
        l1 = l1 * cf1 + ls1;

#pragma unroll
        for (int i = 0; i < 16; i++) {
            of[i][0] *= cf0; of[i][1] *= cf0;
            of[i][2] *= cf1; of[i][3] *= cf1;
        }

        asm volatile("cp.async.wait_group 1;" ::: "memory");
        __syncthreads();

#pragma unroll
        for (int ksv = 0; ksv < 4; ksv++) {
            float c00 = sf[2 * ksv][0],     c01 = sf[2 * ksv][1];
            float c02 = sf[2 * ksv][2],     c03 = sf[2 * ksv][3];
            float c10 = sf[2 * ksv + 1][0], c11 = sf[2 * ksv + 1][1];
            float c12 = sf[2 * ksv + 1][2], c13 = sf[2 * ksv + 1][3];
            uint32_t pa0 = pack_bf16(c00, c01);
            uint32_t pa1 = pack_bf16(c02, c03);
            uint32_t pa2 = pack_bf16(c10, c11);
            uint32_t pa3 = pack_bf16(c12, c13);
            uint32_t pl0 = pack_bf16(c00 - bf16lo_f(pa0), c01 - bf16hi_f(pa0));
            uint32_t pl1 = pack_bf16(c02 - bf16lo_f(pa1), c03 - bf16hi_f(pa1));
            uint32_t pl2 = pack_bf16(c10 - bf16lo_f(pa2), c11 - bf16hi_f(pa2));
            uint32_t pl3 = pack_bf16(c12 - bf16lo_f(pa3), c13 - bf16hi_f(pa3));
            int kvw = ksv * 8 + tq;
#pragma unroll
            for (int nf2 = 0; nf2 < 16; nf2++) {
                uint32_t brow = (uint32_t)(nf2 * 8 + g) * 36;
                uint32_t vh0 = s32[VH_W + brow + kvw];
                uint32_t vh1 = s32[VH_W + brow + kvw + 4];
                uint32_t vl0 = s32[VL_W + brow + kvw];
                uint32_t vl1 = s32[VL_W + brow + kvw + 4];
                mma16816(of[nf2], pa0, pa1, pa2, pa3, vh0, vh1);
                mma16816(of[nf2], pa0, pa1, pa2, pa3, vl0, vl1);
                mma16816(of[nf2], pl0, pl1, pl2, pl3, vh0, vh1);
            }
        }
        __syncthreads();

        if (kb + 1 <= qb) {
#pragma unroll
            for (int i = 0; i < 8; i++) {
                int slot = tid + i * 128;
                int row = slot >> 3, j = slot & 7;
                cp16(sb + (VH_W + row * 36) * 4 + j * 16,
                     Vhp + (size_t)row * S_LEN + (kb + 1) * 64 + j * 8);
            }
#pragma unroll
            for (int i = 0; i < 8; i++) {
                int slot = tid + i * 128;
                int row = slot >> 3, j = slot & 7;
                cp16(sb + (VL_W + row * 36) * 4 + j * 16,
                     Vlp + (size_t)row * S_LEN + (kb + 1) * 64 + j * 8);
            }
        }
        asm volatile("cp.async.commit_group;" ::: "memory");
    }

    float il0 = 1.f / l0, il1 = 1.f / l1;
#pragma unroll
    for (int nf2 = 0; nf2 < 16; nf2++) {
        int col = h * HD + nf2 * 8 + 2 * tq;
        float o00 = of[nf2][0] * il0, o01 = of[nf2][1] * il0;
        float o10 = of[nf2][2] * il1, o11 = of[nf2][3] * il1;
        __nv_bfloat16 h00 = __float2bfloat16(o00), h01 = __float2bfloat16(o01);
        __nv_bfloat16 h10 = __float2bfloat16(o10), h11 = __float2bfloat16(o11);
        *(__nv_bfloat162*)&g_ohi[(size_t)qrow0 * DMODEL + col] = {h00, h01};
        *(__nv_bfloat162*)&g_ohi[(size_t)qrow1 * DMODEL + col] = {h10, h11};
        *(__nv_bfloat162*)&g_olo[(size_t)qrow0 * DMODEL + col] =
            {__float2bfloat16(o00 - __bfloat162float(h00)),
             __float2bfloat16(o01 - __bfloat162float(h01))};
        *(__nv_bfloat162*)&g_olo[(size_t)qrow1 * DMODEL + col] =
            {__float2bfloat16(o10 - __bfloat162float(h10)),
             __float2bfloat16(o11 - __bfloat162float(h11))};
    }
}

// ---------------------------------------------------------------------------
// Launch
// ---------------------------------------------------------------------------
extern "C" void kernel_launch(void* const* d_in, const int* in_sizes, int n_in,
                              void* d_out, int out_size) {
    const float* x    = (const float*)d_in[0];
    const float* wq   = (const float*)d_in[1];
    const float* wk   = (const float*)d_in[2];
    const float* wv   = (const float*)d_in[3];
    const float* wo   = (const float*)d_in[4];
    const float* fcos = (const float*)d_in[5];
    const float* fsin = (const float*)d_in[6];
    float* out = (float*)d_out;

    float *Qp, *Kp, *Vp;
    __nv_bfloat16 *xhi, *xlo, *ohi, *olo, *wth, *wtl;
    cudaGetSymbolAddress((void**)&Qp, g_Q);
    cudaGetSymbolAddress((void**)&Kp, g_K);
    cudaGetSymbolAddress((void**)&Vp, g_V);
    cudaGetSymbolAddress((void**)&xhi, g_xhi);
    cudaGetSymbolAddress((void**)&xlo, g_xlo);
    cudaGetSymbolAddress((void**)&ohi, g_ohi);
    cudaGetSymbolAddress((void**)&olo, g_olo);
    cudaGetSymbolAddress((void**)&wth, g_wth);
    cudaGetSymbolAddress((void**)&wtl, g_wtl);

    cudaFuncSetAttribute(gemm_hmma, cudaFuncAttributeMaxDynamicSharedMemorySize, GEMM_SMEM);
    cudaFuncSetAttribute(attn_hmma, cudaFuncAttributeMaxDynamicSharedMemorySize, ATTN_SMEM);

    int nElem = S_LEN * DMODEL;

    split_kernel<<<nElem / (256 * 4), 256>>>(x, xhi, xlo);
    wt_split4_kernel<<<dim3(DMODEL / 32, DMODEL / 32, 4), dim3(32, 8)>>>(
        wq, wk, wv, wo, wth, wtl);

    // Fused Q/K/V GEMMs (z = 0,1,2)
    gemm_hmma<<<dim3(DMODEL / 128, DMODEL / 128, 3), 256, GEMM_SMEM>>>(
        xhi, xlo, wth, wtl, Qp, Kp, Vp, 0);

    int pairs = S_LEN * NH * (HD / 2);
    rope_split_kernel<<<pairs / 256, 256>>>(fcos, fsin);
    v_split_t_kernel<<<dim3(S_LEN / 32, HD / 32, NH), dim3(32, 8)>>>();

    attn_hmma<<<dim3(S_LEN / 64, NH), 128, ATTN_SMEM>>>();

    // Output projection (weight index 3)
    gemm_hmma<<<dim3(DMODEL / 128, DMODEL / 128, 1), 256, GEMM_SMEM>>>(
        ohi, olo, wth, wtl, out, out, out, 3);
}

// round 12
// speedup vs baseline: 6.5255x; 1.0157x over previous
#include <cuda_runtime.h>
#include <cuda_bf16.h>
#include <math.h>
#include <stdint.h>

#define S_LEN 2048
#define DMODEL 2048
#define NH 16
#define HD 128

// ---------------------------------------------------------------------------
// Scratch (__device__ globals; allocation-free rule)
// ---------------------------------------------------------------------------
__device__ float g_Q[S_LEN * DMODEL];
__device__ float g_K[S_LEN * DMODEL];
__device__ float g_V[S_LEN * DMODEL];

__device__ __nv_bfloat16 g_xhi[S_LEN * DMODEL];
__device__ __nv_bfloat16 g_xlo[S_LEN * DMODEL];
__device__ __nv_bfloat16 g_ohi[S_LEN * DMODEL];
__device__ __nv_bfloat16 g_olo[S_LEN * DMODEL];
__device__ __nv_bfloat16 g_wth[4][DMODEL * DMODEL];  // transposed [N][K] hi
__device__ __nv_bfloat16 g_wtl[4][DMODEL * DMODEL];  // transposed [N][K] lo

// Attention operands, head-major
__device__ __nv_bfloat16 g_Qh[NH * S_LEN * HD];   // [h][s][d]
__device__ __nv_bfloat16 g_Ql[NH * S_LEN * HD];
__device__ __nv_bfloat16 g_Kh[NH * S_LEN * HD];
__device__ __nv_bfloat16 g_Kl[NH * S_LEN * HD];
__device__ __nv_bfloat16 g_Vth[NH * HD * S_LEN];  // [h][d][s]
__device__ __nv_bfloat16 g_Vtl[NH * HD * S_LEN];

// ---------------------------------------------------------------------------
// Helpers
// ---------------------------------------------------------------------------
__device__ __forceinline__ void cp16(uint32_t s, const void* g) {
    asm volatile("cp.async.cg.shared.global [%0], [%1], 16;" :: "r"(s), "l"(g) : "memory");
}
__device__ __forceinline__ uint32_t smem_u32(const void* p) {
    uint32_t a;
    asm("{ .reg .u64 t; cvta.to.shared.u64 t, %1; cvt.u32.u64 %0, t; }"
        : "=r"(a) : "l"(p));
    return a;
}
__device__ __forceinline__ void mma16816(float* c, uint32_t a0, uint32_t a1,
                                         uint32_t a2, uint32_t a3,
                                         uint32_t b0, uint32_t b1) {
    asm volatile(
        "mma.sync.aligned.m16n8k16.row.col.f32.bf16.bf16.f32 "
        "{%0,%1,%2,%3}, {%4,%5,%6,%7}, {%8,%9}, {%0,%1,%2,%3};"
        : "+f"(c[0]), "+f"(c[1]), "+f"(c[2]), "+f"(c[3])
        : "r"(a0), "r"(a1), "r"(a2), "r"(a3), "r"(b0), "r"(b1));
}
__device__ __forceinline__ void ldsm_x4(uint32_t& r0, uint32_t& r1,
                                        uint32_t& r2, uint32_t& r3, uint32_t addr) {
    asm volatile("ldmatrix.sync.aligned.m8n8.x4.shared.b16 {%0,%1,%2,%3}, [%4];"
                 : "=r"(r0), "=r"(r1), "=r"(r2), "=r"(r3) : "r"(addr));
}
// packed = {lo16 = lo, hi16 = hi}
__device__ __forceinline__ uint32_t pack_bf16(float lo, float hi) {
    uint32_t r;
    asm("cvt.rn.bf16x2.f32 %0, %1, %2;" : "=r"(r) : "f"(hi), "f"(lo));
    return r;
}
__device__ __forceinline__ float bf16lo_f(uint32_t p) { return __uint_as_float(p << 16); }
__device__ __forceinline__ float bf16hi_f(uint32_t p) { return __uint_as_float(p & 0xFFFF0000u); }

// ---------------------------------------------------------------------------
// Split fp32 -> bf16 hi/lo (elementwise)
// ---------------------------------------------------------------------------
__global__ void split_kernel(const float* __restrict__ src,
                             __nv_bfloat16* __restrict__ hi,
                             __nv_bfloat16* __restrict__ lo) {
    int i = (blockIdx.x * blockDim.x + threadIdx.x) * 4;
    float4 v = *(const float4*)(src + i);
    float vv[4] = {v.x, v.y, v.z, v.w};
#pragma unroll
    for (int j = 0; j < 4; j++) {
        __nv_bfloat16 h = __float2bfloat16(vv[j]);
        hi[i + j] = h;
        lo[i + j] = __float2bfloat16(vv[j] - __bfloat162float(h));
    }
}

// Transpose + split all 4 weights: W [K][N] -> T [N][K] hi/lo. blockIdx.z = which W.
__global__ void wt_split4_kernel(const float* __restrict__ w0,
                                 const float* __restrict__ w1,
                                 const float* __restrict__ w2,
                                 const float* __restrict__ w3,
                                 __nv_bfloat16* __restrict__ Thi,
                                 __nv_bfloat16* __restrict__ Tlo) {
    __shared__ float tile[32][33];
    int z = blockIdx.z;
    const float* W = (z == 0) ? w0 : (z == 1) ? w1 : (z == 2) ? w2 : w3;
    Thi += (size_t)z * DMODEL * DMODEL;
    Tlo += (size_t)z * DMODEL * DMODEL;
    int n0 = blockIdx.x * 32, k0 = blockIdx.y * 32;
    int tx = threadIdx.x, ty = threadIdx.y;
#pragma unroll
    for (int r = 0; r < 32; r += 8)
        tile[ty + r][tx] = W[(size_t)(k0 + ty + r) * DMODEL + n0 + tx];
    __syncthreads();
#pragma unroll
    for (int r = 0; r < 32; r += 8) {
        float v = tile[tx][ty + r];
        size_t o = (size_t)(n0 + ty + r) * DMODEL + k0 + tx;
        __nv_bfloat16 h = __float2bfloat16(v);
        Thi[o] = h;
        Tlo[o] = __float2bfloat16(v - __bfloat162float(h));
    }
}

// ---------------------------------------------------------------------------
// HMMA split-bf16 GEMM (unchanged from R10)
// ---------------------------------------------------------------------------
#define BK2 32
#define NCHUNK2 (DMODEL / BK2)
#define TILE_BYTES (128 * 64)             // 8192
#define BUF_STRIDE_B (4 * TILE_BYTES)     // 32768
#define GEMM_SMEM (3 * BUF_STRIDE_B)      // 98304

__device__ __forceinline__ void load_tile_sw(uint32_t sbase, const __nv_bfloat16* g,
                                             int row0, int k0, int tid) {
#pragma unroll
    for (int i = 0; i < 2; i++) {
        int slot = tid + i * 256;
        int row = slot >> 2;
        int j = slot & 3;
        uint32_t dst = sbase + row * 64 + ((j ^ ((row >> 1) & 3)) << 4);
        cp16(dst, g + (size_t)(row0 + row) * DMODEL + k0 + j * 8);
    }
}

__device__ __forceinline__ void load_chunk(uint32_t buf, const __nv_bfloat16* Ahi,
                                           const __nv_bfloat16* Alo,
                                           const __nv_bfloat16* Bhi,
                                           const __nv_bfloat16* Blo,
                                           int m0, int n0, int k0, int tid) {
    load_tile_sw(buf, Ahi, m0, k0, tid);
    load_tile_sw(buf + TILE_BYTES, Alo, m0, k0, tid);
    load_tile_sw(buf + 2 * TILE_BYTES, Bhi, n0, k0, tid);
    load_tile_sw(buf + 3 * TILE_BYTES, Blo, n0, k0, tid);
}

__global__ __launch_bounds__(256, 2) void gemm_hmma(
        const __nv_bfloat16* __restrict__ Ahi,
        const __nv_bfloat16* __restrict__ Alo,
        const __nv_bfloat16* __restrict__ Wh,
        const __nv_bfloat16* __restrict__ Wl,
        float* __restrict__ C0, float* __restrict__ C1, float* __restrict__ C2,
        int zoff) {
    extern __shared__ char smem[];
    uint32_t sb = smem_u32(smem);

    const size_t WSZ = (size_t)DMODEL * DMODEL;
    int z = blockIdx.z;
    const __nv_bfloat16* Bhi = Wh + (size_t)(z + zoff) * WSZ;
    const __nv_bfloat16* Blo = Wl + (size_t)(z + zoff) * WSZ;
    float* C = (z == 0) ? C0 : (z == 1) ? C1 : C2;

    int tid = threadIdx.x;
    int wid = tid >> 5, lane = tid & 31;
    int wm = wid & 1, wn = wid >> 1;
    int g = lane >> 2, tq = lane & 3;
    int n0 = blockIdx.x * 128, m0 = blockIdx.y * 128;

    int a_rin = lane & 15;
    uint32_t a_j0 = lane >> 4;
    uint32_t a_t  = (a_rin >> 1) & 3;
    uint32_t a_rowb = (uint32_t)(wm * 64 + a_rin) * 64;

    int b_rin = ((lane >> 4) << 3) + (lane & 7);
    uint32_t b_j0 = (lane >> 3) & 1;
    uint32_t b_t  = (b_rin >> 1) & 3;
    uint32_t b_rowb = (uint32_t)(wn * 32 + b_rin) * 64;

    float acc[4][4][4];
#pragma unroll
    for (int i = 0; i < 4; i++)
#pragma unroll
        for (int j = 0; j < 4; j++)
#pragma unroll
            for (int k = 0; k < 4; k++) acc[i][j][k] = 0.f;

    load_chunk(sb, Ahi, Alo, Bhi, Blo, m0, n0, 0, tid);
    asm volatile("cp.async.commit_group;" ::: "memory");
    load_chunk(sb + BUF_STRIDE_B, Ahi, Alo, Bhi, Blo, m0, n0, BK2, tid);
    asm volatile("cp.async.commit_group;" ::: "memory");

    int bufc = 0;
    for (int c = 0; c < NCHUNK2; ++c) {
        if (c + 1 < NCHUNK2) {
            asm volatile("cp.async.wait_group 1;" ::: "memory");
        } else {
            asm volatile("cp.async.wait_group 0;" ::: "memory");
        }
        __syncthreads();

        if (c + 2 < NCHUNK2) {
            int nb = bufc + 2; if (nb >= 3) nb -= 3;
            load_chunk(sb + nb * BUF_STRIDE_B, Ahi, Alo, Bhi, Blo,
                       m0, n0, (c + 2) * BK2, tid);
            asm volatile("cp.async.commit_group;" ::: "memory");
        }

        uint32_t bufb = sb + bufc * BUF_STRIDE_B;
        uint32_t tAh = bufb;
        uint32_t tAl = bufb + TILE_BYTES;
        uint32_t tBh = bufb + 2 * TILE_BYTES;
        uint32_t tBl = bufb + 3 * TILE_BYTES;

#pragma unroll
        for (int ks = 0; ks < 2; ks++) {
            uint32_t aoff = a_rowb + (((a_j0 + 2 * ks) ^ a_t) << 4);
            uint32_t boff = b_rowb + (((b_j0 + 2 * ks) ^ b_t) << 4);

            uint32_t ah[4][4], bh[4][2];
#pragma unroll
            for (int mf = 0; mf < 4; mf++)
                ldsm_x4(ah[mf][0], ah[mf][1], ah[mf][2], ah[mf][3],
                        tAh + mf * (16 * 64) + aoff);
#pragma unroll
            for (int nfp = 0; nfp < 2; nfp++)
                ldsm_x4(bh[2 * nfp][0], bh[2 * nfp][1],
                        bh[2 * nfp + 1][0], bh[2 * nfp + 1][1],
                        tBh + nfp * (16 * 64) + boff);
#pragma unroll
            for (int mf = 0; mf < 4; mf++)
#pragma unroll
                for (int nf = 0; nf < 4; nf++)
                    mma16816(acc[mf][nf], ah[mf][0], ah[mf][1], ah[mf][2], ah[mf][3],
                             bh[nf][0], bh[nf][1]);

            uint32_t bl[4][2];
#pragma unroll
            for (int nfp = 0; nfp < 2; nfp++)
                ldsm_x4(bl[2 * nfp][0], bl[2 * nfp][1],
                        bl[2 * nfp + 1][0], bl[2 * nfp + 1][1],
                        tBl + nfp * (16 * 64) + boff);
#pragma unroll
            for (int mf = 0; mf < 4; mf++)
#pragma unroll
                for (int nf = 0; nf < 4; nf++)
                    mma16816(acc[mf][nf], ah[mf][0], ah[mf][1], ah[mf][2], ah[mf][3],
                             bl[nf][0], bl[nf][1]);

            uint32_t al[4][4];
#pragma unroll
            for (int mf = 0; mf < 4; mf++)
                ldsm_x4(al[mf][0], al[mf][1], al[mf][2], al[mf][3],
                        tAl + mf * (16 * 64) + aoff);
#pragma unroll
            for (int mf = 0; mf < 4; mf++)
#pragma unroll
                for (int nf = 0; nf < 4; nf++)
                    mma16816(acc[mf][nf], al[mf][0], al[mf][1], al[mf][2], al[mf][3],
                             bh[nf][0], bh[nf][1]);
        }
        if (++bufc >= 3) bufc -= 3;
    }

#pragma unroll
    for (int mf = 0; mf < 4; mf++) {
#pragma unroll
        for (int nf = 0; nf < 4; nf++) {
            int row = m0 + wm * 64 + mf * 16 + g;
            int col = n0 + wn * 32 + nf * 8 + 2 * tq;
            float2 v0 = {acc[mf][nf][0], acc[mf][nf][1]};
            float2 v1 = {acc[mf][nf][2], acc[mf][nf][3]};
            *(float2*)&C[(size_t)row * DMODEL + col] = v0;
            *(float2*)&C[(size_t)(row + 8) * DMODEL + col] = v1;
        }
    }
}

// ---------------------------------------------------------------------------
// RoPE + split to head-major bf16 hi/lo for Q and K
// ---------------------------------------------------------------------------
__global__ void rope_split_kernel(const float* __restrict__ fcos,
                                  const float* __restrict__ fsin) {
    int p = blockIdx.x * blockDim.x + threadIdx.x;
    int i = p & 63;
    int h = (p >> 6) & 15;
    int s = p >> 10;

    float c  = fcos[s * 64 + i];
    float sn = fsin[s * 64 + i];
    size_t src = (size_t)s * DMODEL + h * HD + 2 * i;
    size_t dst = (size_t)h * (S_LEN * HD) + (size_t)s * HD + 2 * i;

    float q0 = g_Q[src], q1 = g_Q[src + 1];
    float r0 = q0 * c - q1 * sn;
    float r1 = q0 * sn + q1 * c;
    __nv_bfloat16 h0 = __float2bfloat16(r0), h1 = __float2bfloat16(r1);
    *(__nv_bfloat162*)&g_Qh[dst] = {h0, h1};
    *(__nv_bfloat162*)&g_Ql[dst] = {__float2bfloat16(r0 - __bfloat162float(h0)),
                                    __float2bfloat16(r1 - __bfloat162float(h1))};

    float k0 = g_K[src], k1 = g_K[src + 1];
    float t0 = k0 * c - k1 * sn;
    float t1 = k0 * sn + k1 * c;
    __nv_bfloat16 u0 = __float2bfloat16(t0), u1 = __float2bfloat16(t1);
    *(__nv_bfloat162*)&g_Kh[dst] = {u0, u1};
    *(__nv_bfloat162*)&g_Kl[dst] = {__float2bfloat16(t0 - __bfloat162float(u0)),
                                    __float2bfloat16(t1 - __bfloat162float(u1))};
}

// V: [s][h*128+d] fp32 -> Vt [h][d][s] bf16 hi/lo
__global__ void v_split_t_kernel() {
    __shared__ float tile[32][33];
    int s0 = blockIdx.x * 32, d0 = blockIdx.y * 32, h = blockIdx.z;
    int tx = threadIdx.x, ty = threadIdx.y;
#pragma unroll
    for (int r = 0; r < 32; r += 8)
        tile[ty + r][tx] = g_V[(size_t)(s0 + ty + r) * DMODEL + h * HD + d0 + tx];
    __syncthreads();
#pragma unroll
    for (int r = 0; r < 32; r += 8) {
        float v = tile[tx][ty + r];
        size_t o = (size_t)(h * HD + d0 + ty + r) * S_LEN + s0 + tx;
        __nv_bfloat16 hh = __float2bfloat16(v);
        g_Vth[o] = hh;
        g_Vtl[o] = __float2bfloat16(v - __bfloat162float(hh));
    }
}

// ---------------------------------------------------------------------------
// FA2-style HMMA flash attention; ldmatrix fragment loads (R11).
// BQ=BKV=64, 4 warps, 1 head per CTA. K/V split-group pipelining as R10.
// Q/K rows: 68 words (272 B); V rows: 36 words (144 B). Both conflict-free
// for ldmatrix (4r mod 32 covers all bank groups).
// ---------------------------------------------------------------------------
#define QH_W 0
#define QL_W (64 * 68)
#define KH_W (2 * 64 * 68)
#define KL_W (3 * 64 * 68)
#define VH_W (4 * 64 * 68)
#define VL_W (4 * 64 * 68 + 128 * 36)
#define QH_B (QH_W * 4)
#define QL_B (QL_W * 4)
#define KH_B (KH_W * 4)
#define KL_B (KL_W * 4)
#define VH_B (VH_W * 4)
#define VL_B (VL_W * 4)
#define ATTN_SMEM ((4 * 64 * 68 + 2 * 128 * 36) * 4)   // 106496 B

__global__ __launch_bounds__(128) void attn_hmma() {
    extern __shared__ char smem[];
    uint32_t sb = smem_u32(smem);

    int tid = threadIdx.x;
    int w = tid >> 5, lane = tid & 31;
    int g = lane >> 2, tq = lane & 3;
    int h = blockIdx.y;
    int qb = gridDim.x - 1 - blockIdx.x;

    const __nv_bfloat16* Qhp = g_Qh + (size_t)h * (S_LEN * HD);
    const __nv_bfloat16* Qlp = g_Ql + (size_t)h * (S_LEN * HD);
    const __nv_bfloat16* Khp = g_Kh + (size_t)h * (S_LEN * HD);
    const __nv_bfloat16* Klp = g_Kl + (size_t)h * (S_LEN * HD);
    const __nv_bfloat16* Vhp = g_Vth + (size_t)h * (HD * S_LEN);
    const __nv_bfloat16* Vlp = g_Vtl + (size_t)h * (HD * S_LEN);

    // ldmatrix lane base offsets (bytes within tile)
    uint32_t qa_base = (uint32_t)(w * 16 + (lane & 15)) * 272 + (lane >> 4) * 16;
    uint32_t kb_base = (uint32_t)(((lane >> 4) << 3) + (lane & 7)) * 272
                       + ((lane >> 3) & 1) * 16;
    uint32_t vb_base = (uint32_t)(((lane >> 4) << 3) + (lane & 7)) * 144
                       + ((lane >> 3) & 1) * 16;

#pragma unroll
    for (int i = 0; i < 8; i++) {
        int slot = tid + i * 128;
        int row = slot >> 4, j = slot & 15;
        cp16(sb + QH_B + row * 272 + j * 16,
             Qhp + (size_t)(qb * 64 + row) * HD + j * 8);
    }
#pragma unroll
    for (int i = 0; i < 8; i++) {
        int slot = tid + i * 128;
        int row = slot >> 4, j = slot & 15;
        cp16(sb + QL_B + row * 272 + j * 16,
             Qlp + (size_t)(qb * 64 + row) * HD + j * 8);
    }
    asm volatile("cp.async.commit_group;" ::: "memory");

#pragma unroll
    for (int i = 0; i < 8; i++) {
        int slot = tid + i * 128;
        int row = slot >> 4, j = slot & 15;
        cp16(sb + KH_B + row * 272 + j * 16, Khp + (size_t)row * HD + j * 8);
    }
#pragma unroll
    for (int i = 0; i < 8; i++) {
        int slot = tid + i * 128;
        int row = slot >> 4, j = slot & 15;
        cp16(sb + KL_B + row * 272 + j * 16, Klp + (size_t)row * HD + j * 8);
    }
    asm volatile("cp.async.commit_group;" ::: "memory");
#pragma unroll
    for (int i = 0; i < 8; i++) {
        int slot = tid + i * 128;
        int row = slot >> 3, j = slot & 7;
        cp16(sb + VH_B + row * 144 + j * 16, Vhp + (size_t)row * S_LEN + j * 8);
    }
#pragma unroll
    for (int i = 0; i < 8; i++) {
        int slot = tid + i * 128;
        int row = slot >> 3, j = slot & 7;
        cp16(sb + VL_B + row * 144 + j * 16, Vlp + (size_t)row * S_LEN + j * 8);
    }
    asm volatile("cp.async.commit_group;" ::: "memory");

    float of[16][4];
#pragma unroll
    for (int i = 0; i < 16; i++)
#pragma unroll
        for (int j = 0; j < 4; j++) of[i][j] = 0.f;
    float m0 = -INFINITY, m1 = -INFINITY, l0 = 0.f, l1 = 0.f;

    const float inv_sqrt_hd = 0.08838834764831845f;
    const int qrow0 = qb * 64 + w * 16 + g;
    const int qrow1 = qrow0 + 8;

    for (int kb = 0; kb <= qb; ++kb) {
        asm volatile("cp.async.wait_group 1;" ::: "memory");
        __syncthreads();

        // --- S = Q K^T (3-term split, ldmatrix) ---
        float sf[8][4];
#pragma unroll
        for (int i = 0; i < 8; i++)
#pragma unroll
            for (int j = 0; j < 4; j++) sf[i][j] = 0.f;

#pragma unroll
        for (int ks = 0; ks < 8; ks++) {
            uint32_t koff = ks * 32;
            uint32_t ah[4], al[4], bh[8][2], bl[8][2];
            ldsm_x4(ah[0], ah[1], ah[2], ah[3], sb + QH_B + qa_base + koff);
            ldsm_x4(al[0], al[1], al[2], al[3], sb + QL_B + qa_base + koff);
#pragma unroll
            for (int nfp = 0; nfp < 4; nfp++)
                ldsm_x4(bh[2 * nfp][0], bh[2 * nfp][1],
                        bh[2 * nfp + 1][0], bh[2 * nfp + 1][1],
                        sb + KH_B + nfp * (16 * 272) + kb_base + koff);
#pragma unroll
            for (int nfp = 0; nfp < 4; nfp++)
                ldsm_x4(bl[2 * nfp][0], bl[2 * nfp][1],
                        bl[2 * nfp + 1][0], bl[2 * nfp + 1][1],
                        sb + KL_B + nfp * (16 * 272) + kb_base + koff);
#pragma unroll
            for (int nf = 0; nf < 8; nf++) {
                mma16816(sf[nf], ah[0], ah[1], ah[2], ah[3], bh[nf][0], bh[nf][1]);
                mma16816(sf[nf], ah[0], ah[1], ah[2], ah[3], bl[nf][0], bl[nf][1]);
                mma16816(sf[nf], al[0], al[1], al[2], al[3], bh[nf][0], bh[nf][1]);
            }
        }
        __syncthreads();

        if (kb + 1 <= qb) {
#pragma unroll
            for (int i = 0; i < 8; i++) {
                int slot = tid + i * 128;
                int row = slot >> 4, j = slot & 15;
                cp16(sb + KH_B + row * 272 + j * 16,
                     Khp + (size_t)((kb + 1) * 64 + row) * HD + j * 8);
            }
#pragma unroll
            for (int i = 0; i < 8; i++) {
                int slot = tid + i * 128;
                int row = slot >> 4, j = slot & 15;
                cp16(sb + KL_B + row * 272 + j * 16,
                     Klp + (size_t)((kb + 1) * 64 + row) * HD + j * 8);
            }
        }
        asm volatile("cp.async.commit_group;" ::: "memory");

        // --- softcap + mask + online softmax (registers) ---
        float mloc0 = -INFINITY, mloc1 = -INFINITY;
        bool diag = (kb == qb);
#pragma unroll
        for (int nf = 0; nf < 8; nf++) {
#pragma unroll
            for (int cc = 0; cc < 2; cc++) {
                int kcol = kb * 64 + nf * 8 + 2 * tq + cc;
                float s = sf[nf][cc] * inv_sqrt_hd;
                float t = s * s * 0.0004f;
                s = s * (1.f - t * (0.3333333333f - 0.1333333333f * t));
                if (diag && kcol > qrow0) s = -INFINITY;
                sf[nf][cc] = s;
                mloc0 = fmaxf(mloc0, s);
                float s2 = sf[nf][cc + 2] * inv_sqrt_hd;
                float t2 = s2 * s2 * 0.0004f;
                s2 = s2 * (1.f - t2 * (0.3333333333f - 0.1333333333f * t2));
                if (diag && kcol > qrow1) s2 = -INFINITY;
                sf[nf][cc + 2] = s2;
                mloc1 = fmaxf(mloc1, s2);
            }
        }
        mloc0 = fmaxf(mloc0, __shfl_xor_sync(0xFFFFFFFF, mloc0, 1));
        mloc0 = fmaxf(mloc0, __shfl_xor_sync(0xFFFFFFFF, mloc0, 2));
        mloc1 = fmaxf(mloc1, __shfl_xor_sync(0xFFFFFFFF, mloc1, 1));
        mloc1 = fmaxf(mloc1, __shfl_xor_sync(0xFFFFFFFF, mloc1, 2));

        float mn0 = fmaxf(m0, mloc0), mn1 = fmaxf(m1, mloc1);
        float cf0 = __expf(m0 - mn0), cf1 = __expf(m1 - mn1);
        m0 = mn0; m1 = mn1;

        float ls0 = 0.f, ls1 = 0.f;
#pragma unroll
        for (int nf = 0; nf < 8; nf++) {
#pragma unroll
            for (int cc = 0; cc < 2; cc++) {
                float p = __expf(sf[nf][cc] - mn0);
                sf[nf][cc] = p; ls0 += p;
                float p2 = __expf(sf[nf][cc + 2] - mn1);
                sf[nf][cc + 2] = p2; ls1 += p2;
            }
        }
        ls0 += __shfl_xor_sync(0xFFFFFFFF, ls0, 1);
        ls0 += __shfl_xor_sync(0xFFFFFFFF, ls0, 2);
        ls1 += __shfl_xor_sync(0xFFFFFFFF, ls1, 1);
        ls1 += __shfl_xor_sync(0xFFFFFFFF, ls1, 2);
        l0 = l0 * cf0 + ls0;
        l1 = l1 * cf1 + ls1;

#pragma unroll
        for (int i = 0; i < 16; i++) {
            of[i][0] *= cf0; of[i][1] *= cf0;
            of[i][2] *= cf1; of[i][3] *= cf1;
        }

        asm volatile("cp.async.wait_group 1;" ::: "memory");
        __syncthreads();

        // --- O += P V (3-term split, ldmatrix for V) ---
#pragma unroll
        for (int ksv = 0; ksv < 4; ksv++) {
            float c00 = sf[2 * ksv][0],     c01 = sf[2 * ksv][1];
            float c02 = sf[2 * ksv][2],     c03 = sf[2 * ksv][3];
            float c10 = sf[2 * ksv + 1][0], c11 = sf[2 * ksv + 1][1];
            float c12 = sf[2 * ksv + 1][2], c13 = sf[2 * ksv + 1][3];
            uint32_t pa0 = pack_bf16(c00, c01);
            uint32_t pa1 = pack_bf16(c02, c03);
            uint32_t pa2 = pack_bf16(c10, c11);
            uint32_t pa3 = pack_bf16(c12, c13);
            uint32_t pl0 = pack_bf16(c00 - bf16lo_f(pa0), c01 - bf16hi_f(pa0));
            uint32_t pl1 = pack_bf16(c02 - bf16lo_f(pa1), c03 - bf16hi_f(pa1));
            uint32_t pl2 = pack_bf16(c10 - bf16lo_f(pa2), c11 - bf16hi_f(pa2));
            uint32_t pl3 = pack_bf16(c12 - bf16lo_f(pa3), c13 - bf16hi_f(pa3));
            uint32_t soff = ksv * 32;
#pragma unroll
            for (int nfp2 = 0; nfp2 < 8; nfp2++) {
                uint32_t vh0, vh1, vh2, vh3, vl0, vl1, vl2, vl3;
                ldsm_x4(vh0, vh1, vh2, vh3,
                        sb + VH_B + nfp2 * (16 * 144) + vb_base + soff);
                ldsm_x4(vl0, vl1, vl2, vl3,
                        sb + VL_B + nfp2 * (16 * 144) + vb_base + soff);
                mma16816(of[2 * nfp2], pa0, pa1, pa2, pa3, vh0, vh1);
                mma16816(of[2 * nfp2], pa0, pa1, pa2, pa3, vl0, vl1);
                mma16816(of[2 * nfp2], pl0, pl1, pl2, pl3, vh0, vh1);
                mma16816(of[2 * nfp2 + 1], pa0, pa1, pa2, pa3, vh2, vh3);
                mma16816(of[2 * nfp2 + 1], pa0, pa1, pa2, pa3, vl2, vl3);
                mma16816(of[2 * nfp2 + 1], pl0, pl1, pl2, pl3, vh2, vh3);
            }
        }
        __syncthreads();

        if (kb + 1 <= qb) {
#pragma unroll
            for (int i = 0; i < 8; i++) {
                int slot = tid + i * 128;
                int row = slot >> 3, j = slot & 7;
                cp16(sb + VH_B + row * 144 + j * 16,
                     Vhp + (size_t)row * S_LEN + (kb + 1) * 64 + j * 8);
            }
#pragma unroll
            for (int i = 0; i < 8; i++) {
                int slot = tid + i * 128;
                int row = slot >> 3, j = slot & 7;
                cp16(sb + VL_B + row * 144 + j * 16,
                     Vlp + (size_t)row * S_LEN + (kb + 1) * 64 + j * 8);
            }
        }
        asm volatile("cp.async.commit_group;" ::: "memory");
    }

    float il0 = 1.f / l0, il1 = 1.f / l1;
#pragma unroll
    for (int nf2 = 0; nf2 < 16; nf2++) {
        int col = h * HD + nf2 * 8 + 2 * tq;
        float o00 = of[nf2][0] * il0, o01 = of[nf2][1] * il0;
        float o10 = of[nf2][2] * il1, o11 = of[nf2][3] * il1;
        __nv_bfloat16 h00 = __float2bfloat16(o00), h01 = __float2bfloat16(o01);
        __nv_bfloat16 h10 = __float2bfloat16(o10), h11 = __float2bfloat16(o11);
        *(__nv_bfloat162*)&g_ohi[(size_t)qrow0 * DMODEL + col] = {h00, h01};
        *(__nv_bfloat162*)&g_ohi[(size_t)qrow1 * DMODEL + col] = {h10, h11};
        *(__nv_bfloat162*)&g_olo[(size_t)qrow0 * DMODEL + col] =
            {__float2bfloat16(o00 - __bfloat162float(h00)),
             __float2bfloat16(o01 - __bfloat162float(h01))};
        *(__nv_bfloat162*)&g_olo[(size_t)qrow1 * DMODEL + col] =
            {__float2bfloat16(o10 - __bfloat162float(h10)),
             __float2bfloat16(o11 - __bfloat162float(h11))};
    }
}

// ---------------------------------------------------------------------------
// Launch
// ---------------------------------------------------------------------------
extern "C" void kernel_launch(void* const* d_in, const int* in_sizes, int n_in,
                              void* d_out, int out_size) {
    const float* x    = (const float*)d_in[0];
    const float* wq   = (const float*)d_in[1];
    const float* wk   = (const float*)d_in[2];
    const float* wv   = (const float*)d_in[3];
    const float* wo   = (const float*)d_in[4];
    const float* fcos = (const float*)d_in[5];
    const float* fsin = (const float*)d_in[6];
    float* out = (float*)d_out;

    float *Qp, *Kp, *Vp;
    __nv_bfloat16 *xhi, *xlo, *ohi, *olo, *wth, *wtl;
    cudaGetSymbolAddress((void**)&Qp, g_Q);
    cudaGetSymbolAddress((void**)&Kp, g_K);
    cudaGetSymbolAddress((void**)&Vp, g_V);
    cudaGetSymbolAddress((void**)&xhi, g_xhi);
    cudaGetSymbolAddress((void**)&xlo, g_xlo);
    cudaGetSymbolAddress((void**)&ohi, g_ohi);
    cudaGetSymbolAddress((void**)&olo, g_olo);
    cudaGetSymbolAddress((void**)&wth, g_wth);
    cudaGetSymbolAddress((void**)&wtl, g_wtl);

    cudaFuncSetAttribute(gemm_hmma, cudaFuncAttributeMaxDynamicSharedMemorySize, GEMM_SMEM);
    cudaFuncSetAttribute(attn_hmma, cudaFuncAttributeMaxDynamicSharedMemorySize, ATTN_SMEM);

    int nElem = S_LEN * DMODEL;

    split_kernel<<<nElem / (256 * 4), 256>>>(x, xhi, xlo);
    wt_split4_kernel<<<dim3(DMODEL / 32, DMODEL / 32, 4), dim3(32, 8)>>>(
        wq, wk, wv, wo, wth, wtl);

    gemm_hmma<<<dim3(DMODEL / 128, DMODEL / 128, 3), 256, GEMM_SMEM>>>(
        xhi, xlo, wth, wtl, Qp, Kp, Vp, 0);

    int pairs = S_LEN * NH * (HD / 2);
    rope_split_kernel<<<pairs / 256, 256>>>(fcos, fsin);
    v_split_t_kernel<<<dim3(S_LEN / 32, HD / 32, NH), dim3(32, 8)>>>();

    attn_hmma<<<dim3(S_LEN / 64, NH), 128, ATTN_SMEM>>>();

    gemm_hmma<<<dim3(DMODEL / 128, DMODEL / 128, 1), 256, GEMM_SMEM>>>(
        ohi, olo, wth, wtl, out, out, out, 3);
}

// round 13
// speedup vs baseline: 6.5896x; 1.0098x over previous
#include <cuda_runtime.h>
#include <cuda_bf16.h>
#include <math.h>
#include <stdint.h>

#define S_LEN 2048
#define DMODEL 2048
#define NH 16
#define HD 128

// ---------------------------------------------------------------------------
// Scratch (__device__ globals; allocation-free rule)
// ---------------------------------------------------------------------------
__device__ float g_Q[S_LEN * DMODEL];
__device__ float g_K[S_LEN * DMODEL];
__device__ float g_V[S_LEN * DMODEL];

__device__ __nv_bfloat16 g_xhi[S_LEN * DMODEL];
__device__ __nv_bfloat16 g_xlo[S_LEN * DMODEL];
__device__ __nv_bfloat16 g_ohi[S_LEN * DMODEL];
__device__ __nv_bfloat16 g_olo[S_LEN * DMODEL];
__device__ __nv_bfloat16 g_wth[4][DMODEL * DMODEL];  // transposed [N][K] hi
__device__ __nv_bfloat16 g_wtl[4][DMODEL * DMODEL];  // transposed [N][K] lo

// Attention operands, head-major
__device__ __nv_bfloat16 g_Qh[NH * S_LEN * HD];   // [h][s][d]
__device__ __nv_bfloat16 g_Ql[NH * S_LEN * HD];
__device__ __nv_bfloat16 g_Kh[NH * S_LEN * HD];
__device__ __nv_bfloat16 g_Kl[NH * S_LEN * HD];
__device__ __nv_bfloat16 g_Vth[NH * HD * S_LEN];  // [h][d][s]
__device__ __nv_bfloat16 g_Vtl[NH * HD * S_LEN];

// ---------------------------------------------------------------------------
// Helpers
// ---------------------------------------------------------------------------
__device__ __forceinline__ void cp16(uint32_t s, const void* g) {
    asm volatile("cp.async.cg.shared.global [%0], [%1], 16;" :: "r"(s), "l"(g) : "memory");
}
__device__ __forceinline__ uint32_t smem_u32(const void* p) {
    uint32_t a;
    asm("{ .reg .u64 t; cvta.to.shared.u64 t, %1; cvt.u32.u64 %0, t; }"
        : "=r"(a) : "l"(p));
    return a;
}
__device__ __forceinline__ void mma16816(float* c, uint32_t a0, uint32_t a1,
                                         uint32_t a2, uint32_t a3,
                                         uint32_t b0, uint32_t b1) {
    asm volatile(
        "mma.sync.aligned.m16n8k16.row.col.f32.bf16.bf16.f32 "
        "{%0,%1,%2,%3}, {%4,%5,%6,%7}, {%8,%9}, {%0,%1,%2,%3};"
        : "+f"(c[0]), "+f"(c[1]), "+f"(c[2]), "+f"(c[3])
        : "r"(a0), "r"(a1), "r"(a2), "r"(a3), "r"(b0), "r"(b1));
}
__device__ __forceinline__ void ldsm_x4(uint32_t& r0, uint32_t& r1,
                                        uint32_t& r2, uint32_t& r3, uint32_t addr) {
    asm volatile("ldmatrix.sync.aligned.m8n8.x4.shared.b16 {%0,%1,%2,%3}, [%4];"
                 : "=r"(r0), "=r"(r1), "=r"(r2), "=r"(r3) : "r"(addr));
}
// packed = {lo16 = lo, hi16 = hi}
__device__ __forceinline__ uint32_t pack_bf16(float lo, float hi) {
    uint32_t r;
    asm("cvt.rn.bf16x2.f32 %0, %1, %2;" : "=r"(r) : "f"(hi), "f"(lo));
    return r;
}
__device__ __forceinline__ float bf16lo_f(uint32_t p) { return __uint_as_float(p << 16); }
__device__ __forceinline__ float bf16hi_f(uint32_t p) { return __uint_as_float(p & 0xFFFF0000u); }

// ---------------------------------------------------------------------------
// Split fp32 -> bf16 hi/lo (elementwise)
// ---------------------------------------------------------------------------
__global__ void split_kernel(const float* __restrict__ src,
                             __nv_bfloat16* __restrict__ hi,
                             __nv_bfloat16* __restrict__ lo) {
    int i = (blockIdx.x * blockDim.x + threadIdx.x) * 4;
    float4 v = *(const float4*)(src + i);
    float vv[4] = {v.x, v.y, v.z, v.w};
#pragma unroll
    for (int j = 0; j < 4; j++) {
        __nv_bfloat16 h = __float2bfloat16(vv[j]);
        hi[i + j] = h;
        lo[i + j] = __float2bfloat16(vv[j] - __bfloat162float(h));
    }
}

// Transpose + split all 4 weights: W [K][N] -> T [N][K] hi/lo. blockIdx.z = which W.
__global__ void wt_split4_kernel(const float* __restrict__ w0,
                                 const float* __restrict__ w1,
                                 const float* __restrict__ w2,
                                 const float* __restrict__ w3,
                                 __nv_bfloat16* __restrict__ Thi,
                                 __nv_bfloat16* __restrict__ Tlo) {
    __shared__ float tile[32][33];
    int z = blockIdx.z;
    const float* W = (z == 0) ? w0 : (z == 1) ? w1 : (z == 2) ? w2 : w3;
    Thi += (size_t)z * DMODEL * DMODEL;
    Tlo += (size_t)z * DMODEL * DMODEL;
    int n0 = blockIdx.x * 32, k0 = blockIdx.y * 32;
    int tx = threadIdx.x, ty = threadIdx.y;
#pragma unroll
    for (int r = 0; r < 32; r += 8)
        tile[ty + r][tx] = W[(size_t)(k0 + ty + r) * DMODEL + n0 + tx];
    __syncthreads();
#pragma unroll
    for (int r = 0; r < 32; r += 8) {
        float v = tile[tx][ty + r];
        size_t o = (size_t)(n0 + ty + r) * DMODEL + k0 + tx;
        __nv_bfloat16 h = __float2bfloat16(v);
        Thi[o] = h;
        Tlo[o] = __float2bfloat16(v - __bfloat162float(h));
    }
}

// ---------------------------------------------------------------------------
// HMMA split-bf16 GEMM (unchanged from R10)
// ---------------------------------------------------------------------------
#define BK2 32
#define NCHUNK2 (DMODEL / BK2)
#define TILE_BYTES (128 * 64)             // 8192
#define BUF_STRIDE_B (4 * TILE_BYTES)     // 32768
#define GEMM_SMEM (3 * BUF_STRIDE_B)      // 98304

__device__ __forceinline__ void load_tile_sw(uint32_t sbase, const __nv_bfloat16* g,
                                             int row0, int k0, int tid) {
#pragma unroll
    for (int i = 0; i < 2; i++) {
        int slot = tid + i * 256;
        int row = slot >> 2;
        int j = slot & 3;
        uint32_t dst = sbase + row * 64 + ((j ^ ((row >> 1) & 3)) << 4);
        cp16(dst, g + (size_t)(row0 + row) * DMODEL + k0 + j * 8);
    }
}

__device__ __forceinline__ void load_chunk(uint32_t buf, const __nv_bfloat16* Ahi,
                                           const __nv_bfloat16* Alo,
                                           const __nv_bfloat16* Bhi,
                                           const __nv_bfloat16* Blo,
                                           int m0, int n0, int k0, int tid) {
    load_tile_sw(buf, Ahi, m0, k0, tid);
    load_tile_sw(buf + TILE_BYTES, Alo, m0, k0, tid);
    load_tile_sw(buf + 2 * TILE_BYTES, Bhi, n0, k0, tid);
    load_tile_sw(buf + 3 * TILE_BYTES, Blo, n0, k0, tid);
}

__global__ __launch_bounds__(256, 2) void gemm_hmma(
        const __nv_bfloat16* __restrict__ Ahi,
        const __nv_bfloat16* __restrict__ Alo,
        const __nv_bfloat16* __restrict__ Wh,
        const __nv_bfloat16* __restrict__ Wl,
        float* __restrict__ C0, float* __restrict__ C1, float* __restrict__ C2,
        int zoff) {
    extern __shared__ char smem[];
    uint32_t sb = smem_u32(smem);

    const size_t WSZ = (size_t)DMODEL * DMODEL;
    int z = blockIdx.z;
    const __nv_bfloat16* Bhi = Wh + (size_t)(z + zoff) * WSZ;
    const __nv_bfloat16* Blo = Wl + (size_t)(z + zoff) * WSZ;
    float* C = (z == 0) ? C0 : (z == 1) ? C1 : C2;

    int tid = threadIdx.x;
    int wid = tid >> 5, lane = tid & 31;
    int wm = wid & 1, wn = wid >> 1;
    int g = lane >> 2, tq = lane & 3;
    int n0 = blockIdx.x * 128, m0 = blockIdx.y * 128;

    int a_rin = lane & 15;
    uint32_t a_j0 = lane >> 4;
    uint32_t a_t  = (a_rin >> 1) & 3;
    uint32_t a_rowb = (uint32_t)(wm * 64 + a_rin) * 64;

    int b_rin = ((lane >> 4) << 3) + (lane & 7);
    uint32_t b_j0 = (lane >> 3) & 1;
    uint32_t b_t  = (b_rin >> 1) & 3;
    uint32_t b_rowb = (uint32_t)(wn * 32 + b_rin) * 64;

    float acc[4][4][4];
#pragma unroll
    for (int i = 0; i < 4; i++)
#pragma unroll
        for (int j = 0; j < 4; j++)
#pragma unroll
            for (int k = 0; k < 4; k++) acc[i][j][k] = 0.f;

    load_chunk(sb, Ahi, Alo, Bhi, Blo, m0, n0, 0, tid);
    asm volatile("cp.async.commit_group;" ::: "memory");
    load_chunk(sb + BUF_STRIDE_B, Ahi, Alo, Bhi, Blo, m0, n0, BK2, tid);
    asm volatile("cp.async.commit_group;" ::: "memory");

    int bufc = 0;
    for (int c = 0; c < NCHUNK2; ++c) {
        if (c + 1 < NCHUNK2) {
            asm volatile("cp.async.wait_group 1;" ::: "memory");
        } else {
            asm volatile("cp.async.wait_group 0;" ::: "memory");
        }
        __syncthreads();

        if (c + 2 < NCHUNK2) {
            int nb = bufc + 2; if (nb >= 3) nb -= 3;
            load_chunk(sb + nb * BUF_STRIDE_B, Ahi, Alo, Bhi, Blo,
                       m0, n0, (c + 2) * BK2, tid);
            asm volatile("cp.async.commit_group;" ::: "memory");
        }

        uint32_t bufb = sb + bufc * BUF_STRIDE_B;
        uint32_t tAh = bufb;
        uint32_t tAl = bufb + TILE_BYTES;
        uint32_t tBh = bufb + 2 * TILE_BYTES;
        uint32_t tBl = bufb + 3 * TILE_BYTES;

#pragma unroll
        for (int ks = 0; ks < 2; ks++) {
            uint32_t aoff = a_rowb + (((a_j0 + 2 * ks) ^ a_t) << 4);
            uint32_t boff = b_rowb + (((b_j0 + 2 * ks) ^ b_t) << 4);

            uint32_t ah[4][4], bh[4][2];
#pragma unroll
            for (int mf = 0; mf < 4; mf++)
                ldsm_x4(ah[mf][0], ah[mf][1], ah[mf][2], ah[mf][3],
                        tAh + mf * (16 * 64) + aoff);
#pragma unroll
            for (int nfp = 0; nfp < 2; nfp++)
                ldsm_x4(bh[2 * nfp][0], bh[2 * nfp][1],
                        bh[2 * nfp + 1][0], bh[2 * nfp + 1][1],
                        tBh + nfp * (16 * 64) + boff);
#pragma unroll
            for (int mf = 0; mf < 4; mf++)
#pragma unroll
                for (int nf = 0; nf < 4; nf++)
                    mma16816(acc[mf][nf], ah[mf][0], ah[mf][1], ah[mf][2], ah[mf][3],
                             bh[nf][0], bh[nf][1]);

            uint32_t bl[4][2];
#pragma unroll
            for (int nfp = 0; nfp < 2; nfp++)
                ldsm_x4(bl[2 * nfp][0], bl[2 * nfp][1],
                        bl[2 * nfp + 1][0], bl[2 * nfp + 1][1],
                        tBl + nfp * (16 * 64) + boff);
#pragma unroll
            for (int mf = 0; mf < 4; mf++)
#pragma unroll
                for (int nf = 0; nf < 4; nf++)
                    mma16816(acc[mf][nf], ah[mf][0], ah[mf][1], ah[mf][2], ah[mf][3],
                             bl[nf][0], bl[nf][1]);

            uint32_t al[4][4];
#pragma unroll
            for (int mf = 0; mf < 4; mf++)
                ldsm_x4(al[mf][0], al[mf][1], al[mf][2], al[mf][3],
                        tAl + mf * (16 * 64) + aoff);
#pragma unroll
            for (int mf = 0; mf < 4; mf++)
#pragma unroll
                for (int nf = 0; nf < 4; nf++)
                    mma16816(acc[mf][nf], al[mf][0], al[mf][1], al[mf][2], al[mf][3],
                             bh[nf][0], bh[nf][1]);
        }
        if (++bufc >= 3) bufc -= 3;
    }

#pragma unroll
    for (int mf = 0; mf < 4; mf++) {
#pragma unroll
        for (int nf = 0; nf < 4; nf++) {
            int row = m0 + wm * 64 + mf * 16 + g;
            int col = n0 + wn * 32 + nf * 8 + 2 * tq;
            float2 v0 = {acc[mf][nf][0], acc[mf][nf][1]};
            float2 v1 = {acc[mf][nf][2], acc[mf][nf][3]};
            *(float2*)&C[(size_t)row * DMODEL + col] = v0;
            *(float2*)&C[(size_t)(row + 8) * DMODEL + col] = v1;
        }
    }
}

// ---------------------------------------------------------------------------
// RoPE + split to head-major bf16 hi/lo for Q and K
// ---------------------------------------------------------------------------
__global__ void rope_split_kernel(const float* __restrict__ fcos,
                                  const float* __restrict__ fsin) {
    int p = blockIdx.x * blockDim.x + threadIdx.x;
    int i = p & 63;
    int h = (p >> 6) & 15;
    int s = p >> 10;

    float c  = fcos[s * 64 + i];
    float sn = fsin[s * 64 + i];
    size_t src = (size_t)s * DMODEL + h * HD + 2 * i;
    size_t dst = (size_t)h * (S_LEN * HD) + (size_t)s * HD + 2 * i;

    float q0 = g_Q[src], q1 = g_Q[src + 1];
    float r0 = q0 * c - q1 * sn;
    float r1 = q0 * sn + q1 * c;
    __nv_bfloat16 h0 = __float2bfloat16(r0), h1 = __float2bfloat16(r1);
    *(__nv_bfloat162*)&g_Qh[dst] = {h0, h1};
    *(__nv_bfloat162*)&g_Ql[dst] = {__float2bfloat16(r0 - __bfloat162float(h0)),
                                    __float2bfloat16(r1 - __bfloat162float(h1))};

    float k0 = g_K[src], k1 = g_K[src + 1];
    float t0 = k0 * c - k1 * sn;
    float t1 = k0 * sn + k1 * c;
    __nv_bfloat16 u0 = __float2bfloat16(t0), u1 = __float2bfloat16(t1);
    *(__nv_bfloat162*)&g_Kh[dst] = {u0, u1};
    *(__nv_bfloat162*)&g_Kl[dst] = {__float2bfloat16(t0 - __bfloat162float(u0)),
                                    __float2bfloat16(t1 - __bfloat162float(u1))};
}

// V: [s][h*128+d] fp32 -> Vt [h][d][s] bf16 hi/lo
__global__ void v_split_t_kernel() {
    __shared__ float tile[32][33];
    int s0 = blockIdx.x * 32, d0 = blockIdx.y * 32, h = blockIdx.z;
    int tx = threadIdx.x, ty = threadIdx.y;
#pragma unroll
    for (int r = 0; r < 32; r += 8)
        tile[ty + r][tx] = g_V[(size_t)(s0 + ty + r) * DMODEL + h * HD + d0 + tx];
    __syncthreads();
#pragma unroll
    for (int r = 0; r < 32; r += 8) {
        float v = tile[tx][ty + r];
        size_t o = (size_t)(h * HD + d0 + ty + r) * S_LEN + s0 + tx;
        __nv_bfloat16 hh = __float2bfloat16(v);
        g_Vth[o] = hh;
        g_Vtl[o] = __float2bfloat16(v - __bfloat162float(hh));
    }
}

// ---------------------------------------------------------------------------
// FA2-style HMMA flash attention; ldmatrix loads; R13: term-major MMA
// ordering (same-accumulator dependency distance 8 in S, 4 in PV).
// Per-accumulator accumulation order unchanged -> bit-identical results.
// ---------------------------------------------------------------------------
#define QH_W 0
#define QL_W (64 * 68)
#define KH_W (2 * 64 * 68)
#define KL_W (3 * 64 * 68)
#define VH_W (4 * 64 * 68)
#define VL_W (4 * 64 * 68 + 128 * 36)
#define QH_B (QH_W * 4)
#define QL_B (QL_W * 4)
#define KH_B (KH_W * 4)
#define KL_B (KL_W * 4)
#define VH_B (VH_W * 4)
#define VL_B (VL_W * 4)
#define ATTN_SMEM ((4 * 64 * 68 + 2 * 128 * 36) * 4)   // 106496 B

__global__ __launch_bounds__(128) void attn_hmma() {
    extern __shared__ char smem[];
    uint32_t sb = smem_u32(smem);

    int tid = threadIdx.x;
    int w = tid >> 5, lane = tid & 31;
    int g = lane >> 2, tq = lane & 3;
    int h = blockIdx.y;
    int qb = gridDim.x - 1 - blockIdx.x;

    const __nv_bfloat16* Qhp = g_Qh + (size_t)h * (S_LEN * HD);
    const __nv_bfloat16* Qlp = g_Ql + (size_t)h * (S_LEN * HD);
    const __nv_bfloat16* Khp = g_Kh + (size_t)h * (S_LEN * HD);
    const __nv_bfloat16* Klp = g_Kl + (size_t)h * (S_LEN * HD);
    const __nv_bfloat16* Vhp = g_Vth + (size_t)h * (HD * S_LEN);
    const __nv_bfloat16* Vlp = g_Vtl + (size_t)h * (HD * S_LEN);

    uint32_t qa_base = (uint32_t)(w * 16 + (lane & 15)) * 272 + (lane >> 4) * 16;
    uint32_t kb_base = (uint32_t)(((lane >> 4) << 3) + (lane & 7)) * 272
                       + ((lane >> 3) & 1) * 16;
    uint32_t vb_base = (uint32_t)(((lane >> 4) << 3) + (lane & 7)) * 144
                       + ((lane >> 3) & 1) * 16;

#pragma unroll
    for (int i = 0; i < 8; i++) {
        int slot = tid + i * 128;
        int row = slot >> 4, j = slot & 15;
        cp16(sb + QH_B + row * 272 + j * 16,
             Qhp + (size_t)(qb * 64 + row) * HD + j * 8);
    }
#pragma unroll
    for (int i = 0; i < 8; i++) {
        int slot = tid + i * 128;
        int row = slot >> 4, j = slot & 15;
        cp16(sb + QL_B + row * 272 + j * 16,
             Qlp + (size_t)(qb * 64 + row) * HD + j * 8);
    }
    asm volatile("cp.async.commit_group;" ::: "memory");

#pragma unroll
    for (int i = 0; i < 8; i++) {
        int slot = tid + i * 128;
        int row = slot >> 4, j = slot & 15;
        cp16(sb + KH_B + row * 272 + j * 16, Khp + (size_t)row * HD + j * 8);
    }
#pragma unroll
    for (int i = 0; i < 8; i++) {
        int slot = tid + i * 128;
        int row = slot >> 4, j = slot & 15;
        cp16(sb + KL_B + row * 272 + j * 16, Klp + (size_t)row * HD + j * 8);
    }
    asm volatile("cp.async.commit_group;" ::: "memory");
#pragma unroll
    for (int i = 0; i < 8; i++) {
        int slot = tid + i * 128;
        int row = slot >> 3, j = slot & 7;
        cp16(sb + VH_B + row * 144 + j * 16, Vhp + (size_t)row * S_LEN + j * 8);
    }
#pragma unroll
    for (int i = 0; i < 8; i++) {
        int slot = tid + i * 128;
        int row = slot >> 3, j = slot & 7;
        cp16(sb + VL_B + row * 144 + j * 16, Vlp + (size_t)row * S_LEN + j * 8);
    }
    asm volatile("cp.async.commit_group;" ::: "memory");

    float of[16][4];
#pragma unroll
    for (int i = 0; i < 16; i++)
#pragma unroll
        for (int j = 0; j < 4; j++) of[i][j] = 0.f;
    float m0 = -INFINITY, m1 = -INFINITY, l0 = 0.f, l1 = 0.f;

    const float inv_sqrt_hd = 0.08838834764831845f;
    const int qrow0 = qb * 64 + w * 16 + g;
    const int qrow1 = qrow0 + 8;

    for (int kb = 0; kb <= qb; ++kb) {
        asm volatile("cp.async.wait_group 1;" ::: "memory");
        __syncthreads();

        // --- S = Q K^T: term-major passes (same-acc distance = 8) ---
        float sf[8][4];
#pragma unroll
        for (int i = 0; i < 8; i++)
#pragma unroll
            for (int j = 0; j < 4; j++) sf[i][j] = 0.f;

#pragma unroll
        for (int ks = 0; ks < 8; ks++) {
            uint32_t koff = ks * 32;
            uint32_t ah[4], al[4], bh[8][2], bl[8][2];
            ldsm_x4(ah[0], ah[1], ah[2], ah[3], sb + QH_B + qa_base + koff);
            ldsm_x4(al[0], al[1], al[2], al[3], sb + QL_B + qa_base + koff);
#pragma unroll
            for (int nfp = 0; nfp < 4; nfp++)
                ldsm_x4(bh[2 * nfp][0], bh[2 * nfp][1],
                        bh[2 * nfp + 1][0], bh[2 * nfp + 1][1],
                        sb + KH_B + nfp * (16 * 272) + kb_base + koff);
#pragma unroll
            for (int nfp = 0; nfp < 4; nfp++)
                ldsm_x4(bl[2 * nfp][0], bl[2 * nfp][1],
                        bl[2 * nfp + 1][0], bl[2 * nfp + 1][1],
                        sb + KL_B + nfp * (16 * 272) + kb_base + koff);
            // pass 1: Qhi * Khi
#pragma unroll
            for (int nf = 0; nf < 8; nf++)
                mma16816(sf[nf], ah[0], ah[1], ah[2], ah[3], bh[nf][0], bh[nf][1]);
            // pass 2: Qhi * Klo
#pragma unroll
            for (int nf = 0; nf < 8; nf++)
                mma16816(sf[nf], ah[0], ah[1], ah[2], ah[3], bl[nf][0], bl[nf][1]);
            // pass 3: Qlo * Khi
#pragma unroll
            for (int nf = 0; nf < 8; nf++)
                mma16816(sf[nf], al[0], al[1], al[2], al[3], bh[nf][0], bh[nf][1]);
        }
        __syncthreads();

        if (kb + 1 <= qb) {
#pragma unroll
            for (int i = 0; i < 8; i++) {
                int slot = tid + i * 128;
                int row = slot >> 4, j = slot & 15;
                cp16(sb + KH_B + row * 272 + j * 16,
                     Khp + (size_t)((kb + 1) * 64 + row) * HD + j * 8);
            }
#pragma unroll
            for (int i = 0; i < 8; i++) {
                int slot = tid + i * 128;
                int row = slot >> 4, j = slot & 15;
                cp16(sb + KL_B + row * 272 + j * 16,
                     Klp + (size_t)((kb + 1) * 64 + row) * HD + j * 8);
            }
        }
        asm volatile("cp.async.commit_group;" ::: "memory");

        // --- softcap + mask + online softmax (registers) ---
        float mloc0 = -INFINITY, mloc1 = -INFINITY;
        bool diag = (kb == qb);
#pragma unroll
        for (int nf = 0; nf < 8; nf++) {
#pragma unroll
            for (int cc = 0; cc < 2; cc++) {
                int kcol = kb * 64 + nf * 8 + 2 * tq + cc;
                float s = sf[nf][cc] * inv_sqrt_hd;
                float t = s * s * 0.0004f;
                s = s * (1.f - t * (0.3333333333f - 0.1333333333f * t));
                if (diag && kcol > qrow0) s = -INFINITY;
                sf[nf][cc] = s;
                mloc0 = fmaxf(mloc0, s);
                float s2 = sf[nf][cc + 2] * inv_sqrt_hd;
                float t2 = s2 * s2 * 0.0004f;
                s2 = s2 * (1.f - t2 * (0.3333333333f - 0.1333333333f * t2));
                if (diag && kcol > qrow1) s2 = -INFINITY;
                sf[nf][cc + 2] = s2;
                mloc1 = fmaxf(mloc1, s2);
            }
        }
        mloc0 = fmaxf(mloc0, __shfl_xor_sync(0xFFFFFFFF, mloc0, 1));
        mloc0 = fmaxf(mloc0, __shfl_xor_sync(0xFFFFFFFF, mloc0, 2));
        mloc1 = fmaxf(mloc1, __shfl_xor_sync(0xFFFFFFFF, mloc1, 1));
        mloc1 = fmaxf(mloc1, __shfl_xor_sync(0xFFFFFFFF, mloc1, 2));

        float mn0 = fmaxf(m0, mloc0), mn1 = fmaxf(m1, mloc1);
        float cf0 = __expf(m0 - mn0), cf1 = __expf(m1 - mn1);
        m0 = mn0; m1 = mn1;

        float ls0 = 0.f, ls1 = 0.f;
#pragma unroll
        for (int nf = 0; nf < 8; nf++) {
#pragma unroll
            for (int cc = 0; cc < 2; cc++) {
                float p = __expf(sf[nf][cc] - mn0);
                sf[nf][cc] = p; ls0 += p;
                float p2 = __expf(sf[nf][cc + 2] - mn1);
                sf[nf][cc + 2] = p2; ls1 += p2;
            }
        }
        ls0 += __shfl_xor_sync(0xFFFFFFFF, ls0, 1);
        ls0 += __shfl_xor_sync(0xFFFFFFFF, ls0, 2);
        ls1 += __shfl_xor_sync(0xFFFFFFFF, ls1, 1);
        ls1 += __shfl_xor_sync(0xFFFFFFFF, ls1, 2);
        l0 = l0 * cf0 + ls0;
        l1 = l1 * cf1 + ls1;

#pragma unroll
        for (int i = 0; i < 16; i++) {
            of[i][0] *= cf0; of[i][1] *= cf0;
            of[i][2] *= cf1; of[i][3] *= cf1;
        }

        asm volatile("cp.async.wait_group 1;" ::: "memory");
        __syncthreads();

        // --- O += P V: pair-of-nfp2, term-major, 4-acc round robin ---
#pragma unroll
        for (int ksv = 0; ksv < 4; ksv++) {
            float c00 = sf[2 * ksv][0],     c01 = sf[2 * ksv][1];
            float c02 = sf[2 * ksv][2],     c03 = sf[2 * ksv][3];
            float c10 = sf[2 * ksv + 1][0], c11 = sf[2 * ksv + 1][1];
            float c12 = sf[2 * ksv + 1][2], c13 = sf[2 * ksv + 1][3];
            uint32_t pa0 = pack_bf16(c00, c01);
            uint32_t pa1 = pack_bf16(c02, c03);
            uint32_t pa2 = pack_bf16(c10, c11);
            uint32_t pa3 = pack_bf16(c12, c13);
            uint32_t pl0 = pack_bf16(c00 - bf16lo_f(pa0), c01 - bf16hi_f(pa0));
            uint32_t pl1 = pack_bf16(c02 - bf16lo_f(pa1), c03 - bf16hi_f(pa1));
            uint32_t pl2 = pack_bf16(c10 - bf16lo_f(pa2), c11 - bf16hi_f(pa2));
            uint32_t pl3 = pack_bf16(c12 - bf16lo_f(pa3), c13 - bf16hi_f(pa3));
            uint32_t soff = ksv * 32;
#pragma unroll
            for (int np = 0; np < 4; np++) {
                int n0i = 2 * np;   // first nfp2 of pair
                uint32_t vhA0, vhA1, vhA2, vhA3, vlA0, vlA1, vlA2, vlA3;
                uint32_t vhB0, vhB1, vhB2, vhB3, vlB0, vlB1, vlB2, vlB3;
                ldsm_x4(vhA0, vhA1, vhA2, vhA3,
                        sb + VH_B + n0i * (16 * 144) + vb_base + soff);
                ldsm_x4(vlA0, vlA1, vlA2, vlA3,
                        sb + VL_B + n0i * (16 * 144) + vb_base + soff);
                ldsm_x4(vhB0, vhB1, vhB2, vhB3,
                        sb + VH_B + (n0i + 1) * (16 * 144) + vb_base + soff);
                ldsm_x4(vlB0, vlB1, vlB2, vlB3,
                        sb + VL_B + (n0i + 1) * (16 * 144) + vb_base + soff);
                float* oA0 = of[2 * n0i];
                float* oA1 = of[2 * n0i + 1];
                float* oB0 = of[2 * n0i + 2];
                float* oB1 = of[2 * n0i + 3];
                // pass 1: Pa * Vhi (acc order preserved per-acc)
                mma16816(oA0, pa0, pa1, pa2, pa3, vhA0, vhA1);
                mma16816(oA1, pa0, pa1, pa2, pa3, vhA2, vhA3);
                mma16816(oB0, pa0, pa1, pa2, pa3, vhB0, vhB1);
                mma16816(oB1, pa0, pa1, pa2, pa3, vhB2, vhB3);
                // pass 2: Pa * Vlo
                mma16816(oA0, pa0, pa1, pa2, pa3, vlA0, vlA1);
                mma16816(oA1, pa0, pa1, pa2, pa3, vlA2, vlA3);
                mma16816(oB0, pa0, pa1, pa2, pa3, vlB0, vlB1);
                mma16816(oB1, pa0, pa1, pa2, pa3, vlB2, vlB3);
                // pass 3: Plo * Vhi
                mma16816(oA0, pl0, pl1, pl2, pl3, vhA0, vhA1);
                mma16816(oA1, pl0, pl1, pl2, pl3, vhA2, vhA3);
                mma16816(oB0, pl0, pl1, pl2, pl3, vhB0, vhB1);
                mma16816(oB1, pl0, pl1, pl2, pl3, vhB2, vhB3);
            }
        }
        __syncthreads();

        if (kb + 1 <= qb) {
#pragma unroll
            for (int i = 0; i < 8; i++) {
                int slot = tid + i * 128;
                int row = slot >> 3, j = slot & 7;
                cp16(sb + VH_B + row * 144 + j * 16,
                     Vhp + (size_t)row * S_LEN + (kb + 1) * 64 + j * 8);
            }
#pragma unroll
            for (int i = 0; i < 8; i++) {
                int slot = tid + i * 128;
                int row = slot >> 3, j = slot & 7;
                cp16(sb + VL_B + row * 144 + j * 16,
                     Vlp + (size_t)row * S_LEN + (kb + 1) * 64 + j * 8);
            }
        }
        asm volatile("cp.async.commit_group;" ::: "memory");
    }

    float il0 = 1.f / l0, il1 = 1.f / l1;
#pragma unroll
    for (int nf2 = 0; nf2 < 16; nf2++) {
        int col = h * HD + nf2 * 8 + 2 * tq;
        float o00 = of[nf2][0] * il0, o01 = of[nf2][1] * il0;
        float o10 = of[nf2][2] * il1, o11 = of[nf2][3] * il1;
        __nv_bfloat16 h00 = __float2bfloat16(o00), h01 = __float2bfloat16(o01);
        __nv_bfloat16 h10 = __float2bfloat16(o10), h11 = __float2bfloat16(o11);
        *(__nv_bfloat162*)&g_ohi[(size_t)qrow0 * DMODEL + col] = {h00, h01};
        *(__nv_bfloat162*)&g_ohi[(size_t)qrow1 * DMODEL + col] = {h10, h11};
        *(__nv_bfloat162*)&g_olo[(size_t)qrow0 * DMODEL + col] =
            {__float2bfloat16(o00 - __bfloat162float(h00)),
             __float2bfloat16(o01 - __bfloat162float(h01))};
        *(__nv_bfloat162*)&g_olo[(size_t)qrow1 * DMODEL + col] =
            {__float2bfloat16(o10 - __bfloat162float(h10)),
             __float2bfloat16(o11 - __bfloat162float(h11))};
    }
}

// ---------------------------------------------------------------------------
// Launch
// ---------------------------------------------------------------------------
extern "C" void kernel_launch(void* const* d_in, const int* in_sizes, int n_in,
                              void* d_out, int out_size) {
    const float* x    = (const float*)d_in[0];
    const float* wq   = (const float*)d_in[1];
    const float* wk   = (const float*)d_in[2];
    const float* wv   = (const float*)d_in[3];
    const float* wo   = (const float*)d_in[4];
    const float* fcos = (const float*)d_in[5];
    const float* fsin = (const float*)d_in[6];
    float* out = (float*)d_out;

    float *Qp, *Kp, *Vp;
    __nv_bfloat16 *xhi, *xlo, *ohi, *olo, *wth, *wtl;
    cudaGetSymbolAddress((void**)&Qp, g_Q);
    cudaGetSymbolAddress((void**)&Kp, g_K);
    cudaGetSymbolAddress((void**)&Vp, g_V);
    cudaGetSymbolAddress((void**)&xhi, g_xhi);
    cudaGetSymbolAddress((void**)&xlo, g_xlo);
    cudaGetSymbolAddress((void**)&ohi, g_ohi);
    cudaGetSymbolAddress((void**)&olo, g_olo);
    cudaGetSymbolAddress((void**)&wth, g_wth);
    cudaGetSymbolAddress((void**)&wtl, g_wtl);

    cudaFuncSetAttribute(gemm_hmma, cudaFuncAttributeMaxDynamicSharedMemorySize, GEMM_SMEM);
    cudaFuncSetAttribute(attn_hmma, cudaFuncAttributeMaxDynamicSharedMemorySize, ATTN_SMEM);

    int nElem = S_LEN * DMODEL;

    split_kernel<<<nElem / (256 * 4), 256>>>(x, xhi, xlo);
    wt_split4_kernel<<<dim3(DMODEL / 32, DMODEL / 32, 4), dim3(32, 8)>>>(
        wq, wk, wv, wo, wth, wtl);

    gemm_hmma<<<dim3(DMODEL / 128, DMODEL / 128, 3), 256, GEMM_SMEM>>>(
        xhi, xlo, wth, wtl, Qp, Kp, Vp, 0);

    int pairs = S_LEN * NH * (HD / 2);
    rope_split_kernel<<<pairs / 256, 256>>>(fcos, fsin);
    v_split_t_kernel<<<dim3(S_LEN / 32, HD / 32, NH), dim3(32, 8)>>>();

    attn_hmma<<<dim3(S_LEN / 64, NH), 128, ATTN_SMEM>>>();

    gemm_hmma<<<dim3(DMODEL / 128, DMODEL / 128, 1), 256, GEMM_SMEM>>>(
        ohi, olo, wth, wtl, out, out, out, 3);
}